// round 1
// baseline (speedup 1.0000x reference)
#include <cuda_runtime.h>
#include <cuda_bf16.h>
#include <math.h>

// ---------------- problem constants ----------------
#define BATCH   4
#define SEQ     4096
#define NT      (BATCH*SEQ)       // 16384 tokens
#define DMODEL  1024
#define DSLOT   128
#define NSLOT   8
#define HID     512
#define SCALE   (0.08838834764831845f)   // 1/sqrt(128)
#define FRESH_THR 0.1f
#define READ_DECAY 0.3f

// output layout (flattened concat, tuple order)
#define O_XENH  ((size_t)0)                       // 4*4096*1024
#define O_WM    ((size_t)16777216)                // 4*8*129
#define O_GATE  ((size_t)16781344)                // 16384
#define O_WG    ((size_t)16797728)                // 16384
#define O_ATTN  ((size_t)16814112)                // 16384*8
#define O_SEL   ((size_t)16945184)                // 16384*8

// ---------------- scratch (static device globals; no allocation) ----------------
__device__ float g_h1[NT*HID];          // shared hidden buffer (rg1 / imp1 / wd1, sequential reuse)
__device__ float g_query[NT*DSLOT];
__device__ float g_ctxslot[NT*DSLOT];
__device__ float g_context[NT*DMODEL];
__device__ float g_fused[NT*DMODEL];
__device__ float g_xslot[NT*DSLOT];
__device__ float g_implogit[NT];
__device__ float g_impsum[BATCH];
__device__ float g_wq[NT*DSLOT];
__device__ float g_wsc[NT*NSLOT];
__device__ float g_wmctx[NT*DSLOT];
__device__ float g_nf[BATCH*NSLOT];
__device__ float g_rp[BATCH*NSLOT];
__device__ int   g_sel[NT];
__device__ float g_ww[NT];

__device__ __forceinline__ float gelu_exact(float v) {
    return 0.5f * v * (1.0f + erff(v * 0.70710678118654752f));
}

// ---------------- tiled SGEMM: C[M,N] = act(A1[M,K1]@W1 + A2[M,K2]@W2 + bias) ----------------
#define BM 64
#define BN 64
#define BKT 16

template<int ACT>
__global__ void __launch_bounds__(256) sgemm_dual(
    const float* __restrict__ A1, int K1,
    const float* __restrict__ A2, int K2,
    const float* __restrict__ W1,
    const float* __restrict__ W2,
    const float* __restrict__ bias,
    float* __restrict__ C, int M, int N)
{
    __shared__ float As[BKT][BM];
    __shared__ float Ws[BKT][BN];

    const int tid = threadIdx.x;
    const int bm = blockIdx.y * BM;
    const int bn = blockIdx.x * BN;
    const int ty = tid >> 4, tx = tid & 15;

    float acc[4][4] = {};

    #pragma unroll 1
    for (int seg = 0; seg < 2; ++seg) {
        const float* A = seg ? A2 : A1;
        const float* W = seg ? W2 : W1;
        const int K = seg ? K2 : K1;
        if (K == 0) continue;
        for (int k0 = 0; k0 < K; k0 += BKT) {
            {   // load A tile (64 rows x 16 k) as float4 per thread
                int row = tid >> 2;
                int kc  = (tid & 3) * 4;
                float4 a = *(const float4*)&A[(size_t)(bm + row) * K + (k0 + kc)];
                As[kc + 0][row] = a.x;
                As[kc + 1][row] = a.y;
                As[kc + 2][row] = a.z;
                As[kc + 3][row] = a.w;
            }
            {   // load W tile (16 k x 64 n)
                int kr = tid >> 4;
                int nc = (tid & 15) * 4;
                *(float4*)&Ws[kr][nc] = *(const float4*)&W[(size_t)(k0 + kr) * N + (bn + nc)];
            }
            __syncthreads();
            #pragma unroll
            for (int kk = 0; kk < BKT; ++kk) {
                float4 a4 = *(const float4*)&As[kk][ty * 4];
                float4 b4 = *(const float4*)&Ws[kk][tx * 4];
                float av[4] = {a4.x, a4.y, a4.z, a4.w};
                float bv[4] = {b4.x, b4.y, b4.z, b4.w};
                #pragma unroll
                for (int i = 0; i < 4; ++i)
                    #pragma unroll
                    for (int j = 0; j < 4; ++j)
                        acc[i][j] = fmaf(av[i], bv[j], acc[i][j]);
            }
            __syncthreads();
        }
    }
    #pragma unroll
    for (int i = 0; i < 4; ++i) {
        int m = bm + ty * 4 + i;
        float4 o;
        float* op = &o.x;
        #pragma unroll
        for (int j = 0; j < 4; ++j) {
            int n = bn + tx * 4 + j;
            float v = acc[i][j] + bias[n];
            if (ACT == 1) v = gelu_exact(v);
            op[j] = v;
        }
        *(float4*)&C[(size_t)m * N + bn + tx * 4] = o;
    }
}

// ---------------- row-dot (N=1 head): out = f(h[t]·w + b) ----------------
// mode 0: sigmoid(z)   mode 1: z   mode 2: sigmoid(z / max(wt,0.1))
__global__ void rowdot_kernel(const float* __restrict__ Hm, int Kd,
                              const float* __restrict__ w, const float* __restrict__ bias,
                              const float* __restrict__ wt, int mode,
                              float* __restrict__ out, int M)
{
    __shared__ float ws[HID];
    for (int i = threadIdx.x; i < Kd; i += blockDim.x) ws[i] = w[i];
    __syncthreads();
    int warp = threadIdx.x >> 5, lane = threadIdx.x & 31;
    int row = blockIdx.x * (blockDim.x >> 5) + warp;
    if (row >= M) return;
    const float* h = Hm + (size_t)row * Kd;
    float s = 0.f;
    for (int i = lane; i < Kd; i += 32) s = fmaf(h[i], ws[i], s);
    #pragma unroll
    for (int o = 16; o; o >>= 1) s += __shfl_xor_sync(0xffffffffu, s, o);
    if (lane == 0) {
        float z = s + bias[0];
        if (mode == 1) out[row] = z;
        else {
            if (mode == 2) z /= fmaxf(wt[0], 0.1f);
            out[row] = 1.f / (1.f + expf(-z));
        }
    }
}

// ---------------- read attention: scores -> stale mask -> softmax -> attn, ctx_slot ----------------
__global__ void read_attn_kernel(const float* __restrict__ query,
                                 const float* __restrict__ wm,
                                 float* __restrict__ attn_out,
                                 float* __restrict__ ctxslot)
{
    __shared__ float cont[NSLOT][DSLOT];
    __shared__ float fresh[NSLOT];
    int tid = threadIdx.x;
    int tokenBase = blockIdx.x * 8;
    int b = tokenBase / SEQ;
    for (int i = tid; i < NSLOT * DSLOT; i += 256) {
        int k = i / DSLOT, d = i % DSLOT;
        cont[k][d] = wm[((size_t)b * NSLOT + k) * (DSLOT + 1) + d];
    }
    if (tid < NSLOT) fresh[tid] = wm[((size_t)b * NSLOT + tid) * (DSLOT + 1) + DSLOT];
    __syncthreads();

    int warp = tid >> 5, lane = tid & 31;
    int t = tokenBase + warp;
    const float* q = query + (size_t)t * DSLOT;
    float ql[4];
    #pragma unroll
    for (int i = 0; i < 4; ++i) ql[i] = q[lane + 32 * i];

    float a[NSLOT];
    #pragma unroll
    for (int k = 0; k < NSLOT; ++k) {
        float s = 0.f;
        #pragma unroll
        for (int i = 0; i < 4; ++i) s = fmaf(ql[i], cont[k][lane + 32 * i], s);
        #pragma unroll
        for (int o = 16; o; o >>= 1) s += __shfl_xor_sync(0xffffffffu, s, o);
        s *= SCALE;
        if (fresh[k] < FRESH_THR) s = -1e9f;
        a[k] = s;
    }
    float mx = a[0];
    #pragma unroll
    for (int k = 1; k < NSLOT; ++k) mx = fmaxf(mx, a[k]);
    float sum = 0.f;
    #pragma unroll
    for (int k = 0; k < NSLOT; ++k) { a[k] = expf(a[k] - mx); sum += a[k]; }
    float inv = 1.f / sum;
    #pragma unroll
    for (int k = 0; k < NSLOT; ++k) a[k] *= inv;

    if (lane == 0) {
        #pragma unroll
        for (int k = 0; k < NSLOT; ++k) attn_out[(size_t)t * NSLOT + k] = a[k];
    }
    #pragma unroll
    for (int i = 0; i < 4; ++i) {
        int d = lane + 32 * i;
        float c = 0.f;
        #pragma unroll
        for (int k = 0; k < NSLOT; ++k) c = fmaf(a[k], cont[k][d], c);
        ctxslot[(size_t)t * DSLOT + d] = c;
    }
}

// ---------------- write attention: raw scores + softmax context ----------------
__global__ void write_attn_kernel(const float* __restrict__ wq,
                                  const float* __restrict__ wm,
                                  float* __restrict__ wsc_out,
                                  float* __restrict__ wmctx)
{
    __shared__ float cont[NSLOT][DSLOT];
    int tid = threadIdx.x;
    int tokenBase = blockIdx.x * 8;
    int b = tokenBase / SEQ;
    for (int i = tid; i < NSLOT * DSLOT; i += 256) {
        int k = i / DSLOT, d = i % DSLOT;
        cont[k][d] = wm[((size_t)b * NSLOT + k) * (DSLOT + 1) + d];
    }
    __syncthreads();

    int warp = tid >> 5, lane = tid & 31;
    int t = tokenBase + warp;
    const float* q = wq + (size_t)t * DSLOT;
    float ql[4];
    #pragma unroll
    for (int i = 0; i < 4; ++i) ql[i] = q[lane + 32 * i];

    float a[NSLOT];
    #pragma unroll
    for (int k = 0; k < NSLOT; ++k) {
        float s = 0.f;
        #pragma unroll
        for (int i = 0; i < 4; ++i) s = fmaf(ql[i], cont[k][lane + 32 * i], s);
        #pragma unroll
        for (int o = 16; o; o >>= 1) s += __shfl_xor_sync(0xffffffffu, s, o);
        a[k] = s * SCALE;
    }
    if (lane == 0) {
        #pragma unroll
        for (int k = 0; k < NSLOT; ++k) wsc_out[(size_t)t * NSLOT + k] = a[k];
    }
    float mx = a[0];
    #pragma unroll
    for (int k = 1; k < NSLOT; ++k) mx = fmaxf(mx, a[k]);
    float sum = 0.f;
    #pragma unroll
    for (int k = 0; k < NSLOT; ++k) { a[k] = expf(a[k] - mx); sum += a[k]; }
    float inv = 1.f / sum;
    #pragma unroll
    for (int k = 0; k < NSLOT; ++k) a[k] *= inv;
    #pragma unroll
    for (int i = 0; i < 4; ++i) {
        int d = lane + 32 * i;
        float c = 0.f;
        #pragma unroll
        for (int k = 0; k < NSLOT; ++k) c = fmaf(a[k], cont[k][d], c);
        wmctx[(size_t)t * DSLOT + d] = c;
    }
}

// ---------------- read pressure: rp[b,k] = sum_s attn ----------------
__global__ void pressure_kernel(const float* __restrict__ attn, float* __restrict__ rp)
{
    int b = blockIdx.x / NSLOT, k = blockIdx.x % NSLOT;
    __shared__ float sh[256];
    float s = 0.f;
    for (int si = threadIdx.x; si < SEQ; si += 256)
        s += attn[((size_t)b * SEQ + si) * NSLOT + k];
    sh[threadIdx.x] = s;
    __syncthreads();
    for (int o = 128; o; o >>= 1) {
        if (threadIdx.x < o) sh[threadIdx.x] += sh[threadIdx.x + o];
        __syncthreads();
    }
    if (threadIdx.x == 0) rp[blockIdx.x] = sh[0];
}

__global__ void freshness_kernel(const float* __restrict__ rp, const float* __restrict__ wm,
                                 float* __restrict__ nf)
{
    int t = threadIdx.x;               // b*8+k, 32 threads
    int b = t / NSLOT;
    __shared__ float s[BATCH * NSLOT];
    s[t] = rp[t];
    __syncthreads();
    float mx = 1e-8f;
    #pragma unroll
    for (int k = 0; k < NSLOT; ++k) mx = fmaxf(mx, s[b * NSLOT + k]);
    float decay = 1.f - (s[t] / mx) * (1.f - READ_DECAY);
    float fr = wm[(size_t)t * (DSLOT + 1) + DSLOT];
    nf[t] = fr * decay;
}

// ---------------- importance normalizer ----------------
__global__ void impsum_kernel(const float* __restrict__ logit, const float* __restrict__ wt,
                              float* __restrict__ outsum)
{
    int b = blockIdx.x;
    float temp = fmaxf(wt[0], 0.1f);
    __shared__ float sh[1024];
    float s = 0.f;
    for (int i = threadIdx.x; i < SEQ; i += 1024)
        s += expf(logit[(size_t)b * SEQ + i] / temp);
    sh[threadIdx.x] = s;
    __syncthreads();
    for (int o = 512; o; o >>= 1) {
        if (threadIdx.x < o) sh[threadIdx.x] += sh[threadIdx.x + o];
        __syncthreads();
    }
    if (threadIdx.x == 0) outsum[b] = sh[0];
}

// ---------------- slot selection + write weights ----------------
__global__ void slotsel_kernel(const float* __restrict__ wsc, const float* __restrict__ nf,
                               const float* __restrict__ logit, const float* __restrict__ impsum,
                               const float* __restrict__ wg, const float* __restrict__ wt,
                               float* __restrict__ sel_onehot, int* __restrict__ sel_idx,
                               float* __restrict__ ww_out)
{
    int t = blockIdx.x * 256 + threadIdx.x;
    if (t >= NT) return;
    int b = t / SEQ;
    float temp = fmaxf(wt[0], 0.1f);
    float best = wsc[(size_t)t * NSLOT] - 2.f * nf[b * NSLOT];
    int bi = 0;
    #pragma unroll
    for (int k = 1; k < NSLOT; ++k) {
        float v = wsc[(size_t)t * NSLOT + k] - 2.f * nf[b * NSLOT + k];
        if (v > best) { best = v; bi = k; }        // first-max, matches jnp.argmax
    }
    float imp = expf(logit[t] / temp) / (impsum[b] + 1e-8f) * (float)SEQ;
    float w = wg[t] * imp;
    sel_idx[t] = bi;
    ww_out[t] = w;
    #pragma unroll
    for (int k = 0; k < NSLOT; ++k)
        sel_onehot[(size_t)t * NSLOT + k] = (k == bi) ? 1.f : 0.f;
}

// ---------------- per-slot aggregation (deterministic serial-over-s) ----------------
__global__ void slotagg_kernel(const int* __restrict__ sel, const float* __restrict__ ww,
                               const float* __restrict__ xslot, const float* __restrict__ wm,
                               const float* __restrict__ nf, float* __restrict__ wm_out)
{
    int bk = blockIdx.x;               // b*8+k
    int b = bk / NSLOT, k = bk % NSLOT;
    int d = threadIdx.x;               // 0..127
    float acc = 0.f, st = 0.f;
    const int s0 = b * SEQ;
    for (int si = 0; si < SEQ; ++si) {
        int tt = s0 + si;
        if (sel[tt] == k) {
            float w = ww[tt];
            st += w;
            acc = fmaf(w, xslot[(size_t)tt * DSLOT + d], acc);
        }
    }
    float nc = acc / fmaxf(st, 1e-8f);
    float has = (st > 0.1f) ? 1.f : 0.f;
    float cont = wm[(size_t)bk * (DSLOT + 1) + d];
    wm_out[(size_t)bk * (DSLOT + 1) + d] = has * nc + (1.f - has) * cont;
    if (d == 0)
        wm_out[(size_t)bk * (DSLOT + 1) + DSLOT] = has * 1.f + (1.f - has) * nf[bk];
}

// ---------------- x_enhanced = (1-g)*x + g*fused ----------------
__global__ void enhance_kernel(const float* __restrict__ x, const float* __restrict__ fused,
                               const float* __restrict__ gate, float* __restrict__ out)
{
    size_t idx = (size_t)blockIdx.x * 256 + threadIdx.x;   // float4 index
    int t = (int)(idx >> 8);                               // D/4 = 256 float4 per row
    float g = gate[t];
    float4 xv = ((const float4*)x)[idx];
    float4 fv = ((const float4*)fused)[idx];
    float4 o;
    o.x = (1.f - g) * xv.x + g * fv.x;
    o.y = (1.f - g) * xv.y + g * fv.y;
    o.z = (1.f - g) * xv.z + g * fv.z;
    o.w = (1.f - g) * xv.w + g * fv.w;
    ((float4*)out)[idx] = o;
}

// ---------------- host launch ----------------
static float* sym(const void* s) {
    void* p = nullptr;
    cudaGetSymbolAddress(&p, s);
    return (float*)p;
}

extern "C" void kernel_launch(void* const* d_in, const int* in_sizes, int n_in,
                              void* d_out, int out_size)
{
    const float* x      = (const float*)d_in[0];
    const float* wm     = (const float*)d_in[1];
    const float* rq_w   = (const float*)d_in[2];
    const float* rq_b   = (const float*)d_in[3];
    const float* fwm_w  = (const float*)d_in[4];
    const float* fwm_b  = (const float*)d_in[5];
    const float* rg1_w  = (const float*)d_in[6];
    const float* rg1_b  = (const float*)d_in[7];
    const float* rg2_w  = (const float*)d_in[8];
    const float* rg2_b  = (const float*)d_in[9];
    const float* fus_w  = (const float*)d_in[10];
    const float* fus_b  = (const float*)d_in[11];
    const float* twm_w  = (const float*)d_in[12];
    const float* twm_b  = (const float*)d_in[13];
    const float* wq_w   = (const float*)d_in[14];
    const float* wq_b   = (const float*)d_in[15];
    const float* imp1_w = (const float*)d_in[16];
    const float* imp1_b = (const float*)d_in[17];
    const float* imp2_w = (const float*)d_in[18];
    const float* imp2_b = (const float*)d_in[19];
    const float* wd1_w  = (const float*)d_in[20];
    const float* wd1_b  = (const float*)d_in[21];
    const float* wd2_w  = (const float*)d_in[22];
    const float* wd2_b  = (const float*)d_in[23];
    const float* wt     = (const float*)d_in[24];

    float* out = (float*)d_out;

    float* h1      = sym(g_h1);
    float* query   = sym(g_query);
    float* ctxslot = sym(g_ctxslot);
    float* context = sym(g_context);
    float* fused   = sym(g_fused);
    float* xslot   = sym(g_xslot);
    float* implog  = sym(g_implogit);
    float* impsum  = sym(g_impsum);
    float* wqbuf   = sym(g_wq);
    float* wsc     = sym(g_wsc);
    float* wmctx   = sym(g_wmctx);
    float* nf      = sym(g_nf);
    float* rp      = sym(g_rp);
    int*   selidx  = (int*)sym(g_sel);
    float* wwbuf   = sym(g_ww);

    dim3 blk(256);

    // read gate path
    sgemm_dual<1><<<dim3(HID/BN, NT/BM), blk>>>(x, DMODEL, nullptr, 0, rg1_w, nullptr, rg1_b, h1, NT, HID);
    rowdot_kernel<<<NT/8, 256>>>(h1, HID, rg2_w, rg2_b, wt, 0, out + O_GATE, NT);

    // read attention
    sgemm_dual<0><<<dim3(DSLOT/BN, NT/BM), blk>>>(x, DMODEL, nullptr, 0, rq_w, nullptr, rq_b, query, NT, DSLOT);
    read_attn_kernel<<<NT/8, 256>>>(query, wm, out + O_ATTN, ctxslot);
    sgemm_dual<0><<<dim3(DMODEL/BN, NT/BM), blk>>>(ctxslot, DSLOT, nullptr, 0, fwm_w, nullptr, fwm_b, context, NT, DMODEL);

    // fusion (concat GEMM as dual-segment)
    sgemm_dual<0><<<dim3(DMODEL/BN, NT/BM), blk>>>(x, DMODEL, context, DMODEL,
                                                   fus_w, fus_w + (size_t)DMODEL * DMODEL,
                                                   fus_b, fused, NT, DMODEL);
    enhance_kernel<<<(NT*DMODEL/4)/256, 256>>>(x, fused, out + O_GATE, out + O_XENH);

    // freshness decay
    pressure_kernel<<<BATCH*NSLOT, 256>>>(out + O_ATTN, rp);
    freshness_kernel<<<1, BATCH*NSLOT>>>(rp, wm, nf);

    // write path
    sgemm_dual<0><<<dim3(DSLOT/BN, NT/BM), blk>>>(x, DMODEL, nullptr, 0, twm_w, nullptr, twm_b, xslot, NT, DSLOT);
    sgemm_dual<1><<<dim3(HID/BN, NT/BM), blk>>>(x, DMODEL, nullptr, 0, imp1_w, nullptr, imp1_b, h1, NT, HID);
    rowdot_kernel<<<NT/8, 256>>>(h1, HID, imp2_w, imp2_b, wt, 1, implog, NT);
    impsum_kernel<<<BATCH, 1024>>>(implog, wt, impsum);

    sgemm_dual<0><<<dim3(DSLOT/BN, NT/BM), blk>>>(x, DMODEL, nullptr, 0, wq_w, nullptr, wq_b, wqbuf, NT, DSLOT);
    write_attn_kernel<<<NT/8, 256>>>(wqbuf, wm, wsc, wmctx);

    sgemm_dual<1><<<dim3(HID/BN, NT/BM), blk>>>(x, DMODEL, wmctx, DSLOT,
                                                wd1_w, wd1_w + (size_t)DMODEL * HID,
                                                wd1_b, h1, NT, HID);
    rowdot_kernel<<<NT/8, 256>>>(h1, HID, wd2_w, wd2_b, wt, 2, out + O_WG, NT);

    slotsel_kernel<<<NT/256, 256>>>(wsc, nf, implog, impsum, out + O_WG, wt,
                                    out + O_SEL, selidx, wwbuf);
    slotagg_kernel<<<BATCH*NSLOT, DSLOT>>>(selidx, wwbuf, xslot, wm, nf, out + O_WM);
}

// round 6
// speedup vs baseline: 2.1523x; 2.1523x over previous
#include <cuda_runtime.h>
#include <cuda_bf16.h>
#include <math.h>
#include <stdint.h>

#define BATCH   4
#define SEQ     4096
#define NT      (BATCH*SEQ)
#define DMODEL  1024
#define DSLOT   128
#define NSLOT   8
#define HID     512
#define SCALE   (0.08838834764831845f)
#define FRESH_THR 0.1f
#define READ_DECAY 0.3f

#define O_XENH  ((size_t)0)
#define O_WM    ((size_t)16777216)
#define O_GATE  ((size_t)16781344)
#define O_WG    ((size_t)16797728)
#define O_ATTN  ((size_t)16814112)
#define O_SEL   ((size_t)16945184)

// ---------------- scratch ----------------
__device__ float g_h1[NT*HID];
__device__ float g_query[NT*DSLOT];
__device__ float g_fused[NT*DMODEL];
__device__ float g_xslot[NT*DSLOT];
__device__ float g_implogit[NT];
__device__ float g_impsum[BATCH];
__device__ float g_wqv[NT*DSLOT];
__device__ float g_wsc[NT*NSLOT];
__device__ float g_nf[BATCH*NSLOT];
__device__ float g_rp[BATCH*NSLOT];
__device__ int   g_sel[NT];
__device__ float g_ww[NT];

__device__ __nv_bfloat16 g_xh[NT*DMODEL],  g_xl[NT*DMODEL];
__device__ __nv_bfloat16 g_ctxh[NT*DSLOT], g_ctxl[NT*DSLOT];
__device__ __nv_bfloat16 g_conh[NT*DMODEL],g_conl[NT*DMODEL];
__device__ __nv_bfloat16 g_wmh[NT*DSLOT],  g_wml[NT*DSLOT];

#define WT_TOTAL 4259840
__device__ __nv_bfloat16 g_wth[WT_TOTAL], g_wtl[WT_TOTAL];
#define OFF_RG1 0
#define OFF_RQ  524288
#define OFF_FWM 655360
#define OFF_FUS 786432
#define OFF_TWM 2883584
#define OFF_WQ  3014656
#define OFF_IMP 3145728
#define OFF_WD1 3670016

__device__ __forceinline__ float gelu_exact(float v) {
    return 0.5f * v * (1.0f + erff(v * 0.70710678118654752f));
}

// ---------------- async copy helpers ----------------
__device__ __forceinline__ uint32_t smem_u32(const void* p) {
    uint32_t a;
    asm("{ .reg .u64 t; cvta.to.shared.u64 t, %1; cvt.u32.u64 %0, t; }" : "=r"(a) : "l"(p));
    return a;
}
__device__ __forceinline__ void cpa16(uint32_t s, const void* g) {
    asm volatile("cp.async.cg.shared.global [%0], [%1], 16;\n" :: "r"(s), "l"(g));
}
__device__ __forceinline__ void cp_commit() { asm volatile("cp.async.commit_group;\n" ::); }

__device__ __forceinline__ void mma_bf16(float* c, uint32_t a0, uint32_t a1, uint32_t a2,
                                         uint32_t a3, uint32_t b0, uint32_t b1) {
    asm volatile(
        "mma.sync.aligned.m16n8k16.row.col.f32.bf16.bf16.f32 "
        "{%0,%1,%2,%3},{%4,%5,%6,%7},{%8,%9},{%0,%1,%2,%3};"
        : "+f"(c[0]), "+f"(c[1]), "+f"(c[2]), "+f"(c[3])
        : "r"(a0), "r"(a1), "r"(a2), "r"(a3), "r"(b0), "r"(b1));
}
__device__ __forceinline__ uint32_t lds32(uint32_t a) {
    uint32_t v;
    asm volatile("ld.shared.b32 %0, [%1];" : "=r"(v) : "r"(a));
    return v;
}

// ---------------- mma.sync bf16x3 GEMM: C[M,N] = act(A@Wt^T + bias) ----------------
// BM=BN=128, KC=32 per chunk, 2-stage cp.async pipeline, 8 warps (2m x 4n), 64x32 warp tile.
#define SROW   80
#define TILEB  10240        // 128 rows * 80B
#define STAGEB 40960        // Ah,Al,Bh,Bl
#define SMEMB  81920        // 2 stages

template<int MODE>   // 0: f32 out, 1: f32 gelu, 2: bf16 hi/lo out
__global__ void __launch_bounds__(256) tc_gemm(
    const __nv_bfloat16* __restrict__ A1h, const __nv_bfloat16* __restrict__ A1l, int K1,
    const __nv_bfloat16* __restrict__ A2h, const __nv_bfloat16* __restrict__ A2l,
    const __nv_bfloat16* __restrict__ Wh,  const __nv_bfloat16* __restrict__ Wl,  int Ktot,
    const float* __restrict__ bias,
    float* __restrict__ Cf, __nv_bfloat16* __restrict__ Chi, __nv_bfloat16* __restrict__ Clo,
    int N)
{
    extern __shared__ __align__(16) char smem[];
    const uint32_t sb = smem_u32(smem);
    const int tid = threadIdx.x, wid = tid >> 5, lane = tid & 31;
    const int g = lane >> 2, tg = lane & 3;
    const int m0 = blockIdx.y * 128, bn = blockIdx.x * 128;
    const int wm = (wid & 1) * 64, wn = (wid >> 1) * 32;

    float acc[4][4][4] = {};
    const int nchunk = Ktot / 32;

    auto load_chunk = [&](int ci, int buf) {
        int k0 = ci * 32;
        const __nv_bfloat16 *Ah, *Al; int sA, kA;
        if (k0 < K1) { Ah = A1h; Al = A1l; sA = K1; kA = k0; }
        else         { Ah = A2h; Al = A2l; sA = Ktot - K1; kA = k0 - K1; }
        uint32_t base = sb + buf * STAGEB;
        #pragma unroll
        for (int u = tid; u < 512; u += 256) {
            int r = u >> 2, c = (u & 3) * 8;
            uint32_t o = (uint32_t)(r * SROW + c * 2);
            size_t gi = (size_t)(m0 + r) * sA + kA + c;
            cpa16(base + o, Ah + gi);
            cpa16(base + TILEB + o, Al + gi);
        }
        #pragma unroll
        for (int u = tid; u < 512; u += 256) {
            int r = u >> 2, c = (u & 3) * 8;
            uint32_t o = (uint32_t)(r * SROW + c * 2);
            size_t gi = (size_t)(bn + r) * Ktot + k0 + c;
            cpa16(base + 2 * TILEB + o, Wh + gi);
            cpa16(base + 3 * TILEB + o, Wl + gi);
        }
        cp_commit();
    };

    load_chunk(0, 0);

    for (int ci = 0; ci < nchunk; ++ci) {
        if (ci + 1 < nchunk) {
            load_chunk(ci + 1, (ci + 1) & 1);
            asm volatile("cp.async.wait_group 1;" ::: "memory");
        } else {
            asm volatile("cp.async.wait_group 0;" ::: "memory");
        }
        __syncthreads();

        uint32_t sAh = sb + (ci & 1) * STAGEB;
        uint32_t sAl = sAh + TILEB;
        uint32_t sBh = sAh + 2 * TILEB;
        uint32_t sBl = sAh + 3 * TILEB;

        #pragma unroll
        for (int ks = 0; ks < 2; ++ks) {
            const uint32_t kb = (uint32_t)((ks * 16 + tg * 2) * 2);
            uint32_t ah[4][4], al[4][4];
            #pragma unroll
            for (int mi = 0; mi < 4; ++mi) {
                uint32_t ro = (uint32_t)((wm + mi * 16 + g) * SROW) + kb;
                ah[mi][0] = lds32(sAh + ro);
                ah[mi][1] = lds32(sAh + ro + 8 * SROW);
                ah[mi][2] = lds32(sAh + ro + 16);
                ah[mi][3] = lds32(sAh + ro + 8 * SROW + 16);
                al[mi][0] = lds32(sAl + ro);
                al[mi][1] = lds32(sAl + ro + 8 * SROW);
                al[mi][2] = lds32(sAl + ro + 16);
                al[mi][3] = lds32(sAl + ro + 8 * SROW + 16);
            }
            #pragma unroll
            for (int ni = 0; ni < 4; ++ni) {
                uint32_t ro = (uint32_t)((wn + ni * 8 + g) * SROW) + kb;
                uint32_t bh0 = lds32(sBh + ro), bh1 = lds32(sBh + ro + 16);
                uint32_t bl0 = lds32(sBl + ro), bl1 = lds32(sBl + ro + 16);
                #pragma unroll
                for (int mi = 0; mi < 4; ++mi) {
                    mma_bf16(acc[mi][ni], ah[mi][0], ah[mi][1], ah[mi][2], ah[mi][3], bh0, bh1);
                    mma_bf16(acc[mi][ni], ah[mi][0], ah[mi][1], ah[mi][2], ah[mi][3], bl0, bl1);
                    mma_bf16(acc[mi][ni], al[mi][0], al[mi][1], al[mi][2], al[mi][3], bh0, bh1);
                }
            }
        }
        __syncthreads();
    }

    #pragma unroll
    for (int mi = 0; mi < 4; ++mi) {
        #pragma unroll
        for (int ni = 0; ni < 4; ++ni) {
            int row = m0 + wm + mi * 16 + g;
            int col = bn + wn + ni * 8 + tg * 2;
            float b0 = bias[col], b1 = bias[col + 1];
            #pragma unroll
            for (int h = 0; h < 2; ++h) {
                int r = row + h * 8;
                float v0 = acc[mi][ni][h * 2]     + b0;
                float v1 = acc[mi][ni][h * 2 + 1] + b1;
                if (MODE == 1) { v0 = gelu_exact(v0); v1 = gelu_exact(v1); }
                if (MODE == 2) {
                    __nv_bfloat16 h0 = __float2bfloat16(v0);
                    __nv_bfloat16 h1 = __float2bfloat16(v1);
                    __nv_bfloat162 hp; hp.x = h0; hp.y = h1;
                    __nv_bfloat162 lp;
                    lp.x = __float2bfloat16(v0 - __bfloat162float(h0));
                    lp.y = __float2bfloat16(v1 - __bfloat162float(h1));
                    *(__nv_bfloat162*)&Chi[(size_t)r * N + col] = hp;
                    *(__nv_bfloat162*)&Clo[(size_t)r * N + col] = lp;
                } else {
                    float2 o; o.x = v0; o.y = v1;
                    *(float2*)&Cf[(size_t)r * N + col] = o;
                }
            }
        }
    }
}

// ---------------- split x ----------------
__global__ void split_x_kernel(const float4* __restrict__ x,
                               __nv_bfloat16* __restrict__ h, __nv_bfloat16* __restrict__ l)
{
    size_t i = (size_t)blockIdx.x * 256 + threadIdx.x;
    float4 v = x[i];
    float a[4] = {v.x, v.y, v.z, v.w};
    __nv_bfloat16 hh[4];
    #pragma unroll
    for (int c = 0; c < 4; ++c) hh[c] = __float2bfloat16(a[c]);
    __nv_bfloat162 hp0, hp1, lp0, lp1;
    hp0.x = hh[0]; hp0.y = hh[1]; hp1.x = hh[2]; hp1.y = hh[3];
    lp0.x = __float2bfloat16(a[0] - __bfloat162float(hh[0]));
    lp0.y = __float2bfloat16(a[1] - __bfloat162float(hh[1]));
    lp1.x = __float2bfloat16(a[2] - __bfloat162float(hh[2]));
    lp1.y = __float2bfloat16(a[3] - __bfloat162float(hh[3]));
    *(__nv_bfloat162*)&h[i * 4]     = hp0;
    *(__nv_bfloat162*)&h[i * 4 + 2] = hp1;
    *(__nv_bfloat162*)&l[i * 4]     = lp0;
    *(__nv_bfloat162*)&l[i * 4 + 2] = lp1;
}

// ---------------- weight transpose + split: W[K,N] -> Wt[N][K] ----------------
__global__ void wsplit_kernel(const float* __restrict__ W, int K, int N,
                              __nv_bfloat16* __restrict__ Th, __nv_bfloat16* __restrict__ Tl)
{
    __shared__ float tile[32][33];
    int kb = blockIdx.x * 32, nb = blockIdx.y * 32;
    int tx = threadIdx.x, ty = threadIdx.y;
    #pragma unroll
    for (int i = 0; i < 4; ++i)
        tile[ty + i * 8][tx] = W[(size_t)(kb + ty + i * 8) * N + nb + tx];
    __syncthreads();
    #pragma unroll
    for (int i = 0; i < 4; ++i) {
        int n = nb + ty + i * 8, k = kb + tx;
        float v = tile[tx][ty + i * 8];
        size_t o = (size_t)n * K + k;
        __nv_bfloat16 h = __float2bfloat16(v);
        Th[o] = h;
        Tl[o] = __float2bfloat16(v - __bfloat162float(h));
    }
}

// ---------------- row-dot ----------------
__global__ void rowdot_kernel(const float* __restrict__ Hm,
                              const float* __restrict__ w, const float* __restrict__ bias,
                              const float* __restrict__ wt, int mode,
                              float* __restrict__ out)
{
    __shared__ float ws[HID];
    for (int i = threadIdx.x; i < HID; i += blockDim.x) ws[i] = w[i];
    __syncthreads();
    int warp = threadIdx.x >> 5, lane = threadIdx.x & 31;
    int row = blockIdx.x * 8 + warp;
    const float* h = Hm + (size_t)row * HID;
    float s = 0.f;
    for (int i = lane; i < HID; i += 32) s = fmaf(h[i], ws[i], s);
    #pragma unroll
    for (int o = 16; o; o >>= 1) s += __shfl_xor_sync(0xffffffffu, s, o);
    if (lane == 0) {
        float z = s + bias[0];
        if (mode == 1) out[row] = z;
        else {
            if (mode == 2) z /= fmaxf(wt[0], 0.1f);
            out[row] = 1.f / (1.f + expf(-z));
        }
    }
}

// ---------------- read attention ----------------
__global__ void read_attn_kernel(const float* __restrict__ query,
                                 const float* __restrict__ wm,
                                 float* __restrict__ attn_out,
                                 __nv_bfloat16* __restrict__ ctxh,
                                 __nv_bfloat16* __restrict__ ctxl)
{
    __shared__ float cont[NSLOT][DSLOT];
    __shared__ float fresh[NSLOT];
    int tid = threadIdx.x;
    int tokenBase = blockIdx.x * 8;
    int b = tokenBase / SEQ;
    for (int i = tid; i < NSLOT * DSLOT; i += 256) {
        int k = i / DSLOT, d = i % DSLOT;
        cont[k][d] = wm[((size_t)b * NSLOT + k) * (DSLOT + 1) + d];
    }
    if (tid < NSLOT) fresh[tid] = wm[((size_t)b * NSLOT + tid) * (DSLOT + 1) + DSLOT];
    __syncthreads();
    int warp = tid >> 5, lane = tid & 31;
    int t = tokenBase + warp;
    const float* q = query + (size_t)t * DSLOT;
    float ql[4];
    #pragma unroll
    for (int i = 0; i < 4; ++i) ql[i] = q[lane + 32 * i];
    float a[NSLOT];
    #pragma unroll
    for (int k = 0; k < NSLOT; ++k) {
        float s = 0.f;
        #pragma unroll
        for (int i = 0; i < 4; ++i) s = fmaf(ql[i], cont[k][lane + 32 * i], s);
        #pragma unroll
        for (int o = 16; o; o >>= 1) s += __shfl_xor_sync(0xffffffffu, s, o);
        s *= SCALE;
        if (fresh[k] < FRESH_THR) s = -1e9f;
        a[k] = s;
    }
    float mx = a[0];
    #pragma unroll
    for (int k = 1; k < NSLOT; ++k) mx = fmaxf(mx, a[k]);
    float sum = 0.f;
    #pragma unroll
    for (int k = 0; k < NSLOT; ++k) { a[k] = expf(a[k] - mx); sum += a[k]; }
    float inv = 1.f / sum;
    #pragma unroll
    for (int k = 0; k < NSLOT; ++k) a[k] *= inv;
    if (lane == 0) {
        #pragma unroll
        for (int k = 0; k < NSLOT; ++k) attn_out[(size_t)t * NSLOT + k] = a[k];
    }
    #pragma unroll
    for (int i = 0; i < 4; ++i) {
        int d = lane + 32 * i;
        float c = 0.f;
        #pragma unroll
        for (int k = 0; k < NSLOT; ++k) c = fmaf(a[k], cont[k][d], c);
        __nv_bfloat16 h = __float2bfloat16(c);
        ctxh[(size_t)t * DSLOT + d] = h;
        ctxl[(size_t)t * DSLOT + d] = __float2bfloat16(c - __bfloat162float(h));
    }
}

// ---------------- write attention ----------------
__global__ void write_attn_kernel(const float* __restrict__ wq,
                                  const float* __restrict__ wm,
                                  float* __restrict__ wsc_out,
                                  __nv_bfloat16* __restrict__ wmh,
                                  __nv_bfloat16* __restrict__ wml)
{
    __shared__ float cont[NSLOT][DSLOT];
    int tid = threadIdx.x;
    int tokenBase = blockIdx.x * 8;
    int b = tokenBase / SEQ;
    for (int i = tid; i < NSLOT * DSLOT; i += 256) {
        int k = i / DSLOT, d = i % DSLOT;
        cont[k][d] = wm[((size_t)b * NSLOT + k) * (DSLOT + 1) + d];
    }
    __syncthreads();
    int warp = tid >> 5, lane = tid & 31;
    int t = tokenBase + warp;
    const float* q = wq + (size_t)t * DSLOT;
    float ql[4];
    #pragma unroll
    for (int i = 0; i < 4; ++i) ql[i] = q[lane + 32 * i];
    float a[NSLOT];
    #pragma unroll
    for (int k = 0; k < NSLOT; ++k) {
        float s = 0.f;
        #pragma unroll
        for (int i = 0; i < 4; ++i) s = fmaf(ql[i], cont[k][lane + 32 * i], s);
        #pragma unroll
        for (int o = 16; o; o >>= 1) s += __shfl_xor_sync(0xffffffffu, s, o);
        a[k] = s * SCALE;
    }
    if (lane == 0) {
        #pragma unroll
        for (int k = 0; k < NSLOT; ++k) wsc_out[(size_t)t * NSLOT + k] = a[k];
    }
    float mx = a[0];
    #pragma unroll
    for (int k = 1; k < NSLOT; ++k) mx = fmaxf(mx, a[k]);
    float sum = 0.f;
    #pragma unroll
    for (int k = 0; k < NSLOT; ++k) { a[k] = expf(a[k] - mx); sum += a[k]; }
    float inv = 1.f / sum;
    #pragma unroll
    for (int k = 0; k < NSLOT; ++k) a[k] *= inv;
    #pragma unroll
    for (int i = 0; i < 4; ++i) {
        int d = lane + 32 * i;
        float c = 0.f;
        #pragma unroll
        for (int k = 0; k < NSLOT; ++k) c = fmaf(a[k], cont[k][d], c);
        __nv_bfloat16 h = __float2bfloat16(c);
        wmh[(size_t)t * DSLOT + d] = h;
        wml[(size_t)t * DSLOT + d] = __float2bfloat16(c - __bfloat162float(h));
    }
}

// ---------------- small reductions ----------------
__global__ void pressure_kernel(const float* __restrict__ attn, float* __restrict__ rp)
{
    int b = blockIdx.x / NSLOT, k = blockIdx.x % NSLOT;
    __shared__ float sh[256];
    float s = 0.f;
    for (int si = threadIdx.x; si < SEQ; si += 256)
        s += attn[((size_t)b * SEQ + si) * NSLOT + k];
    sh[threadIdx.x] = s;
    __syncthreads();
    for (int o = 128; o; o >>= 1) {
        if (threadIdx.x < o) sh[threadIdx.x] += sh[threadIdx.x + o];
        __syncthreads();
    }
    if (threadIdx.x == 0) rp[blockIdx.x] = sh[0];
}

__global__ void freshness_kernel(const float* __restrict__ rp, const float* __restrict__ wm,
                                 float* __restrict__ nf)
{
    int t = threadIdx.x;
    int b = t / NSLOT;
    __shared__ float s[BATCH * NSLOT];
    s[t] = rp[t];
    __syncthreads();
    float mx = 1e-8f;
    #pragma unroll
    for (int k = 0; k < NSLOT; ++k) mx = fmaxf(mx, s[b * NSLOT + k]);
    float decay = 1.f - (s[t] / mx) * (1.f - READ_DECAY);
    nf[t] = wm[(size_t)t * (DSLOT + 1) + DSLOT] * decay;
}

__global__ void impsum_kernel(const float* __restrict__ logit, const float* __restrict__ wt,
                              float* __restrict__ outsum)
{
    int b = blockIdx.x;
    float temp = fmaxf(wt[0], 0.1f);
    __shared__ float sh[1024];
    float s = 0.f;
    for (int i = threadIdx.x; i < SEQ; i += 1024)
        s += expf(logit[(size_t)b * SEQ + i] / temp);
    sh[threadIdx.x] = s;
    __syncthreads();
    for (int o = 512; o; o >>= 1) {
        if (threadIdx.x < o) sh[threadIdx.x] += sh[threadIdx.x + o];
        __syncthreads();
    }
    if (threadIdx.x == 0) outsum[b] = sh[0];
}

__global__ void slotsel_kernel(const float* __restrict__ wsc, const float* __restrict__ nf,
                               const float* __restrict__ logit, const float* __restrict__ impsum,
                               const float* __restrict__ wg, const float* __restrict__ wt,
                               float* __restrict__ sel_onehot, int* __restrict__ sel_idx,
                               float* __restrict__ ww_out)
{
    int t = blockIdx.x * 256 + threadIdx.x;
    int b = t / SEQ;
    float temp = fmaxf(wt[0], 0.1f);
    float best = wsc[(size_t)t * NSLOT] - 2.f * nf[b * NSLOT];
    int bi = 0;
    #pragma unroll
    for (int k = 1; k < NSLOT; ++k) {
        float v = wsc[(size_t)t * NSLOT + k] - 2.f * nf[b * NSLOT + k];
        if (v > best) { best = v; bi = k; }
    }
    float imp = expf(logit[t] / temp) / (impsum[b] + 1e-8f) * (float)SEQ;
    sel_idx[t] = bi;
    ww_out[t] = wg[t] * imp;
    #pragma unroll
    for (int k = 0; k < NSLOT; ++k)
        sel_onehot[(size_t)t * NSLOT + k] = (k == bi) ? 1.f : 0.f;
}

__global__ void slotagg_kernel(const int* __restrict__ sel, const float* __restrict__ ww,
                               const float* __restrict__ xslot, const float* __restrict__ wm,
                               const float* __restrict__ nf, float* __restrict__ wm_out)
{
    int bk = blockIdx.x;
    int b = bk / NSLOT, k = bk % NSLOT;
    int d = threadIdx.x;
    float acc = 0.f, st = 0.f;
    const int s0 = b * SEQ;
    for (int si = 0; si < SEQ; ++si) {
        int tt = s0 + si;
        if (sel[tt] == k) {
            float w = ww[tt];
            st += w;
            acc = fmaf(w, xslot[(size_t)tt * DSLOT + d], acc);
        }
    }
    float nc = acc / fmaxf(st, 1e-8f);
    float has = (st > 0.1f) ? 1.f : 0.f;
    float cont = wm[(size_t)bk * (DSLOT + 1) + d];
    wm_out[(size_t)bk * (DSLOT + 1) + d] = has * nc + (1.f - has) * cont;
    if (d == 0)
        wm_out[(size_t)bk * (DSLOT + 1) + DSLOT] = has * 1.f + (1.f - has) * nf[bk];
}

__global__ void enhance_kernel(const float* __restrict__ x, const float* __restrict__ fused,
                               const float* __restrict__ gate, float* __restrict__ out)
{
    size_t idx = (size_t)blockIdx.x * 256 + threadIdx.x;
    int t = (int)(idx >> 8);
    float g = gate[t];
    float4 xv = ((const float4*)x)[idx];
    float4 fv = ((const float4*)fused)[idx];
    float4 o;
    o.x = (1.f - g) * xv.x + g * fv.x;
    o.y = (1.f - g) * xv.y + g * fv.y;
    o.z = (1.f - g) * xv.z + g * fv.z;
    o.w = (1.f - g) * xv.w + g * fv.w;
    ((float4*)out)[idx] = o;
}

// ---------------- host ----------------
static void* symv(const void* s) { void* p = nullptr; cudaGetSymbolAddress(&p, s); return p; }

extern "C" void kernel_launch(void* const* d_in, const int* in_sizes, int n_in,
                              void* d_out, int out_size)
{
    const float* x      = (const float*)d_in[0];
    const float* wm     = (const float*)d_in[1];
    const float* rq_w   = (const float*)d_in[2];
    const float* rq_b   = (const float*)d_in[3];
    const float* fwm_w  = (const float*)d_in[4];
    const float* fwm_b  = (const float*)d_in[5];
    const float* rg1_w  = (const float*)d_in[6];
    const float* rg1_b  = (const float*)d_in[7];
    const float* rg2_w  = (const float*)d_in[8];
    const float* rg2_b  = (const float*)d_in[9];
    const float* fus_w  = (const float*)d_in[10];
    const float* fus_b  = (const float*)d_in[11];
    const float* twm_w  = (const float*)d_in[12];
    const float* twm_b  = (const float*)d_in[13];
    const float* wq_w   = (const float*)d_in[14];
    const float* wq_b   = (const float*)d_in[15];
    const float* imp1_w = (const float*)d_in[16];
    const float* imp1_b = (const float*)d_in[17];
    const float* imp2_w = (const float*)d_in[18];
    const float* imp2_b = (const float*)d_in[19];
    const float* wd1_w  = (const float*)d_in[20];
    const float* wd1_b  = (const float*)d_in[21];
    const float* wd2_w  = (const float*)d_in[22];
    const float* wd2_b  = (const float*)d_in[23];
    const float* wt     = (const float*)d_in[24];

    float* out = (float*)d_out;
    float* h1     = (float*)symv(g_h1);
    float* query  = (float*)symv(g_query);
    float* fused  = (float*)symv(g_fused);
    float* xslot  = (float*)symv(g_xslot);
    float* implog = (float*)symv(g_implogit);
    float* impsum = (float*)symv(g_impsum);
    float* wqbuf  = (float*)symv(g_wqv);
    float* wsc    = (float*)symv(g_wsc);
    float* nf     = (float*)symv(g_nf);
    float* rp     = (float*)symv(g_rp);
    int*   selidx = (int*)symv(g_sel);
    float* wwbuf  = (float*)symv(g_ww);
    __nv_bfloat16* xh   = (__nv_bfloat16*)symv(g_xh);
    __nv_bfloat16* xl   = (__nv_bfloat16*)symv(g_xl);
    __nv_bfloat16* ctxh = (__nv_bfloat16*)symv(g_ctxh);
    __nv_bfloat16* ctxl = (__nv_bfloat16*)symv(g_ctxl);
    __nv_bfloat16* conh = (__nv_bfloat16*)symv(g_conh);
    __nv_bfloat16* conl = (__nv_bfloat16*)symv(g_conl);
    __nv_bfloat16* wmh  = (__nv_bfloat16*)symv(g_wmh);
    __nv_bfloat16* wml  = (__nv_bfloat16*)symv(g_wml);
    __nv_bfloat16* wth  = (__nv_bfloat16*)symv(g_wth);
    __nv_bfloat16* wtl  = (__nv_bfloat16*)symv(g_wtl);

    cudaFuncSetAttribute(tc_gemm<0>, cudaFuncAttributeMaxDynamicSharedMemorySize, SMEMB);
    cudaFuncSetAttribute(tc_gemm<1>, cudaFuncAttributeMaxDynamicSharedMemorySize, SMEMB);
    cudaFuncSetAttribute(tc_gemm<2>, cudaFuncAttributeMaxDynamicSharedMemorySize, SMEMB);

    dim3 tb8(32, 8);

    split_x_kernel<<<NT*DMODEL/4/256, 256>>>((const float4*)x, xh, xl);
    wsplit_kernel<<<dim3(1024/32,  512/32), tb8>>>(rg1_w, 1024,  512, wth+OFF_RG1, wtl+OFF_RG1);
    wsplit_kernel<<<dim3(1024/32,  128/32), tb8>>>(rq_w,  1024,  128, wth+OFF_RQ,  wtl+OFF_RQ);
    wsplit_kernel<<<dim3( 128/32, 1024/32), tb8>>>(fwm_w,  128, 1024, wth+OFF_FWM, wtl+OFF_FWM);
    wsplit_kernel<<<dim3(2048/32, 1024/32), tb8>>>(fus_w, 2048, 1024, wth+OFF_FUS, wtl+OFF_FUS);
    wsplit_kernel<<<dim3(1024/32,  128/32), tb8>>>(twm_w, 1024,  128, wth+OFF_TWM, wtl+OFF_TWM);
    wsplit_kernel<<<dim3(1024/32,  128/32), tb8>>>(wq_w,  1024,  128, wth+OFF_WQ,  wtl+OFF_WQ);
    wsplit_kernel<<<dim3(1024/32,  512/32), tb8>>>(imp1_w,1024,  512, wth+OFF_IMP, wtl+OFF_IMP);
    wsplit_kernel<<<dim3(1152/32,  512/32), tb8>>>(wd1_w, 1152,  512, wth+OFF_WD1, wtl+OFF_WD1);

    // read gate
    tc_gemm<1><<<dim3(4,128), 256, SMEMB>>>(xh, xl, 1024, nullptr, nullptr,
        wth+OFF_RG1, wtl+OFF_RG1, 1024, rg1_b, h1, nullptr, nullptr, 512);
    rowdot_kernel<<<NT/8, 256>>>(h1, rg2_w, rg2_b, wt, 0, out + O_GATE);

    // read attention path
    tc_gemm<0><<<dim3(1,128), 256, SMEMB>>>(xh, xl, 1024, nullptr, nullptr,
        wth+OFF_RQ, wtl+OFF_RQ, 1024, rq_b, query, nullptr, nullptr, 128);
    read_attn_kernel<<<NT/8, 256>>>(query, wm, out + O_ATTN, ctxh, ctxl);
    tc_gemm<2><<<dim3(8,128), 256, SMEMB>>>(ctxh, ctxl, 128, nullptr, nullptr,
        wth+OFF_FWM, wtl+OFF_FWM, 128, fwm_b, nullptr, conh, conl, 1024);
    tc_gemm<0><<<dim3(8,128), 256, SMEMB>>>(xh, xl, 1024, conh, conl,
        wth+OFF_FUS, wtl+OFF_FUS, 2048, fus_b, fused, nullptr, nullptr, 1024);
    enhance_kernel<<<(NT*DMODEL/4)/256, 256>>>(x, fused, out + O_GATE, out + O_XENH);

    pressure_kernel<<<BATCH*NSLOT, 256>>>(out + O_ATTN, rp);
    freshness_kernel<<<1, BATCH*NSLOT>>>(rp, wm, nf);

    // write path
    tc_gemm<0><<<dim3(1,128), 256, SMEMB>>>(xh, xl, 1024, nullptr, nullptr,
        wth+OFF_TWM, wtl+OFF_TWM, 1024, twm_b, xslot, nullptr, nullptr, 128);
    tc_gemm<1><<<dim3(4,128), 256, SMEMB>>>(xh, xl, 1024, nullptr, nullptr,
        wth+OFF_IMP, wtl+OFF_IMP, 1024, imp1_b, h1, nullptr, nullptr, 512);
    rowdot_kernel<<<NT/8, 256>>>(h1, imp2_w, imp2_b, wt, 1, implog);
    impsum_kernel<<<BATCH, 1024>>>(implog, wt, impsum);

    tc_gemm<0><<<dim3(1,128), 256, SMEMB>>>(xh, xl, 1024, nullptr, nullptr,
        wth+OFF_WQ, wtl+OFF_WQ, 1024, wq_b, wqbuf, nullptr, nullptr, 128);
    write_attn_kernel<<<NT/8, 256>>>(wqbuf, wm, wsc, wmh, wml);

    tc_gemm<1><<<dim3(4,128), 256, SMEMB>>>(xh, xl, 1024, wmh, wml,
        wth+OFF_WD1, wtl+OFF_WD1, 1152, wd1_b, h1, nullptr, nullptr, 512);
    rowdot_kernel<<<NT/8, 256>>>(h1, wd2_w, wd2_b, wt, 2, out + O_WG);

    slotsel_kernel<<<NT/256, 256>>>(wsc, nf, implog, impsum, out + O_WG, wt,
                                    out + O_SEL, selidx, wwbuf);
    slotagg_kernel<<<BATCH*NSLOT, DSLOT>>>(selidx, wwbuf, xslot, wm, nf, out + O_WM);
}

// round 8
// speedup vs baseline: 2.6269x; 1.2205x over previous
#include <cuda_runtime.h>
#include <cuda_bf16.h>
#include <math.h>
#include <stdint.h>

#define BATCH   4
#define SEQ     4096
#define NT      (BATCH*SEQ)
#define DMODEL  1024
#define DSLOT   128
#define NSLOT   8
#define HID     512
#define SCALE   (0.08838834764831845f)
#define FRESH_THR 0.1f
#define READ_DECAY 0.3f

#define O_XENH  ((size_t)0)
#define O_WM    ((size_t)16777216)
#define O_GATE  ((size_t)16781344)
#define O_WG    ((size_t)16797728)
#define O_ATTN  ((size_t)16814112)
#define O_SEL   ((size_t)16945184)

// ---------------- scratch ----------------
__device__ float g_h1[NT*HID];          // wd1 hidden
__device__ float g_hg[NT*1024];         // rg1|imp1 merged hidden
__device__ float g_q3[NT*384];          // query|xslot|wq merged
__device__ float g_fused[NT*DMODEL];
__device__ float g_implogit[NT];
__device__ float g_impsum[BATCH];
__device__ float g_wsc[NT*NSLOT];
__device__ float g_nf[BATCH*NSLOT];
__device__ float g_rp[BATCH*NSLOT];
__device__ int   g_sel[NT];
__device__ float g_ww[NT];
__device__ float g_bg[1024];
__device__ float g_b3[384];
__device__ float g_pacc[256*128];
__device__ float g_pst[256];

__device__ __nv_bfloat16 g_xh[NT*DMODEL],  g_xl[NT*DMODEL];
__device__ __nv_bfloat16 g_ctxh[NT*DSLOT], g_ctxl[NT*DSLOT];
__device__ __nv_bfloat16 g_conh[NT*DMODEL],g_conl[NT*DMODEL];
__device__ __nv_bfloat16 g_wmh[NT*DSLOT],  g_wml[NT*DSLOT];

#define WT_TOTAL 4259840
__device__ __nv_bfloat16 g_wth[WT_TOTAL], g_wtl[WT_TOTAL];
#define OFF_G   0
#define OFF_RG1 (OFF_G)
#define OFF_IMP (OFF_G + 524288)
#define OFF_Q3  1048576
#define OFF_RQ  (OFF_Q3)
#define OFF_TWM (OFF_Q3 + 131072)
#define OFF_WQ  (OFF_Q3 + 262144)
#define OFF_FWM 1441792
#define OFF_FUS 1572864
#define OFF_WD1 3670016

__device__ __forceinline__ float gelu_exact(float v) {
    return 0.5f * v * (1.0f + erff(v * 0.70710678118654752f));
}

// ---------------- asm helpers ----------------
__device__ __forceinline__ uint32_t smem_u32(const void* p) {
    uint32_t a;
    asm("{ .reg .u64 t; cvta.to.shared.u64 t, %1; cvt.u32.u64 %0, t; }" : "=r"(a) : "l"(p));
    return a;
}
__device__ __forceinline__ void cpa16(uint32_t s, const void* g) {
    asm volatile("cp.async.cg.shared.global [%0], [%1], 16;\n" :: "r"(s), "l"(g));
}
__device__ __forceinline__ void cp_commit() { asm volatile("cp.async.commit_group;\n" ::); }

__device__ __forceinline__ void mma_bf16(float* c, uint32_t a0, uint32_t a1, uint32_t a2,
                                         uint32_t a3, uint32_t b0, uint32_t b1) {
    asm volatile(
        "mma.sync.aligned.m16n8k16.row.col.f32.bf16.bf16.f32 "
        "{%0,%1,%2,%3},{%4,%5,%6,%7},{%8,%9},{%0,%1,%2,%3};"
        : "+f"(c[0]), "+f"(c[1]), "+f"(c[2]), "+f"(c[3])
        : "r"(a0), "r"(a1), "r"(a2), "r"(a3), "r"(b0), "r"(b1));
}
#define LDSM4(r, addr) \
    asm volatile("ldmatrix.sync.aligned.m8n8.x4.shared.b16 {%0,%1,%2,%3}, [%4];" \
        : "=r"((r)[0]), "=r"((r)[1]), "=r"((r)[2]), "=r"((r)[3]) : "r"(addr))

// ---------------- mma.sync bf16x3 GEMM ----------------
// BM=BN=128, KC=32/chunk, 3-stage cp.async, 8 warps (2m x 4n), 64x32 warp tile.
#define SROW   80
#define TILEB  10240
#define STAGEB 40960
#define NSTAGE 3
#define SMEMB  (NSTAGE*STAGEB)

template<int MODE>   // 0: f32 out, 1: f32 gelu, 2: bf16 hi/lo out
__global__ void __launch_bounds__(256) tc_gemm(
    const __nv_bfloat16* __restrict__ A1h, const __nv_bfloat16* __restrict__ A1l, int K1,
    const __nv_bfloat16* __restrict__ A2h, const __nv_bfloat16* __restrict__ A2l,
    const __nv_bfloat16* __restrict__ Wh,  const __nv_bfloat16* __restrict__ Wl,  int Ktot,
    const float* __restrict__ bias,
    float* __restrict__ Cf, __nv_bfloat16* __restrict__ Chi, __nv_bfloat16* __restrict__ Clo,
    int N)
{
    extern __shared__ __align__(16) char smem[];
    const uint32_t sb = smem_u32(smem);
    const int tid = threadIdx.x, wid = tid >> 5, lane = tid & 31;
    const int g = lane >> 2, tg = lane & 3;
    const int m0 = blockIdx.y * 128, bn = blockIdx.x * 128;
    const int wm = (wid & 1) * 64, wn = (wid >> 1) * 32;

    float acc[4][4][4] = {};
    const int nchunk = Ktot / 32;

    auto load_chunk = [&](int ci, int buf) {
        int k0 = ci * 32;
        const __nv_bfloat16 *Ah, *Al; int sA, kA;
        if (k0 < K1) { Ah = A1h; Al = A1l; sA = K1; kA = k0; }
        else         { Ah = A2h; Al = A2l; sA = Ktot - K1; kA = k0 - K1; }
        uint32_t base = sb + buf * STAGEB;
        #pragma unroll
        for (int u = tid; u < 512; u += 256) {
            int r = u >> 2, c = (u & 3) * 8;
            uint32_t o = (uint32_t)(r * SROW + c * 2);
            size_t gi = (size_t)(m0 + r) * sA + kA + c;
            cpa16(base + o, Ah + gi);
            cpa16(base + TILEB + o, Al + gi);
        }
        #pragma unroll
        for (int u = tid; u < 512; u += 256) {
            int r = u >> 2, c = (u & 3) * 8;
            uint32_t o = (uint32_t)(r * SROW + c * 2);
            size_t gi = (size_t)(bn + r) * Ktot + k0 + c;
            cpa16(base + 2 * TILEB + o, Wh + gi);
            cpa16(base + 3 * TILEB + o, Wl + gi);
        }
        cp_commit();
    };

    // ldmatrix lane offsets
    const uint32_t aoff = (uint32_t)(((lane & 7) + ((lane >> 3) & 1) * 8) * SROW
                                     + ((lane >> 4) & 1) * 16);
    const uint32_t boff = (uint32_t)(((lane & 7) + ((lane >> 4) & 1) * 8) * SROW
                                     + ((lane >> 3) & 1) * 16);

    load_chunk(0, 0);
    if (nchunk > 1) load_chunk(1, 1);

    for (int ci = 0; ci < nchunk; ++ci) {
        if (ci + 2 < nchunk) {
            load_chunk(ci + 2, (ci + 2) % NSTAGE);
            asm volatile("cp.async.wait_group 2;" ::: "memory");
        } else if (ci + 1 < nchunk) {
            asm volatile("cp.async.wait_group 1;" ::: "memory");
        } else {
            asm volatile("cp.async.wait_group 0;" ::: "memory");
        }
        __syncthreads();

        uint32_t st = sb + (ci % NSTAGE) * STAGEB;
        uint32_t sAh = st, sAl = st + TILEB, sBh = st + 2 * TILEB, sBl = st + 3 * TILEB;

        #pragma unroll
        for (int ks = 0; ks < 2; ++ks) {
            uint32_t ka = (uint32_t)(ks * 32);
            uint32_t ah[4][4], al[4][4], bh[2][4], bl[2][4];
            uint32_t abase = (uint32_t)(wm * SROW) + aoff + ka;
            #pragma unroll
            for (int mi = 0; mi < 4; ++mi) {
                LDSM4(ah[mi], sAh + abase + mi * 16 * SROW);
                LDSM4(al[mi], sAl + abase + mi * 16 * SROW);
            }
            uint32_t bbase = (uint32_t)(wn * SROW) + boff + ka;
            #pragma unroll
            for (int np = 0; np < 2; ++np) {
                LDSM4(bh[np], sBh + bbase + np * 16 * SROW);
                LDSM4(bl[np], sBl + bbase + np * 16 * SROW);
            }
            #pragma unroll
            for (int np = 0; np < 2; ++np) {
                #pragma unroll
                for (int sub = 0; sub < 2; ++sub) {
                    int ni = np * 2 + sub;
                    uint32_t h0 = bh[np][sub * 2], h1 = bh[np][sub * 2 + 1];
                    uint32_t l0 = bl[np][sub * 2], l1 = bl[np][sub * 2 + 1];
                    #pragma unroll
                    for (int mi = 0; mi < 4; ++mi) {
                        mma_bf16(acc[mi][ni], ah[mi][0], ah[mi][1], ah[mi][2], ah[mi][3], h0, h1);
                        mma_bf16(acc[mi][ni], ah[mi][0], ah[mi][1], ah[mi][2], ah[mi][3], l0, l1);
                        mma_bf16(acc[mi][ni], al[mi][0], al[mi][1], al[mi][2], al[mi][3], h0, h1);
                    }
                }
            }
        }
        __syncthreads();
    }

    #pragma unroll
    for (int mi = 0; mi < 4; ++mi) {
        #pragma unroll
        for (int ni = 0; ni < 4; ++ni) {
            int row = m0 + wm + mi * 16 + g;
            int col = bn + wn + ni * 8 + tg * 2;
            float b0 = bias[col], b1 = bias[col + 1];
            #pragma unroll
            for (int h = 0; h < 2; ++h) {
                int r = row + h * 8;
                float v0 = acc[mi][ni][h * 2]     + b0;
                float v1 = acc[mi][ni][h * 2 + 1] + b1;
                if (MODE == 1) { v0 = gelu_exact(v0); v1 = gelu_exact(v1); }
                if (MODE == 2) {
                    __nv_bfloat16 h0 = __float2bfloat16(v0);
                    __nv_bfloat16 h1 = __float2bfloat16(v1);
                    __nv_bfloat162 hp; hp.x = h0; hp.y = h1;
                    __nv_bfloat162 lp;
                    lp.x = __float2bfloat16(v0 - __bfloat162float(h0));
                    lp.y = __float2bfloat16(v1 - __bfloat162float(h1));
                    *(__nv_bfloat162*)&Chi[(size_t)r * N + col] = hp;
                    *(__nv_bfloat162*)&Clo[(size_t)r * N + col] = lp;
                } else {
                    float2 o; o.x = v0; o.y = v1;
                    *(float2*)&Cf[(size_t)r * N + col] = o;
                }
            }
        }
    }
}

// ---------------- split x ----------------
__global__ void split_x_kernel(const float4* __restrict__ x,
                               __nv_bfloat16* __restrict__ h, __nv_bfloat16* __restrict__ l)
{
    size_t i = (size_t)blockIdx.x * 256 + threadIdx.x;
    float4 v = x[i];
    float a[4] = {v.x, v.y, v.z, v.w};
    __nv_bfloat16 hh[4];
    #pragma unroll
    for (int c = 0; c < 4; ++c) hh[c] = __float2bfloat16(a[c]);
    __nv_bfloat162 hp0, hp1, lp0, lp1;
    hp0.x = hh[0]; hp0.y = hh[1]; hp1.x = hh[2]; hp1.y = hh[3];
    lp0.x = __float2bfloat16(a[0] - __bfloat162float(hh[0]));
    lp0.y = __float2bfloat16(a[1] - __bfloat162float(hh[1]));
    lp1.x = __float2bfloat16(a[2] - __bfloat162float(hh[2]));
    lp1.y = __float2bfloat16(a[3] - __bfloat162float(hh[3]));
    *(__nv_bfloat162*)&h[i * 4]     = hp0;
    *(__nv_bfloat162*)&h[i * 4 + 2] = hp1;
    *(__nv_bfloat162*)&l[i * 4]     = lp0;
    *(__nv_bfloat162*)&l[i * 4 + 2] = lp1;
}

// ---------------- weight transpose + split ----------------
__global__ void wsplit_kernel(const float* __restrict__ W, int K, int N,
                              __nv_bfloat16* __restrict__ Th, __nv_bfloat16* __restrict__ Tl)
{
    __shared__ float tile[32][33];
    int kb = blockIdx.x * 32, nb = blockIdx.y * 32;
    int tx = threadIdx.x, ty = threadIdx.y;
    #pragma unroll
    for (int i = 0; i < 4; ++i)
        tile[ty + i * 8][tx] = W[(size_t)(kb + ty + i * 8) * N + nb + tx];
    __syncthreads();
    #pragma unroll
    for (int i = 0; i < 4; ++i) {
        int n = nb + ty + i * 8, k = kb + tx;
        float v = tile[tx][ty + i * 8];
        size_t o = (size_t)n * K + k;
        __nv_bfloat16 h = __float2bfloat16(v);
        Th[o] = h;
        Tl[o] = __float2bfloat16(v - __bfloat162float(h));
    }
}

// ---------------- bias concat ----------------
__global__ void biascat_kernel(const float* rg1_b, const float* imp1_b,
                               const float* rq_b, const float* twm_b, const float* wq_b,
                               float* bg, float* b3)
{
    int i = blockIdx.x * 256 + threadIdx.x;
    if (i < 512) bg[i] = rg1_b[i];
    else if (i < 1024) bg[i] = imp1_b[i - 512];
    else if (i < 1152) b3[i - 1024] = rq_b[i - 1024];
    else if (i < 1280) b3[i - 1024] = twm_b[i - 1152];
    else if (i < 1408) b3[i - 1024] = wq_b[i - 1280];
}

// ---------------- row-dot (strided hidden) ----------------
__global__ void rowdot_kernel(const float* __restrict__ Hm, int stride,
                              const float* __restrict__ w, const float* __restrict__ bias,
                              const float* __restrict__ wt, int mode,
                              float* __restrict__ out)
{
    __shared__ float ws[HID];
    for (int i = threadIdx.x; i < HID; i += blockDim.x) ws[i] = w[i];
    __syncthreads();
    int warp = threadIdx.x >> 5, lane = threadIdx.x & 31;
    int row = blockIdx.x * 8 + warp;
    const float* h = Hm + (size_t)row * stride;
    float s = 0.f;
    for (int i = lane; i < HID; i += 32) s = fmaf(h[i], ws[i], s);
    #pragma unroll
    for (int o = 16; o; o >>= 1) s += __shfl_xor_sync(0xffffffffu, s, o);
    if (lane == 0) {
        float z = s + bias[0];
        if (mode == 1) out[row] = z;
        else {
            if (mode == 2) z /= fmaxf(wt[0], 0.1f);
            out[row] = 1.f / (1.f + expf(-z));
        }
    }
}

// ---------------- read attention (query stride 384) ----------------
__global__ void read_attn_kernel(const float* __restrict__ query,
                                 const float* __restrict__ wm,
                                 float* __restrict__ attn_out,
                                 __nv_bfloat16* __restrict__ ctxh,
                                 __nv_bfloat16* __restrict__ ctxl)
{
    __shared__ float cont[NSLOT][DSLOT];
    __shared__ float fresh[NSLOT];
    int tid = threadIdx.x;
    int tokenBase = blockIdx.x * 8;
    int b = tokenBase / SEQ;
    for (int i = tid; i < NSLOT * DSLOT; i += 256) {
        int k = i / DSLOT, d = i % DSLOT;
        cont[k][d] = wm[((size_t)b * NSLOT + k) * (DSLOT + 1) + d];
    }
    if (tid < NSLOT) fresh[tid] = wm[((size_t)b * NSLOT + tid) * (DSLOT + 1) + DSLOT];
    __syncthreads();
    int warp = tid >> 5, lane = tid & 31;
    int t = tokenBase + warp;
    const float* q = query + (size_t)t * 384;
    float ql[4];
    #pragma unroll
    for (int i = 0; i < 4; ++i) ql[i] = q[lane + 32 * i];
    float a[NSLOT];
    #pragma unroll
    for (int k = 0; k < NSLOT; ++k) {
        float s = 0.f;
        #pragma unroll
        for (int i = 0; i < 4; ++i) s = fmaf(ql[i], cont[k][lane + 32 * i], s);
        #pragma unroll
        for (int o = 16; o; o >>= 1) s += __shfl_xor_sync(0xffffffffu, s, o);
        s *= SCALE;
        if (fresh[k] < FRESH_THR) s = -1e9f;
        a[k] = s;
    }
    float mx = a[0];
    #pragma unroll
    for (int k = 1; k < NSLOT; ++k) mx = fmaxf(mx, a[k]);
    float sum = 0.f;
    #pragma unroll
    for (int k = 0; k < NSLOT; ++k) { a[k] = expf(a[k] - mx); sum += a[k]; }
    float inv = 1.f / sum;
    #pragma unroll
    for (int k = 0; k < NSLOT; ++k) a[k] *= inv;
    if (lane == 0) {
        #pragma unroll
        for (int k = 0; k < NSLOT; ++k) attn_out[(size_t)t * NSLOT + k] = a[k];
    }
    #pragma unroll
    for (int i = 0; i < 4; ++i) {
        int d = lane + 32 * i;
        float c = 0.f;
        #pragma unroll
        for (int k = 0; k < NSLOT; ++k) c = fmaf(a[k], cont[k][d], c);
        __nv_bfloat16 h = __float2bfloat16(c);
        ctxh[(size_t)t * DSLOT + d] = h;
        ctxl[(size_t)t * DSLOT + d] = __float2bfloat16(c - __bfloat162float(h));
    }
}

// ---------------- write attention (wq stride 384) ----------------
__global__ void write_attn_kernel(const float* __restrict__ wq,
                                  const float* __restrict__ wm,
                                  float* __restrict__ wsc_out,
                                  __nv_bfloat16* __restrict__ wmh,
                                  __nv_bfloat16* __restrict__ wml)
{
    __shared__ float cont[NSLOT][DSLOT];
    int tid = threadIdx.x;
    int tokenBase = blockIdx.x * 8;
    int b = tokenBase / SEQ;
    for (int i = tid; i < NSLOT * DSLOT; i += 256) {
        int k = i / DSLOT, d = i % DSLOT;
        cont[k][d] = wm[((size_t)b * NSLOT + k) * (DSLOT + 1) + d];
    }
    __syncthreads();
    int warp = tid >> 5, lane = tid & 31;
    int t = tokenBase + warp;
    const float* q = wq + (size_t)t * 384;
    float ql[4];
    #pragma unroll
    for (int i = 0; i < 4; ++i) ql[i] = q[lane + 32 * i];
    float a[NSLOT];
    #pragma unroll
    for (int k = 0; k < NSLOT; ++k) {
        float s = 0.f;
        #pragma unroll
        for (int i = 0; i < 4; ++i) s = fmaf(ql[i], cont[k][lane + 32 * i], s);
        #pragma unroll
        for (int o = 16; o; o >>= 1) s += __shfl_xor_sync(0xffffffffu, s, o);
        a[k] = s * SCALE;
    }
    if (lane == 0) {
        #pragma unroll
        for (int k = 0; k < NSLOT; ++k) wsc_out[(size_t)t * NSLOT + k] = a[k];
    }
    float mx = a[0];
    #pragma unroll
    for (int k = 1; k < NSLOT; ++k) mx = fmaxf(mx, a[k]);
    float sum = 0.f;
    #pragma unroll
    for (int k = 0; k < NSLOT; ++k) { a[k] = expf(a[k] - mx); sum += a[k]; }
    float inv = 1.f / sum;
    #pragma unroll
    for (int k = 0; k < NSLOT; ++k) a[k] *= inv;
    #pragma unroll
    for (int i = 0; i < 4; ++i) {
        int d = lane + 32 * i;
        float c = 0.f;
        #pragma unroll
        for (int k = 0; k < NSLOT; ++k) c = fmaf(a[k], cont[k][d], c);
        __nv_bfloat16 h = __float2bfloat16(c);
        wmh[(size_t)t * DSLOT + d] = h;
        wml[(size_t)t * DSLOT + d] = __float2bfloat16(c - __bfloat162float(h));
    }
}

// ---------------- small reductions ----------------
__global__ void pressure_kernel(const float* __restrict__ attn, float* __restrict__ rp)
{
    int b = blockIdx.x / NSLOT, k = blockIdx.x % NSLOT;
    __shared__ float sh[256];
    float s = 0.f;
    for (int si = threadIdx.x; si < SEQ; si += 256)
        s += attn[((size_t)b * SEQ + si) * NSLOT + k];
    sh[threadIdx.x] = s;
    __syncthreads();
    for (int o = 128; o; o >>= 1) {
        if (threadIdx.x < o) sh[threadIdx.x] += sh[threadIdx.x + o];
        __syncthreads();
    }
    if (threadIdx.x == 0) rp[blockIdx.x] = sh[0];
}

__global__ void freshness_kernel(const float* __restrict__ rp, const float* __restrict__ wm,
                                 float* __restrict__ nf)
{
    int t = threadIdx.x;
    int b = t / NSLOT;
    __shared__ float s[BATCH * NSLOT];
    s[t] = rp[t];
    __syncthreads();
    float mx = 1e-8f;
    #pragma unroll
    for (int k = 0; k < NSLOT; ++k) mx = fmaxf(mx, s[b * NSLOT + k]);
    float decay = 1.f - (s[t] / mx) * (1.f - READ_DECAY);
    nf[t] = wm[(size_t)t * (DSLOT + 1) + DSLOT] * decay;
}

__global__ void impsum_kernel(const float* __restrict__ logit, const float* __restrict__ wt,
                              float* __restrict__ outsum)
{
    int b = blockIdx.x;
    float temp = fmaxf(wt[0], 0.1f);
    __shared__ float sh[1024];
    float s = 0.f;
    for (int i = threadIdx.x; i < SEQ; i += 1024)
        s += expf(logit[(size_t)b * SEQ + i] / temp);
    sh[threadIdx.x] = s;
    __syncthreads();
    for (int o = 512; o; o >>= 1) {
        if (threadIdx.x < o) sh[threadIdx.x] += sh[threadIdx.x + o];
        __syncthreads();
    }
    if (threadIdx.x == 0) outsum[b] = sh[0];
}

__global__ void slotsel_kernel(const float* __restrict__ wsc, const float* __restrict__ nf,
                               const float* __restrict__ logit, const float* __restrict__ impsum,
                               const float* __restrict__ wg, const float* __restrict__ wt,
                               float* __restrict__ sel_onehot, int* __restrict__ sel_idx,
                               float* __restrict__ ww_out)
{
    int t = blockIdx.x * 256 + threadIdx.x;
    int b = t / SEQ;
    float temp = fmaxf(wt[0], 0.1f);
    float best = wsc[(size_t)t * NSLOT] - 2.f * nf[b * NSLOT];
    int bi = 0;
    #pragma unroll
    for (int k = 1; k < NSLOT; ++k) {
        float v = wsc[(size_t)t * NSLOT + k] - 2.f * nf[b * NSLOT + k];
        if (v > best) { best = v; bi = k; }
    }
    float imp = expf(logit[t] / temp) / (impsum[b] + 1e-8f) * (float)SEQ;
    sel_idx[t] = bi;
    ww_out[t] = wg[t] * imp;
    #pragma unroll
    for (int k = 0; k < NSLOT; ++k)
        sel_onehot[(size_t)t * NSLOT + k] = (k == bi) ? 1.f : 0.f;
}

// ---------------- slot aggregation: 2-phase ----------------
#define NSEG 8
#define SEGLEN (SEQ/NSEG)
__global__ void slotagg1_kernel(const int* __restrict__ sel, const float* __restrict__ ww,
                                const float* __restrict__ xslot,
                                float* __restrict__ pacc, float* __restrict__ pst)
{
    int blk = blockIdx.x;          // bk*NSEG + seg
    int bk = blk / NSEG, seg = blk % NSEG;
    int b = bk / NSLOT, k = bk % NSLOT;
    int d = threadIdx.x;
    float acc = 0.f, st = 0.f;
    const int s0 = b * SEQ + seg * SEGLEN;
    for (int si = 0; si < SEGLEN; ++si) {
        int tt = s0 + si;
        if (sel[tt] == k) {
            float w = ww[tt];
            st += w;
            acc = fmaf(w, xslot[(size_t)tt * 384 + d], acc);
        }
    }
    pacc[(size_t)blk * 128 + d] = acc;
    if (d == 0) pst[blk] = st;
}

__global__ void slotagg2_kernel(const float* __restrict__ pacc, const float* __restrict__ pst,
                                const float* __restrict__ wm, const float* __restrict__ nf,
                                float* __restrict__ wm_out)
{
    int bk = blockIdx.x;
    int d = threadIdx.x;
    float acc = 0.f, st = 0.f;
    #pragma unroll
    for (int s = 0; s < NSEG; ++s) {
        acc += pacc[(size_t)(bk * NSEG + s) * 128 + d];
        st  += pst[bk * NSEG + s];
    }
    float nc = acc / fmaxf(st, 1e-8f);
    float has = (st > 0.1f) ? 1.f : 0.f;
    float cont = wm[(size_t)bk * (DSLOT + 1) + d];
    wm_out[(size_t)bk * (DSLOT + 1) + d] = has * nc + (1.f - has) * cont;
    if (d == 0)
        wm_out[(size_t)bk * (DSLOT + 1) + DSLOT] = has * 1.f + (1.f - has) * nf[bk];
}

__global__ void enhance_kernel(const float* __restrict__ x, const float* __restrict__ fused,
                               const float* __restrict__ gate, float* __restrict__ out)
{
    size_t idx = (size_t)blockIdx.x * 256 + threadIdx.x;
    int t = (int)(idx >> 8);
    float g = gate[t];
    float4 xv = ((const float4*)x)[idx];
    float4 fv = ((const float4*)fused)[idx];
    float4 o;
    o.x = (1.f - g) * xv.x + g * fv.x;
    o.y = (1.f - g) * xv.y + g * fv.y;
    o.z = (1.f - g) * xv.z + g * fv.z;
    o.w = (1.f - g) * xv.w + g * fv.w;
    ((float4*)out)[idx] = o;
}

// ---------------- host ----------------
static void* symv(const void* s) { void* p = nullptr; cudaGetSymbolAddress(&p, s); return p; }

extern "C" void kernel_launch(void* const* d_in, const int* in_sizes, int n_in,
                              void* d_out, int out_size)
{
    const float* x      = (const float*)d_in[0];
    const float* wm     = (const float*)d_in[1];
    const float* rq_w   = (const float*)d_in[2];
    const float* rq_b   = (const float*)d_in[3];
    const float* fwm_w  = (const float*)d_in[4];
    const float* fwm_b  = (const float*)d_in[5];
    const float* rg1_w  = (const float*)d_in[6];
    const float* rg1_b  = (const float*)d_in[7];
    const float* rg2_w  = (const float*)d_in[8];
    const float* rg2_b  = (const float*)d_in[9];
    const float* fus_w  = (const float*)d_in[10];
    const float* fus_b  = (const float*)d_in[11];
    const float* twm_w  = (const float*)d_in[12];
    const float* twm_b  = (const float*)d_in[13];
    const float* wq_w   = (const float*)d_in[14];
    const float* wq_b   = (const float*)d_in[15];
    const float* imp1_w = (const float*)d_in[16];
    const float* imp1_b = (const float*)d_in[17];
    const float* imp2_w = (const float*)d_in[18];
    const float* imp2_b = (const float*)d_in[19];
    const float* wd1_w  = (const float*)d_in[20];
    const float* wd1_b  = (const float*)d_in[21];
    const float* wd2_w  = (const float*)d_in[22];
    const float* wd2_b  = (const float*)d_in[23];
    const float* wt     = (const float*)d_in[24];

    float* out = (float*)d_out;
    float* h1     = (float*)symv(g_h1);
    float* hg     = (float*)symv(g_hg);
    float* q3     = (float*)symv(g_q3);
    float* fused  = (float*)symv(g_fused);
    float* implog = (float*)symv(g_implogit);
    float* impsum = (float*)symv(g_impsum);
    float* wsc    = (float*)symv(g_wsc);
    float* nf     = (float*)symv(g_nf);
    float* rp     = (float*)symv(g_rp);
    int*   selidx = (int*)symv(g_sel);
    float* wwbuf  = (float*)symv(g_ww);
    float* bg     = (float*)symv(g_bg);
    float* b3     = (float*)symv(g_b3);
    float* pacc   = (float*)symv(g_pacc);
    float* pst    = (float*)symv(g_pst);
    __nv_bfloat16* xh   = (__nv_bfloat16*)symv(g_xh);
    __nv_bfloat16* xl   = (__nv_bfloat16*)symv(g_xl);
    __nv_bfloat16* ctxh = (__nv_bfloat16*)symv(g_ctxh);
    __nv_bfloat16* ctxl = (__nv_bfloat16*)symv(g_ctxl);
    __nv_bfloat16* conh = (__nv_bfloat16*)symv(g_conh);
    __nv_bfloat16* conl = (__nv_bfloat16*)symv(g_conl);
    __nv_bfloat16* wmh  = (__nv_bfloat16*)symv(g_wmh);
    __nv_bfloat16* wml  = (__nv_bfloat16*)symv(g_wml);
    __nv_bfloat16* wth  = (__nv_bfloat16*)symv(g_wth);
    __nv_bfloat16* wtl  = (__nv_bfloat16*)symv(g_wtl);

    cudaFuncSetAttribute(tc_gemm<0>, cudaFuncAttributeMaxDynamicSharedMemorySize, SMEMB);
    cudaFuncSetAttribute(tc_gemm<1>, cudaFuncAttributeMaxDynamicSharedMemorySize, SMEMB);
    cudaFuncSetAttribute(tc_gemm<2>, cudaFuncAttributeMaxDynamicSharedMemorySize, SMEMB);

    dim3 tb8(32, 8);

    split_x_kernel<<<NT*DMODEL/4/256, 256>>>((const float4*)x, xh, xl);
    wsplit_kernel<<<dim3(1024/32,  512/32), tb8>>>(rg1_w, 1024,  512, wth+OFF_RG1, wtl+OFF_RG1);
    wsplit_kernel<<<dim3(1024/32,  512/32), tb8>>>(imp1_w,1024,  512, wth+OFF_IMP, wtl+OFF_IMP);
    wsplit_kernel<<<dim3(1024/32,  128/32), tb8>>>(rq_w,  1024,  128, wth+OFF_RQ,  wtl+OFF_RQ);
    wsplit_kernel<<<dim3(1024/32,  128/32), tb8>>>(twm_w, 1024,  128, wth+OFF_TWM, wtl+OFF_TWM);
    wsplit_kernel<<<dim3(1024/32,  128/32), tb8>>>(wq_w,  1024,  128, wth+OFF_WQ,  wtl+OFF_WQ);
    wsplit_kernel<<<dim3( 128/32, 1024/32), tb8>>>(fwm_w,  128, 1024, wth+OFF_FWM, wtl+OFF_FWM);
    wsplit_kernel<<<dim3(2048/32, 1024/32), tb8>>>(fus_w, 2048, 1024, wth+OFF_FUS, wtl+OFF_FUS);
    wsplit_kernel<<<dim3(1152/32,  512/32), tb8>>>(wd1_w, 1152,  512, wth+OFF_WD1, wtl+OFF_WD1);
    biascat_kernel<<<6, 256>>>(rg1_b, imp1_b, rq_b, twm_b, wq_b, bg, b3);

    // merged gelu-hidden GEMM: [rg1 | imp1]
    tc_gemm<1><<<dim3(8,128), 256, SMEMB>>>(xh, xl, 1024, nullptr, nullptr,
        wth+OFF_G, wtl+OFF_G, 1024, bg, hg, nullptr, nullptr, 1024);
    rowdot_kernel<<<NT/8, 256>>>(hg,       1024, rg2_w,  rg2_b,  wt, 0, out + O_GATE);
    rowdot_kernel<<<NT/8, 256>>>(hg + 512, 1024, imp2_w, imp2_b, wt, 1, implog);
    impsum_kernel<<<BATCH, 1024>>>(implog, wt, impsum);

    // merged q3 GEMM: [query | xslot | wq]
    tc_gemm<0><<<dim3(3,128), 256, SMEMB>>>(xh, xl, 1024, nullptr, nullptr,
        wth+OFF_Q3, wtl+OFF_Q3, 1024, b3, q3, nullptr, nullptr, 384);

    read_attn_kernel<<<NT/8, 256>>>(q3, wm, out + O_ATTN, ctxh, ctxl);
    tc_gemm<2><<<dim3(8,128), 256, SMEMB>>>(ctxh, ctxl, 128, nullptr, nullptr,
        wth+OFF_FWM, wtl+OFF_FWM, 128, fwm_b, nullptr, conh, conl, 1024);
    tc_gemm<0><<<dim3(8,128), 256, SMEMB>>>(xh, xl, 1024, conh, conl,
        wth+OFF_FUS, wtl+OFF_FUS, 2048, fus_b, fused, nullptr, nullptr, 1024);
    enhance_kernel<<<(NT*DMODEL/4)/256, 256>>>(x, fused, out + O_GATE, out + O_XENH);

    pressure_kernel<<<BATCH*NSLOT, 256>>>(out + O_ATTN, rp);
    freshness_kernel<<<1, BATCH*NSLOT>>>(rp, wm, nf);

    write_attn_kernel<<<NT/8, 256>>>(q3 + 256, wm, wsc, wmh, wml);
    tc_gemm<1><<<dim3(4,128), 256, SMEMB>>>(xh, xl, 1024, wmh, wml,
        wth+OFF_WD1, wtl+OFF_WD1, 1152, wd1_b, h1, nullptr, nullptr, 512);
    rowdot_kernel<<<NT/8, 256>>>(h1, 512, wd2_w, wd2_b, wt, 2, out + O_WG);

    slotsel_kernel<<<NT/256, 256>>>(wsc, nf, implog, impsum, out + O_WG, wt,
                                    out + O_SEL, selidx, wwbuf);
    slotagg1_kernel<<<BATCH*NSLOT*NSEG, 128>>>(selidx, wwbuf, q3 + 128, pacc, pst);
    slotagg2_kernel<<<BATCH*NSLOT, DSLOT>>>(pacc, pst, wm, nf, out + O_WM);
}

// round 11
// speedup vs baseline: 3.0923x; 1.1772x over previous
#include <cuda_runtime.h>
#include <cuda_bf16.h>
#include <math.h>
#include <stdint.h>

#define BATCH   4
#define SEQ     4096
#define NT      (BATCH*SEQ)
#define DMODEL  1024
#define DSLOT   128
#define NSLOT   8
#define HID     512
#define SCALE   (0.08838834764831845f)
#define FRESH_THR 0.1f
#define READ_DECAY 0.3f

#define O_XENH  ((size_t)0)
#define O_WM    ((size_t)16777216)
#define O_GATE  ((size_t)16781344)
#define O_WG    ((size_t)16797728)
#define O_ATTN  ((size_t)16814112)
#define O_SEL   ((size_t)16945184)

// ---------------- scratch ----------------
__device__ float g_h1[NT*HID];          // wd1 hidden
__device__ float g_hg[NT*1024];         // rg1|imp1 merged hidden
__device__ float g_q3[NT*384];          // query|xslot|wq merged
__device__ float g_fused[NT*DMODEL];
__device__ float g_implogit[NT];
__device__ float g_impsum[BATCH];
__device__ float g_wsc[NT*NSLOT];
__device__ float g_nf[BATCH*NSLOT];
__device__ float g_rp[BATCH*NSLOT];
__device__ int   g_sel[NT];
__device__ float g_ww[NT];
__device__ float g_bg[1024];
__device__ float g_b3[384];
__device__ float g_pacc[256*128];
__device__ float g_pst[256];

__device__ __nv_bfloat16 g_xh[NT*DMODEL],  g_xl[NT*DMODEL];
__device__ __nv_bfloat16 g_ctxh[NT*DSLOT], g_ctxl[NT*DSLOT];
__device__ __nv_bfloat16 g_conh[NT*DMODEL],g_conl[NT*DMODEL];
__device__ __nv_bfloat16 g_wmh[NT*DSLOT],  g_wml[NT*DSLOT];

#define WT_TOTAL 4259840
__device__ __nv_bfloat16 g_wth[WT_TOTAL], g_wtl[WT_TOTAL];
#define OFF_G   0
#define OFF_RG1 (OFF_G)
#define OFF_IMP (OFF_G + 524288)
#define OFF_Q3  1048576
#define OFF_RQ  (OFF_Q3)
#define OFF_TWM (OFF_Q3 + 131072)
#define OFF_WQ  (OFF_Q3 + 262144)
#define OFF_FWM 1441792
#define OFF_FUS 1572864
#define OFF_WD1 3670016

__device__ __forceinline__ float gelu_exact(float v) {
    return 0.5f * v * (1.0f + erff(v * 0.70710678118654752f));
}

// ---------------- asm helpers ----------------
__device__ __forceinline__ uint32_t smem_u32(const void* p) {
    uint32_t a;
    asm("{ .reg .u64 t; cvta.to.shared.u64 t, %1; cvt.u32.u64 %0, t; }" : "=r"(a) : "l"(p));
    return a;
}
__device__ __forceinline__ void cpa16(uint32_t s, const void* g) {
    asm volatile("cp.async.cg.shared.global [%0], [%1], 16;\n" :: "r"(s), "l"(g));
}
__device__ __forceinline__ void cp_commit() { asm volatile("cp.async.commit_group;\n" ::); }

__device__ __forceinline__ void mma_bf16(float* c, uint32_t a0, uint32_t a1, uint32_t a2,
                                         uint32_t a3, uint32_t b0, uint32_t b1) {
    asm volatile(
        "mma.sync.aligned.m16n8k16.row.col.f32.bf16.bf16.f32 "
        "{%0,%1,%2,%3},{%4,%5,%6,%7},{%8,%9},{%0,%1,%2,%3};"
        : "+f"(c[0]), "+f"(c[1]), "+f"(c[2]), "+f"(c[3])
        : "r"(a0), "r"(a1), "r"(a2), "r"(a3), "r"(b0), "r"(b1));
}
#define LDSM4(r, addr) \
    asm volatile("ldmatrix.sync.aligned.m8n8.x4.shared.b16 {%0,%1,%2,%3}, [%4];" \
        : "=r"((r)[0]), "=r"((r)[1]), "=r"((r)[2]), "=r"((r)[3]) : "r"(addr))

// ---------------- mma.sync bf16x3 GEMM ----------------
// BM=BN=128, KC=32/chunk, 2-stage cp.async, 8 warps (2m x 4n), 64x32 warp tile.
// 2 CTAs/SM via launch_bounds(256,2); A-lo fragments reuse the A-hi registers.
#define SROW   80
#define TILEB  10240
#define STAGEB 40960
#define SMEMB  81920

template<int MODE>   // 0: f32 out, 1: f32 gelu, 2: bf16 hi/lo out
__global__ void __launch_bounds__(256, 2) tc_gemm(
    const __nv_bfloat16* __restrict__ A1h, const __nv_bfloat16* __restrict__ A1l, int K1,
    const __nv_bfloat16* __restrict__ A2h, const __nv_bfloat16* __restrict__ A2l,
    const __nv_bfloat16* __restrict__ Wh,  const __nv_bfloat16* __restrict__ Wl,  int Ktot,
    const float* __restrict__ bias,
    float* __restrict__ Cf, __nv_bfloat16* __restrict__ Chi, __nv_bfloat16* __restrict__ Clo,
    int N)
{
    extern __shared__ __align__(16) char smem[];
    const uint32_t sb = smem_u32(smem);
    const int tid = threadIdx.x, wid = tid >> 5, lane = tid & 31;
    const int g = lane >> 2, tg = lane & 3;
    const int m0 = blockIdx.y * 128, bn = blockIdx.x * 128;
    const int wm = (wid & 1) * 64, wn = (wid >> 1) * 32;

    float acc[4][4][4] = {};
    const int nchunk = Ktot / 32;

    auto load_chunk = [&](int ci, int buf) {
        int k0 = ci * 32;
        const __nv_bfloat16 *Ah, *Al; int sA, kA;
        if (k0 < K1) { Ah = A1h; Al = A1l; sA = K1; kA = k0; }
        else         { Ah = A2h; Al = A2l; sA = Ktot - K1; kA = k0 - K1; }
        uint32_t base = sb + buf * STAGEB;
        #pragma unroll
        for (int u = tid; u < 512; u += 256) {
            int r = u >> 2, c = (u & 3) * 8;
            uint32_t o = (uint32_t)(r * SROW + c * 2);
            size_t gi = (size_t)(m0 + r) * sA + kA + c;
            cpa16(base + o, Ah + gi);
            cpa16(base + TILEB + o, Al + gi);
        }
        #pragma unroll
        for (int u = tid; u < 512; u += 256) {
            int r = u >> 2, c = (u & 3) * 8;
            uint32_t o = (uint32_t)(r * SROW + c * 2);
            size_t gi = (size_t)(bn + r) * Ktot + k0 + c;
            cpa16(base + 2 * TILEB + o, Wh + gi);
            cpa16(base + 3 * TILEB + o, Wl + gi);
        }
        cp_commit();
    };

    // ldmatrix lane offsets
    const uint32_t aoff = (uint32_t)(((lane & 7) + ((lane >> 3) & 1) * 8) * SROW
                                     + ((lane >> 4) & 1) * 16);
    const uint32_t boff = (uint32_t)(((lane & 7) + ((lane >> 4) & 1) * 8) * SROW
                                     + ((lane >> 3) & 1) * 16);

    load_chunk(0, 0);

    for (int ci = 0; ci < nchunk; ++ci) {
        if (ci + 1 < nchunk) {
            load_chunk(ci + 1, (ci + 1) & 1);
            asm volatile("cp.async.wait_group 1;" ::: "memory");
        } else {
            asm volatile("cp.async.wait_group 0;" ::: "memory");
        }
        __syncthreads();

        uint32_t st = sb + (ci & 1) * STAGEB;
        uint32_t sAh = st, sAl = st + TILEB, sBh = st + 2 * TILEB, sBl = st + 3 * TILEB;

        #pragma unroll
        for (int ks = 0; ks < 2; ++ks) {
            uint32_t ka = (uint32_t)(ks * 32);
            uint32_t ah[4][4], bh[2][4], bl[2][4];
            uint32_t abase = (uint32_t)(wm * SROW) + aoff + ka;
            #pragma unroll
            for (int mi = 0; mi < 4; ++mi)
                LDSM4(ah[mi], sAh + abase + mi * 16 * SROW);
            uint32_t bbase = (uint32_t)(wn * SROW) + boff + ka;
            #pragma unroll
            for (int np = 0; np < 2; ++np) {
                LDSM4(bh[np], sBh + bbase + np * 16 * SROW);
                LDSM4(bl[np], sBl + bbase + np * 16 * SROW);
            }
            // products 1+2: Ah*Bh, Ah*Bl
            #pragma unroll
            for (int np = 0; np < 2; ++np)
                #pragma unroll
                for (int sub = 0; sub < 2; ++sub) {
                    int ni = np * 2 + sub;
                    uint32_t h0 = bh[np][sub * 2], h1 = bh[np][sub * 2 + 1];
                    uint32_t l0 = bl[np][sub * 2], l1 = bl[np][sub * 2 + 1];
                    #pragma unroll
                    for (int mi = 0; mi < 4; ++mi) {
                        mma_bf16(acc[mi][ni], ah[mi][0], ah[mi][1], ah[mi][2], ah[mi][3], h0, h1);
                        mma_bf16(acc[mi][ni], ah[mi][0], ah[mi][1], ah[mi][2], ah[mi][3], l0, l1);
                    }
                }
            // product 3: Al*Bh (reload A-lo into the same registers)
            #pragma unroll
            for (int mi = 0; mi < 4; ++mi)
                LDSM4(ah[mi], sAl + abase + mi * 16 * SROW);
            #pragma unroll
            for (int np = 0; np < 2; ++np)
                #pragma unroll
                for (int sub = 0; sub < 2; ++sub) {
                    int ni = np * 2 + sub;
                    uint32_t h0 = bh[np][sub * 2], h1 = bh[np][sub * 2 + 1];
                    #pragma unroll
                    for (int mi = 0; mi < 4; ++mi)
                        mma_bf16(acc[mi][ni], ah[mi][0], ah[mi][1], ah[mi][2], ah[mi][3], h0, h1);
                }
        }
        __syncthreads();
    }

    #pragma unroll
    for (int mi = 0; mi < 4; ++mi) {
        #pragma unroll
        for (int ni = 0; ni < 4; ++ni) {
            int row = m0 + wm + mi * 16 + g;
            int col = bn + wn + ni * 8 + tg * 2;
            float b0 = bias[col], b1 = bias[col + 1];
            #pragma unroll
            for (int h = 0; h < 2; ++h) {
                int r = row + h * 8;
                float v0 = acc[mi][ni][h * 2]     + b0;
                float v1 = acc[mi][ni][h * 2 + 1] + b1;
                if (MODE == 1) { v0 = gelu_exact(v0); v1 = gelu_exact(v1); }
                if (MODE == 2) {
                    __nv_bfloat16 h0 = __float2bfloat16(v0);
                    __nv_bfloat16 h1 = __float2bfloat16(v1);
                    __nv_bfloat162 hp; hp.x = h0; hp.y = h1;
                    __nv_bfloat162 lp;
                    lp.x = __float2bfloat16(v0 - __bfloat162float(h0));
                    lp.y = __float2bfloat16(v1 - __bfloat162float(h1));
                    *(__nv_bfloat162*)&Chi[(size_t)r * N + col] = hp;
                    *(__nv_bfloat162*)&Clo[(size_t)r * N + col] = lp;
                } else {
                    float2 o; o.x = v0; o.y = v1;
                    *(float2*)&Cf[(size_t)r * N + col] = o;
                }
            }
        }
    }
}

// ---------------- split x ----------------
__global__ void split_x_kernel(const float4* __restrict__ x,
                               __nv_bfloat16* __restrict__ h, __nv_bfloat16* __restrict__ l)
{
    size_t i = (size_t)blockIdx.x * 256 + threadIdx.x;
    float4 v = x[i];
    float a[4] = {v.x, v.y, v.z, v.w};
    __nv_bfloat16 hh[4];
    #pragma unroll
    for (int c = 0; c < 4; ++c) hh[c] = __float2bfloat16(a[c]);
    __nv_bfloat162 hp0, hp1, lp0, lp1;
    hp0.x = hh[0]; hp0.y = hh[1]; hp1.x = hh[2]; hp1.y = hh[3];
    lp0.x = __float2bfloat16(a[0] - __bfloat162float(hh[0]));
    lp0.y = __float2bfloat16(a[1] - __bfloat162float(hh[1]));
    lp1.x = __float2bfloat16(a[2] - __bfloat162float(hh[2]));
    lp1.y = __float2bfloat16(a[3] - __bfloat162float(hh[3]));
    *(__nv_bfloat162*)&h[i * 4]     = hp0;
    *(__nv_bfloat162*)&h[i * 4 + 2] = hp1;
    *(__nv_bfloat162*)&l[i * 4]     = lp0;
    *(__nv_bfloat162*)&l[i * 4 + 2] = lp1;
}

// ---------------- weight transpose + split ----------------
__global__ void wsplit_kernel(const float* __restrict__ W, int K, int N,
                              __nv_bfloat16* __restrict__ Th, __nv_bfloat16* __restrict__ Tl)
{
    __shared__ float tile[32][33];
    int kb = blockIdx.x * 32, nb = blockIdx.y * 32;
    int tx = threadIdx.x, ty = threadIdx.y;
    #pragma unroll
    for (int i = 0; i < 4; ++i)
        tile[ty + i * 8][tx] = W[(size_t)(kb + ty + i * 8) * N + nb + tx];
    __syncthreads();
    #pragma unroll
    for (int i = 0; i < 4; ++i) {
        int n = nb + ty + i * 8, k = kb + tx;
        float v = tile[tx][ty + i * 8];
        size_t o = (size_t)n * K + k;
        __nv_bfloat16 h = __float2bfloat16(v);
        Th[o] = h;
        Tl[o] = __float2bfloat16(v - __bfloat162float(h));
    }
}

// ---------------- bias concat ----------------
__global__ void biascat_kernel(const float* rg1_b, const float* imp1_b,
                               const float* rq_b, const float* twm_b, const float* wq_b,
                               float* bg, float* b3)
{
    int i = blockIdx.x * 256 + threadIdx.x;
    if (i < 512) bg[i] = rg1_b[i];
    else if (i < 1024) bg[i] = imp1_b[i - 512];
    else if (i < 1152) b3[i - 1024] = rq_b[i - 1024];
    else if (i < 1280) b3[i - 1024] = twm_b[i - 1152];
    else if (i < 1408) b3[i - 1024] = wq_b[i - 1280];
}

// ---------------- row-dot (strided hidden) ----------------
__global__ void rowdot_kernel(const float* __restrict__ Hm, int stride,
                              const float* __restrict__ w, const float* __restrict__ bias,
                              const float* __restrict__ wt, int mode,
                              float* __restrict__ out)
{
    __shared__ float ws[HID];
    for (int i = threadIdx.x; i < HID; i += blockDim.x) ws[i] = w[i];
    __syncthreads();
    int warp = threadIdx.x >> 5, lane = threadIdx.x & 31;
    int row = blockIdx.x * 8 + warp;
    const float* h = Hm + (size_t)row * stride;
    float s = 0.f;
    for (int i = lane; i < HID; i += 32) s = fmaf(h[i], ws[i], s);
    #pragma unroll
    for (int o = 16; o; o >>= 1) s += __shfl_xor_sync(0xffffffffu, s, o);
    if (lane == 0) {
        float z = s + bias[0];
        if (mode == 1) out[row] = z;
        else {
            if (mode == 2) z /= fmaxf(wt[0], 0.1f);
            out[row] = 1.f / (1.f + expf(-z));
        }
    }
}

// ---------------- read attention (query stride 384) ----------------
__global__ void read_attn_kernel(const float* __restrict__ query,
                                 const float* __restrict__ wm,
                                 float* __restrict__ attn_out,
                                 __nv_bfloat16* __restrict__ ctxh,
                                 __nv_bfloat16* __restrict__ ctxl)
{
    __shared__ float cont[NSLOT][DSLOT];
    __shared__ float fresh[NSLOT];
    int tid = threadIdx.x;
    int tokenBase = blockIdx.x * 8;
    int b = tokenBase / SEQ;
    for (int i = tid; i < NSLOT * DSLOT; i += 256) {
        int k = i / DSLOT, d = i % DSLOT;
        cont[k][d] = wm[((size_t)b * NSLOT + k) * (DSLOT + 1) + d];
    }
    if (tid < NSLOT) fresh[tid] = wm[((size_t)b * NSLOT + tid) * (DSLOT + 1) + DSLOT];
    __syncthreads();
    int warp = tid >> 5, lane = tid & 31;
    int t = tokenBase + warp;
    const float* q = query + (size_t)t * 384;
    float ql[4];
    #pragma unroll
    for (int i = 0; i < 4; ++i) ql[i] = q[lane + 32 * i];
    float a[NSLOT];
    #pragma unroll
    for (int k = 0; k < NSLOT; ++k) {
        float s = 0.f;
        #pragma unroll
        for (int i = 0; i < 4; ++i) s = fmaf(ql[i], cont[k][lane + 32 * i], s);
        #pragma unroll
        for (int o = 16; o; o >>= 1) s += __shfl_xor_sync(0xffffffffu, s, o);
        s *= SCALE;
        if (fresh[k] < FRESH_THR) s = -1e9f;
        a[k] = s;
    }
    float mx = a[0];
    #pragma unroll
    for (int k = 1; k < NSLOT; ++k) mx = fmaxf(mx, a[k]);
    float sum = 0.f;
    #pragma unroll
    for (int k = 0; k < NSLOT; ++k) { a[k] = expf(a[k] - mx); sum += a[k]; }
    float inv = 1.f / sum;
    #pragma unroll
    for (int k = 0; k < NSLOT; ++k) a[k] *= inv;
    if (lane == 0) {
        #pragma unroll
        for (int k = 0; k < NSLOT; ++k) attn_out[(size_t)t * NSLOT + k] = a[k];
    }
    #pragma unroll
    for (int i = 0; i < 4; ++i) {
        int d = lane + 32 * i;
        float c = 0.f;
        #pragma unroll
        for (int k = 0; k < NSLOT; ++k) c = fmaf(a[k], cont[k][d], c);
        __nv_bfloat16 h = __float2bfloat16(c);
        ctxh[(size_t)t * DSLOT + d] = h;
        ctxl[(size_t)t * DSLOT + d] = __float2bfloat16(c - __bfloat162float(h));
    }
}

// ---------------- write attention (wq stride 384) ----------------
__global__ void write_attn_kernel(const float* __restrict__ wq,
                                  const float* __restrict__ wm,
                                  float* __restrict__ wsc_out,
                                  __nv_bfloat16* __restrict__ wmh,
                                  __nv_bfloat16* __restrict__ wml)
{
    __shared__ float cont[NSLOT][DSLOT];
    int tid = threadIdx.x;
    int tokenBase = blockIdx.x * 8;
    int b = tokenBase / SEQ;
    for (int i = tid; i < NSLOT * DSLOT; i += 256) {
        int k = i / DSLOT, d = i % DSLOT;
        cont[k][d] = wm[((size_t)b * NSLOT + k) * (DSLOT + 1) + d];
    }
    __syncthreads();
    int warp = tid >> 5, lane = tid & 31;
    int t = tokenBase + warp;
    const float* q = wq + (size_t)t * 384;
    float ql[4];
    #pragma unroll
    for (int i = 0; i < 4; ++i) ql[i] = q[lane + 32 * i];
    float a[NSLOT];
    #pragma unroll
    for (int k = 0; k < NSLOT; ++k) {
        float s = 0.f;
        #pragma unroll
        for (int i = 0; i < 4; ++i) s = fmaf(ql[i], cont[k][lane + 32 * i], s);
        #pragma unroll
        for (int o = 16; o; o >>= 1) s += __shfl_xor_sync(0xffffffffu, s, o);
        a[k] = s * SCALE;
    }
    if (lane == 0) {
        #pragma unroll
        for (int k = 0; k < NSLOT; ++k) wsc_out[(size_t)t * NSLOT + k] = a[k];
    }
    float mx = a[0];
    #pragma unroll
    for (int k = 1; k < NSLOT; ++k) mx = fmaxf(mx, a[k]);
    float sum = 0.f;
    #pragma unroll
    for (int k = 0; k < NSLOT; ++k) { a[k] = expf(a[k] - mx); sum += a[k]; }
    float inv = 1.f / sum;
    #pragma unroll
    for (int k = 0; k < NSLOT; ++k) a[k] *= inv;
    #pragma unroll
    for (int i = 0; i < 4; ++i) {
        int d = lane + 32 * i;
        float c = 0.f;
        #pragma unroll
        for (int k = 0; k < NSLOT; ++k) c = fmaf(a[k], cont[k][d], c);
        __nv_bfloat16 h = __float2bfloat16(c);
        wmh[(size_t)t * DSLOT + d] = h;
        wml[(size_t)t * DSLOT + d] = __float2bfloat16(c - __bfloat162float(h));
    }
}

// ---------------- small reductions ----------------
__global__ void pressure_kernel(const float* __restrict__ attn, float* __restrict__ rp)
{
    int b = blockIdx.x / NSLOT, k = blockIdx.x % NSLOT;
    __shared__ float sh[256];
    float s = 0.f;
    for (int si = threadIdx.x; si < SEQ; si += 256)
        s += attn[((size_t)b * SEQ + si) * NSLOT + k];
    sh[threadIdx.x] = s;
    __syncthreads();
    for (int o = 128; o; o >>= 1) {
        if (threadIdx.x < o) sh[threadIdx.x] += sh[threadIdx.x + o];
        __syncthreads();
    }
    if (threadIdx.x == 0) rp[blockIdx.x] = sh[0];
}

__global__ void freshness_kernel(const float* __restrict__ rp, const float* __restrict__ wm,
                                 float* __restrict__ nf)
{
    int t = threadIdx.x;
    int b = t / NSLOT;
    __shared__ float s[BATCH * NSLOT];
    s[t] = rp[t];
    __syncthreads();
    float mx = 1e-8f;
    #pragma unroll
    for (int k = 0; k < NSLOT; ++k) mx = fmaxf(mx, s[b * NSLOT + k]);
    float decay = 1.f - (s[t] / mx) * (1.f - READ_DECAY);
    nf[t] = wm[(size_t)t * (DSLOT + 1) + DSLOT] * decay;
}

__global__ void impsum_kernel(const float* __restrict__ logit, const float* __restrict__ wt,
                              float* __restrict__ outsum)
{
    int b = blockIdx.x;
    float temp = fmaxf(wt[0], 0.1f);
    __shared__ float sh[1024];
    float s = 0.f;
    for (int i = threadIdx.x; i < SEQ; i += 1024)
        s += expf(logit[(size_t)b * SEQ + i] / temp);
    sh[threadIdx.x] = s;
    __syncthreads();
    for (int o = 512; o; o >>= 1) {
        if (threadIdx.x < o) sh[threadIdx.x] += sh[threadIdx.x + o];
        __syncthreads();
    }
    if (threadIdx.x == 0) outsum[b] = sh[0];
}

__global__ void slotsel_kernel(const float* __restrict__ wsc, const float* __restrict__ nf,
                               const float* __restrict__ logit, const float* __restrict__ impsum,
                               const float* __restrict__ wg, const float* __restrict__ wt,
                               float* __restrict__ sel_onehot, int* __restrict__ sel_idx,
                               float* __restrict__ ww_out)
{
    int t = blockIdx.x * 256 + threadIdx.x;
    int b = t / SEQ;
    float temp = fmaxf(wt[0], 0.1f);
    float best = wsc[(size_t)t * NSLOT] - 2.f * nf[b * NSLOT];
    int bi = 0;
    #pragma unroll
    for (int k = 1; k < NSLOT; ++k) {
        float v = wsc[(size_t)t * NSLOT + k] - 2.f * nf[b * NSLOT + k];
        if (v > best) { best = v; bi = k; }
    }
    float imp = expf(logit[t] / temp) / (impsum[b] + 1e-8f) * (float)SEQ;
    sel_idx[t] = bi;
    ww_out[t] = wg[t] * imp;
    #pragma unroll
    for (int k = 0; k < NSLOT; ++k)
        sel_onehot[(size_t)t * NSLOT + k] = (k == bi) ? 1.f : 0.f;
}

// ---------------- slot aggregation: 2-phase ----------------
#define NSEG 8
#define SEGLEN (SEQ/NSEG)
__global__ void slotagg1_kernel(const int* __restrict__ sel, const float* __restrict__ ww,
                                const float* __restrict__ xslot,
                                float* __restrict__ pacc, float* __restrict__ pst)
{
    int blk = blockIdx.x;          // bk*NSEG + seg
    int bk = blk / NSEG, seg = blk % NSEG;
    int b = bk / NSLOT, k = bk % NSLOT;
    int d = threadIdx.x;
    float acc = 0.f, st = 0.f;
    const int s0 = b * SEQ + seg * SEGLEN;
    for (int si = 0; si < SEGLEN; ++si) {
        int tt = s0 + si;
        if (sel[tt] == k) {
            float w = ww[tt];
            st += w;
            acc = fmaf(w, xslot[(size_t)tt * 384 + d], acc);
        }
    }
    pacc[(size_t)blk * 128 + d] = acc;
    if (d == 0) pst[blk] = st;
}

__global__ void slotagg2_kernel(const float* __restrict__ pacc, const float* __restrict__ pst,
                                const float* __restrict__ wm, const float* __restrict__ nf,
                                float* __restrict__ wm_out)
{
    int bk = blockIdx.x;
    int d = threadIdx.x;
    float acc = 0.f, st = 0.f;
    #pragma unroll
    for (int s = 0; s < NSEG; ++s) {
        acc += pacc[(size_t)(bk * NSEG + s) * 128 + d];
        st  += pst[bk * NSEG + s];
    }
    float nc = acc / fmaxf(st, 1e-8f);
    float has = (st > 0.1f) ? 1.f : 0.f;
    float cont = wm[(size_t)bk * (DSLOT + 1) + d];
    wm_out[(size_t)bk * (DSLOT + 1) + d] = has * nc + (1.f - has) * cont;
    if (d == 0)
        wm_out[(size_t)bk * (DSLOT + 1) + DSLOT] = has * 1.f + (1.f - has) * nf[bk];
}

__global__ void enhance_kernel(const float* __restrict__ x, const float* __restrict__ fused,
                               const float* __restrict__ gate, float* __restrict__ out)
{
    size_t idx = (size_t)blockIdx.x * 256 + threadIdx.x;
    int t = (int)(idx >> 8);
    float g = gate[t];
    float4 xv = ((const float4*)x)[idx];
    float4 fv = ((const float4*)fused)[idx];
    float4 o;
    o.x = (1.f - g) * xv.x + g * fv.x;
    o.y = (1.f - g) * xv.y + g * fv.y;
    o.z = (1.f - g) * xv.z + g * fv.z;
    o.w = (1.f - g) * xv.w + g * fv.w;
    ((float4*)out)[idx] = o;
}

// ---------------- host ----------------
static void* symv(const void* s) { void* p = nullptr; cudaGetSymbolAddress(&p, s); return p; }

extern "C" void kernel_launch(void* const* d_in, const int* in_sizes, int n_in,
                              void* d_out, int out_size)
{
    const float* x      = (const float*)d_in[0];
    const float* wm     = (const float*)d_in[1];
    const float* rq_w   = (const float*)d_in[2];
    const float* rq_b   = (const float*)d_in[3];
    const float* fwm_w  = (const float*)d_in[4];
    const float* fwm_b  = (const float*)d_in[5];
    const float* rg1_w  = (const float*)d_in[6];
    const float* rg1_b  = (const float*)d_in[7];
    const float* rg2_w  = (const float*)d_in[8];
    const float* rg2_b  = (const float*)d_in[9];
    const float* fus_w  = (const float*)d_in[10];
    const float* fus_b  = (const float*)d_in[11];
    const float* twm_w  = (const float*)d_in[12];
    const float* twm_b  = (const float*)d_in[13];
    const float* wq_w   = (const float*)d_in[14];
    const float* wq_b   = (const float*)d_in[15];
    const float* imp1_w = (const float*)d_in[16];
    const float* imp1_b = (const float*)d_in[17];
    const float* imp2_w = (const float*)d_in[18];
    const float* imp2_b = (const float*)d_in[19];
    const float* wd1_w  = (const float*)d_in[20];
    const float* wd1_b  = (const float*)d_in[21];
    const float* wd2_w  = (const float*)d_in[22];
    const float* wd2_b  = (const float*)d_in[23];
    const float* wt     = (const float*)d_in[24];

    float* out = (float*)d_out;
    float* h1     = (float*)symv(g_h1);
    float* hg     = (float*)symv(g_hg);
    float* q3     = (float*)symv(g_q3);
    float* fused  = (float*)symv(g_fused);
    float* implog = (float*)symv(g_implogit);
    float* impsum = (float*)symv(g_impsum);
    float* wsc    = (float*)symv(g_wsc);
    float* nf     = (float*)symv(g_nf);
    float* rp     = (float*)symv(g_rp);
    int*   selidx = (int*)symv(g_sel);
    float* wwbuf  = (float*)symv(g_ww);
    float* bg     = (float*)symv(g_bg);
    float* b3     = (float*)symv(g_b3);
    float* pacc   = (float*)symv(g_pacc);
    float* pst    = (float*)symv(g_pst);
    __nv_bfloat16* xh   = (__nv_bfloat16*)symv(g_xh);
    __nv_bfloat16* xl   = (__nv_bfloat16*)symv(g_xl);
    __nv_bfloat16* ctxh = (__nv_bfloat16*)symv(g_ctxh);
    __nv_bfloat16* ctxl = (__nv_bfloat16*)symv(g_ctxl);
    __nv_bfloat16* conh = (__nv_bfloat16*)symv(g_conh);
    __nv_bfloat16* conl = (__nv_bfloat16*)symv(g_conl);
    __nv_bfloat16* wmh  = (__nv_bfloat16*)symv(g_wmh);
    __nv_bfloat16* wml  = (__nv_bfloat16*)symv(g_wml);
    __nv_bfloat16* wth  = (__nv_bfloat16*)symv(g_wth);
    __nv_bfloat16* wtl  = (__nv_bfloat16*)symv(g_wtl);

    cudaFuncSetAttribute(tc_gemm<0>, cudaFuncAttributeMaxDynamicSharedMemorySize, SMEMB);
    cudaFuncSetAttribute(tc_gemm<1>, cudaFuncAttributeMaxDynamicSharedMemorySize, SMEMB);
    cudaFuncSetAttribute(tc_gemm<2>, cudaFuncAttributeMaxDynamicSharedMemorySize, SMEMB);

    dim3 tb8(32, 8);

    split_x_kernel<<<NT*DMODEL/4/256, 256>>>((const float4*)x, xh, xl);
    wsplit_kernel<<<dim3(1024/32,  512/32), tb8>>>(rg1_w, 1024,  512, wth+OFF_RG1, wtl+OFF_RG1);
    wsplit_kernel<<<dim3(1024/32,  512/32), tb8>>>(imp1_w,1024,  512, wth+OFF_IMP, wtl+OFF_IMP);
    wsplit_kernel<<<dim3(1024/32,  128/32), tb8>>>(rq_w,  1024,  128, wth+OFF_RQ,  wtl+OFF_RQ);
    wsplit_kernel<<<dim3(1024/32,  128/32), tb8>>>(twm_w, 1024,  128, wth+OFF_TWM, wtl+OFF_TWM);
    wsplit_kernel<<<dim3(1024/32,  128/32), tb8>>>(wq_w,  1024,  128, wth+OFF_WQ,  wtl+OFF_WQ);
    wsplit_kernel<<<dim3( 128/32, 1024/32), tb8>>>(fwm_w,  128, 1024, wth+OFF_FWM, wtl+OFF_FWM);
    wsplit_kernel<<<dim3(2048/32, 1024/32), tb8>>>(fus_w, 2048, 1024, wth+OFF_FUS, wtl+OFF_FUS);
    wsplit_kernel<<<dim3(1152/32,  512/32), tb8>>>(wd1_w, 1152,  512, wth+OFF_WD1, wtl+OFF_WD1);
    biascat_kernel<<<6, 256>>>(rg1_b, imp1_b, rq_b, twm_b, wq_b, bg, b3);

    // merged gelu-hidden GEMM: [rg1 | imp1]
    tc_gemm<1><<<dim3(8,128), 256, SMEMB>>>(xh, xl, 1024, nullptr, nullptr,
        wth+OFF_G, wtl+OFF_G, 1024, bg, hg, nullptr, nullptr, 1024);
    rowdot_kernel<<<NT/8, 256>>>(hg,       1024, rg2_w,  rg2_b,  wt, 0, out + O_GATE);
    rowdot_kernel<<<NT/8, 256>>>(hg + 512, 1024, imp2_w, imp2_b, wt, 1, implog);
    impsum_kernel<<<BATCH, 1024>>>(implog, wt, impsum);

    // merged q3 GEMM: [query | xslot | wq]
    tc_gemm<0><<<dim3(3,128), 256, SMEMB>>>(xh, xl, 1024, nullptr, nullptr,
        wth+OFF_Q3, wtl+OFF_Q3, 1024, b3, q3, nullptr, nullptr, 384);

    read_attn_kernel<<<NT/8, 256>>>(q3, wm, out + O_ATTN, ctxh, ctxl);
    tc_gemm<2><<<dim3(8,128), 256, SMEMB>>>(ctxh, ctxl, 128, nullptr, nullptr,
        wth+OFF_FWM, wtl+OFF_FWM, 128, fwm_b, nullptr, conh, conl, 1024);
    tc_gemm<0><<<dim3(8,128), 256, SMEMB>>>(xh, xl, 1024, conh, conl,
        wth+OFF_FUS, wtl+OFF_FUS, 2048, fus_b, fused, nullptr, nullptr, 1024);
    enhance_kernel<<<(NT*DMODEL/4)/256, 256>>>(x, fused, out + O_GATE, out + O_XENH);

    pressure_kernel<<<BATCH*NSLOT, 256>>>(out + O_ATTN, rp);
    freshness_kernel<<<1, BATCH*NSLOT>>>(rp, wm, nf);

    write_attn_kernel<<<NT/8, 256>>>(q3 + 256, wm, wsc, wmh, wml);
    tc_gemm<1><<<dim3(4,128), 256, SMEMB>>>(xh, xl, 1024, wmh, wml,
        wth+OFF_WD1, wtl+OFF_WD1, 1152, wd1_b, h1, nullptr, nullptr, 512);
    rowdot_kernel<<<NT/8, 256>>>(h1, 512, wd2_w, wd2_b, wt, 2, out + O_WG);

    slotsel_kernel<<<NT/256, 256>>>(wsc, nf, implog, impsum, out + O_WG, wt,
                                    out + O_SEL, selidx, wwbuf);
    slotagg1_kernel<<<BATCH*NSLOT*NSEG, 128>>>(selidx, wwbuf, q3 + 128, pacc, pst);
    slotagg2_kernel<<<BATCH*NSLOT, DSLOT>>>(pacc, pst, wm, nf, out + O_WM);
}

// round 12
// speedup vs baseline: 4.0300x; 1.3032x over previous
#include <cuda_runtime.h>
#include <cuda_bf16.h>
#include <cuda_fp16.h>
#include <math.h>
#include <stdint.h>

#define BATCH   4
#define SEQ     4096
#define NT      (BATCH*SEQ)
#define DMODEL  1024
#define DSLOT   128
#define NSLOT   8
#define HID     512
#define SCALE   (0.08838834764831845f)
#define FRESH_THR 0.1f
#define READ_DECAY 0.3f

#define O_XENH  ((size_t)0)
#define O_WM    ((size_t)16777216)
#define O_GATE  ((size_t)16781344)
#define O_WG    ((size_t)16797728)
#define O_ATTN  ((size_t)16814112)
#define O_SEL   ((size_t)16945184)

// ---------------- scratch ----------------
__device__ float g_h1[NT*HID];
__device__ float g_hg[NT*1024];
__device__ float g_q3[NT*384];
__device__ float g_fused[NT*DMODEL];
__device__ float g_implogit[NT];
__device__ float g_impsum[BATCH];
__device__ float g_wsc[NT*NSLOT];
__device__ float g_nf[BATCH*NSLOT];
__device__ float g_rp[BATCH*NSLOT];
__device__ int   g_sel[NT];
__device__ float g_ww[NT];
__device__ float g_bg[1024];
__device__ float g_b3[384];
__device__ float g_pacc[256*128];
__device__ float g_pst[256];

// bf16 hi/lo activations (q3 path only)
__device__ __nv_bfloat16 g_xh[NT*DMODEL], g_xl[NT*DMODEL];
// fp16 activations (fast path)
__device__ __half g_xf[NT*DMODEL];
__device__ __half g_ctxf[NT*DSLOT];
__device__ __half g_conf[NT*DMODEL];
__device__ __half g_wmf[NT*DSLOT];

// bf16 hi/lo weights: q3 only [rq|twm|wq], each [128][1024]
#define WB_TOTAL 393216
__device__ __nv_bfloat16 g_wbh[WB_TOTAL], g_wbl[WB_TOTAL];
#define B_RQ  0
#define B_TWM 131072
#define B_WQ  262144

// fp16 hi/lo weights: G [1024][1024], FWM [1024][128], FUS [1024][2048], WD1 [512][1152]
#define WF_TOTAL 3866624
__device__ __half g_wfh[WF_TOTAL], g_wfl[WF_TOTAL];
#define F_G   0
#define F_RG1 (F_G)
#define F_IMP (F_G + 524288)
#define F_FWM 1048576
#define F_FUS 1179648
#define F_WD1 3276800

__device__ __forceinline__ float gelu_exact(float v) {
    return 0.5f * v * (1.0f + erff(v * 0.70710678118654752f));
}

// ---------------- asm helpers ----------------
__device__ __forceinline__ uint32_t smem_u32(const void* p) {
    uint32_t a;
    asm("{ .reg .u64 t; cvta.to.shared.u64 t, %1; cvt.u32.u64 %0, t; }" : "=r"(a) : "l"(p));
    return a;
}
__device__ __forceinline__ void cpa16(uint32_t s, const void* g) {
    asm volatile("cp.async.cg.shared.global [%0], [%1], 16;\n" :: "r"(s), "l"(g));
}
__device__ __forceinline__ void cp_commit() { asm volatile("cp.async.commit_group;\n" ::); }

__device__ __forceinline__ void mma_bf16(float* c, uint32_t a0, uint32_t a1, uint32_t a2,
                                         uint32_t a3, uint32_t b0, uint32_t b1) {
    asm volatile(
        "mma.sync.aligned.m16n8k16.row.col.f32.bf16.bf16.f32 "
        "{%0,%1,%2,%3},{%4,%5,%6,%7},{%8,%9},{%0,%1,%2,%3};"
        : "+f"(c[0]), "+f"(c[1]), "+f"(c[2]), "+f"(c[3])
        : "r"(a0), "r"(a1), "r"(a2), "r"(a3), "r"(b0), "r"(b1));
}
__device__ __forceinline__ void mma_f16(float* c, uint32_t a0, uint32_t a1, uint32_t a2,
                                        uint32_t a3, uint32_t b0, uint32_t b1) {
    asm volatile(
        "mma.sync.aligned.m16n8k16.row.col.f32.f16.f16.f32 "
        "{%0,%1,%2,%3},{%4,%5,%6,%7},{%8,%9},{%0,%1,%2,%3};"
        : "+f"(c[0]), "+f"(c[1]), "+f"(c[2]), "+f"(c[3])
        : "r"(a0), "r"(a1), "r"(a2), "r"(a3), "r"(b0), "r"(b1));
}
#define LDSM4(r, addr) \
    asm volatile("ldmatrix.sync.aligned.m8n8.x4.shared.b16 {%0,%1,%2,%3}, [%4];" \
        : "=r"((r)[0]), "=r"((r)[1]), "=r"((r)[2]), "=r"((r)[3]) : "r"(addr))

#define SROW   80
#define TILEB  10240

// ---------------- bf16x3 GEMM (q3 path): 2-stage, 2 CTA/SM ----------------
#define STAGEB3 40960
#define SMEMB3  81920

__global__ void __launch_bounds__(256, 2) tc3_gemm(
    const __nv_bfloat16* __restrict__ Ah, const __nv_bfloat16* __restrict__ Al,
    const __nv_bfloat16* __restrict__ Wh, const __nv_bfloat16* __restrict__ Wl, int Ktot,
    const float* __restrict__ bias, float* __restrict__ Cf, int N)
{
    extern __shared__ __align__(16) char smem[];
    const uint32_t sb = smem_u32(smem);
    const int tid = threadIdx.x, wid = tid >> 5, lane = tid & 31;
    const int g = lane >> 2, tg = lane & 3;
    const int m0 = blockIdx.y * 128, bn = blockIdx.x * 128;
    const int wm = (wid & 1) * 64, wn = (wid >> 1) * 32;

    float acc[4][4][4] = {};
    const int nchunk = Ktot / 32;

    auto load_chunk = [&](int ci, int buf) {
        int k0 = ci * 32;
        uint32_t base = sb + buf * STAGEB3;
        #pragma unroll
        for (int u = tid; u < 512; u += 256) {
            int r = u >> 2, c = (u & 3) * 8;
            uint32_t o = (uint32_t)(r * SROW + c * 2);
            size_t gi = (size_t)(m0 + r) * Ktot + k0 + c;
            cpa16(base + o, Ah + gi);
            cpa16(base + TILEB + o, Al + gi);
        }
        #pragma unroll
        for (int u = tid; u < 512; u += 256) {
            int r = u >> 2, c = (u & 3) * 8;
            uint32_t o = (uint32_t)(r * SROW + c * 2);
            size_t gi = (size_t)(bn + r) * Ktot + k0 + c;
            cpa16(base + 2 * TILEB + o, Wh + gi);
            cpa16(base + 3 * TILEB + o, Wl + gi);
        }
        cp_commit();
    };

    const uint32_t aoff = (uint32_t)(((lane & 7) + ((lane >> 3) & 1) * 8) * SROW
                                     + ((lane >> 4) & 1) * 16);
    const uint32_t boff = (uint32_t)(((lane & 7) + ((lane >> 4) & 1) * 8) * SROW
                                     + ((lane >> 3) & 1) * 16);

    load_chunk(0, 0);

    for (int ci = 0; ci < nchunk; ++ci) {
        if (ci + 1 < nchunk) {
            load_chunk(ci + 1, (ci + 1) & 1);
            asm volatile("cp.async.wait_group 1;" ::: "memory");
        } else {
            asm volatile("cp.async.wait_group 0;" ::: "memory");
        }
        __syncthreads();

        uint32_t st = sb + (ci & 1) * STAGEB3;
        uint32_t sAh = st, sAl = st + TILEB, sBh = st + 2 * TILEB, sBl = st + 3 * TILEB;

        #pragma unroll
        for (int ks = 0; ks < 2; ++ks) {
            uint32_t ka = (uint32_t)(ks * 32);
            uint32_t ah[4][4], bh[2][4], bl[2][4];
            uint32_t abase = (uint32_t)(wm * SROW) + aoff + ka;
            #pragma unroll
            for (int mi = 0; mi < 4; ++mi)
                LDSM4(ah[mi], sAh + abase + mi * 16 * SROW);
            uint32_t bbase = (uint32_t)(wn * SROW) + boff + ka;
            #pragma unroll
            for (int np = 0; np < 2; ++np) {
                LDSM4(bh[np], sBh + bbase + np * 16 * SROW);
                LDSM4(bl[np], sBl + bbase + np * 16 * SROW);
            }
            #pragma unroll
            for (int np = 0; np < 2; ++np)
                #pragma unroll
                for (int sub = 0; sub < 2; ++sub) {
                    int ni = np * 2 + sub;
                    uint32_t h0 = bh[np][sub * 2], h1 = bh[np][sub * 2 + 1];
                    uint32_t l0 = bl[np][sub * 2], l1 = bl[np][sub * 2 + 1];
                    #pragma unroll
                    for (int mi = 0; mi < 4; ++mi) {
                        mma_bf16(acc[mi][ni], ah[mi][0], ah[mi][1], ah[mi][2], ah[mi][3], h0, h1);
                        mma_bf16(acc[mi][ni], ah[mi][0], ah[mi][1], ah[mi][2], ah[mi][3], l0, l1);
                    }
                }
            #pragma unroll
            for (int mi = 0; mi < 4; ++mi)
                LDSM4(ah[mi], sAl + abase + mi * 16 * SROW);
            #pragma unroll
            for (int np = 0; np < 2; ++np)
                #pragma unroll
                for (int sub = 0; sub < 2; ++sub) {
                    int ni = np * 2 + sub;
                    uint32_t h0 = bh[np][sub * 2], h1 = bh[np][sub * 2 + 1];
                    #pragma unroll
                    for (int mi = 0; mi < 4; ++mi)
                        mma_bf16(acc[mi][ni], ah[mi][0], ah[mi][1], ah[mi][2], ah[mi][3], h0, h1);
                }
        }
        __syncthreads();
    }

    #pragma unroll
    for (int mi = 0; mi < 4; ++mi)
        #pragma unroll
        for (int ni = 0; ni < 4; ++ni) {
            int row = m0 + wm + mi * 16 + g;
            int col = bn + wn + ni * 8 + tg * 2;
            float b0 = bias[col], b1 = bias[col + 1];
            #pragma unroll
            for (int h = 0; h < 2; ++h) {
                int r = row + h * 8;
                float2 o;
                o.x = acc[mi][ni][h * 2]     + b0;
                o.y = acc[mi][ni][h * 2 + 1] + b1;
                *(float2*)&Cf[(size_t)r * N + col] = o;
            }
        }
}

// ---------------- fp16x2 GEMM (fast path): 2-stage, 2 CTA/SM ----------------
#define STAGEB2 30720
#define SMEMB2  61440

template<int MODE>   // 0: f32 out, 1: f32 gelu, 2: f16 out
__global__ void __launch_bounds__(256, 2) tc2_gemm(
    const __half* __restrict__ A1, int K1,
    const __half* __restrict__ A2,
    const __half* __restrict__ Wh, const __half* __restrict__ Wl, int Ktot,
    const float* __restrict__ bias,
    float* __restrict__ Cf, __half* __restrict__ Ch,
    int N)
{
    extern __shared__ __align__(16) char smem[];
    const uint32_t sb = smem_u32(smem);
    const int tid = threadIdx.x, wid = tid >> 5, lane = tid & 31;
    const int g = lane >> 2, tg = lane & 3;
    const int m0 = blockIdx.y * 128, bn = blockIdx.x * 128;
    const int wm = (wid & 1) * 64, wn = (wid >> 1) * 32;

    float acc[4][4][4] = {};
    const int nchunk = Ktot / 32;

    auto load_chunk = [&](int ci, int buf) {
        int k0 = ci * 32;
        const __half* A; int sA, kA;
        if (k0 < K1) { A = A1; sA = K1; kA = k0; }
        else         { A = A2; sA = Ktot - K1; kA = k0 - K1; }
        uint32_t base = sb + buf * STAGEB2;
        #pragma unroll
        for (int u = tid; u < 512; u += 256) {
            int r = u >> 2, c = (u & 3) * 8;
            uint32_t o = (uint32_t)(r * SROW + c * 2);
            cpa16(base + o, A + (size_t)(m0 + r) * sA + kA + c);
        }
        #pragma unroll
        for (int u = tid; u < 512; u += 256) {
            int r = u >> 2, c = (u & 3) * 8;
            uint32_t o = (uint32_t)(r * SROW + c * 2);
            size_t gi = (size_t)(bn + r) * Ktot + k0 + c;
            cpa16(base + TILEB + o, Wh + gi);
            cpa16(base + 2 * TILEB + o, Wl + gi);
        }
        cp_commit();
    };

    const uint32_t aoff = (uint32_t)(((lane & 7) + ((lane >> 3) & 1) * 8) * SROW
                                     + ((lane >> 4) & 1) * 16);
    const uint32_t boff = (uint32_t)(((lane & 7) + ((lane >> 4) & 1) * 8) * SROW
                                     + ((lane >> 3) & 1) * 16);

    load_chunk(0, 0);

    for (int ci = 0; ci < nchunk; ++ci) {
        if (ci + 1 < nchunk) {
            load_chunk(ci + 1, (ci + 1) & 1);
            asm volatile("cp.async.wait_group 1;" ::: "memory");
        } else {
            asm volatile("cp.async.wait_group 0;" ::: "memory");
        }
        __syncthreads();

        uint32_t st = sb + (ci & 1) * STAGEB2;
        uint32_t sA = st, sBh = st + TILEB, sBl = st + 2 * TILEB;

        #pragma unroll
        for (int ks = 0; ks < 2; ++ks) {
            uint32_t ka = (uint32_t)(ks * 32);
            uint32_t ah[4][4], bh[2][4], bl[2][4];
            uint32_t abase = (uint32_t)(wm * SROW) + aoff + ka;
            #pragma unroll
            for (int mi = 0; mi < 4; ++mi)
                LDSM4(ah[mi], sA + abase + mi * 16 * SROW);
            uint32_t bbase = (uint32_t)(wn * SROW) + boff + ka;
            #pragma unroll
            for (int np = 0; np < 2; ++np) {
                LDSM4(bh[np], sBh + bbase + np * 16 * SROW);
                LDSM4(bl[np], sBl + bbase + np * 16 * SROW);
            }
            #pragma unroll
            for (int np = 0; np < 2; ++np)
                #pragma unroll
                for (int sub = 0; sub < 2; ++sub) {
                    int ni = np * 2 + sub;
                    uint32_t h0 = bh[np][sub * 2], h1 = bh[np][sub * 2 + 1];
                    uint32_t l0 = bl[np][sub * 2], l1 = bl[np][sub * 2 + 1];
                    #pragma unroll
                    for (int mi = 0; mi < 4; ++mi) {
                        mma_f16(acc[mi][ni], ah[mi][0], ah[mi][1], ah[mi][2], ah[mi][3], h0, h1);
                        mma_f16(acc[mi][ni], ah[mi][0], ah[mi][1], ah[mi][2], ah[mi][3], l0, l1);
                    }
                }
        }
        __syncthreads();
    }

    #pragma unroll
    for (int mi = 0; mi < 4; ++mi)
        #pragma unroll
        for (int ni = 0; ni < 4; ++ni) {
            int row = m0 + wm + mi * 16 + g;
            int col = bn + wn + ni * 8 + tg * 2;
            float b0 = bias[col], b1 = bias[col + 1];
            #pragma unroll
            for (int h = 0; h < 2; ++h) {
                int r = row + h * 8;
                float v0 = acc[mi][ni][h * 2]     + b0;
                float v1 = acc[mi][ni][h * 2 + 1] + b1;
                if (MODE == 1) { v0 = gelu_exact(v0); v1 = gelu_exact(v1); }
                if (MODE == 2) {
                    __half2 hp; hp.x = __float2half(v0); hp.y = __float2half(v1);
                    *(__half2*)&Ch[(size_t)r * N + col] = hp;
                } else {
                    float2 o; o.x = v0; o.y = v1;
                    *(float2*)&Cf[(size_t)r * N + col] = o;
                }
            }
        }
}

// ---------------- split x -> bf16 hi/lo + fp16 ----------------
__global__ void split_x_kernel(const float4* __restrict__ x,
                               __nv_bfloat16* __restrict__ h, __nv_bfloat16* __restrict__ l,
                               __half* __restrict__ f)
{
    size_t i = (size_t)blockIdx.x * 256 + threadIdx.x;
    float4 v = x[i];
    float a[4] = {v.x, v.y, v.z, v.w};
    __nv_bfloat16 hh[4];
    #pragma unroll
    for (int c = 0; c < 4; ++c) hh[c] = __float2bfloat16(a[c]);
    __nv_bfloat162 hp0, hp1, lp0, lp1;
    hp0.x = hh[0]; hp0.y = hh[1]; hp1.x = hh[2]; hp1.y = hh[3];
    lp0.x = __float2bfloat16(a[0] - __bfloat162float(hh[0]));
    lp0.y = __float2bfloat16(a[1] - __bfloat162float(hh[1]));
    lp1.x = __float2bfloat16(a[2] - __bfloat162float(hh[2]));
    lp1.y = __float2bfloat16(a[3] - __bfloat162float(hh[3]));
    *(__nv_bfloat162*)&h[i * 4]     = hp0;
    *(__nv_bfloat162*)&h[i * 4 + 2] = hp1;
    *(__nv_bfloat162*)&l[i * 4]     = lp0;
    *(__nv_bfloat162*)&l[i * 4 + 2] = lp1;
    __half2 f0, f1;
    f0.x = __float2half(a[0]); f0.y = __float2half(a[1]);
    f1.x = __float2half(a[2]); f1.y = __float2half(a[3]);
    *(__half2*)&f[i * 4]     = f0;
    *(__half2*)&f[i * 4 + 2] = f1;
}

// ---------------- weight transpose + split (bf16) ----------------
__global__ void wsplit_bf(const float* __restrict__ W, int K, int N,
                          __nv_bfloat16* __restrict__ Th, __nv_bfloat16* __restrict__ Tl)
{
    __shared__ float tile[32][33];
    int kb = blockIdx.x * 32, nb = blockIdx.y * 32;
    int tx = threadIdx.x, ty = threadIdx.y;
    #pragma unroll
    for (int i = 0; i < 4; ++i)
        tile[ty + i * 8][tx] = W[(size_t)(kb + ty + i * 8) * N + nb + tx];
    __syncthreads();
    #pragma unroll
    for (int i = 0; i < 4; ++i) {
        int n = nb + ty + i * 8, k = kb + tx;
        float v = tile[tx][ty + i * 8];
        size_t o = (size_t)n * K + k;
        __nv_bfloat16 h = __float2bfloat16(v);
        Th[o] = h;
        Tl[o] = __float2bfloat16(v - __bfloat162float(h));
    }
}

// ---------------- weight transpose + split (fp16) ----------------
__global__ void wsplit_hf(const float* __restrict__ W, int K, int N,
                          __half* __restrict__ Th, __half* __restrict__ Tl)
{
    __shared__ float tile[32][33];
    int kb = blockIdx.x * 32, nb = blockIdx.y * 32;
    int tx = threadIdx.x, ty = threadIdx.y;
    #pragma unroll
    for (int i = 0; i < 4; ++i)
        tile[ty + i * 8][tx] = W[(size_t)(kb + ty + i * 8) * N + nb + tx];
    __syncthreads();
    #pragma unroll
    for (int i = 0; i < 4; ++i) {
        int n = nb + ty + i * 8, k = kb + tx;
        float v = tile[tx][ty + i * 8];
        size_t o = (size_t)n * K + k;
        __half h = __float2half(v);
        Th[o] = h;
        Tl[o] = __float2half(v - __half2float(h));
    }
}

// ---------------- bias concat ----------------
__global__ void biascat_kernel(const float* rg1_b, const float* imp1_b,
                               const float* rq_b, const float* twm_b, const float* wq_b,
                               float* bg, float* b3)
{
    int i = blockIdx.x * 256 + threadIdx.x;
    if (i < 512) bg[i] = rg1_b[i];
    else if (i < 1024) bg[i] = imp1_b[i - 512];
    else if (i < 1152) b3[i - 1024] = rq_b[i - 1024];
    else if (i < 1280) b3[i - 1024] = twm_b[i - 1152];
    else if (i < 1408) b3[i - 1024] = wq_b[i - 1280];
}

// ---------------- row-dot ----------------
__global__ void rowdot_kernel(const float* __restrict__ Hm, int stride,
                              const float* __restrict__ w, const float* __restrict__ bias,
                              const float* __restrict__ wt, int mode,
                              float* __restrict__ out)
{
    __shared__ float ws[HID];
    for (int i = threadIdx.x; i < HID; i += blockDim.x) ws[i] = w[i];
    __syncthreads();
    int warp = threadIdx.x >> 5, lane = threadIdx.x & 31;
    int row = blockIdx.x * 8 + warp;
    const float* h = Hm + (size_t)row * stride;
    float s = 0.f;
    for (int i = lane; i < HID; i += 32) s = fmaf(h[i], ws[i], s);
    #pragma unroll
    for (int o = 16; o; o >>= 1) s += __shfl_xor_sync(0xffffffffu, s, o);
    if (lane == 0) {
        float z = s + bias[0];
        if (mode == 1) out[row] = z;
        else {
            if (mode == 2) z /= fmaxf(wt[0], 0.1f);
            out[row] = 1.f / (1.f + expf(-z));
        }
    }
}

// ---------------- read attention (query stride 384, ctx out fp16) ----------------
__global__ void read_attn_kernel(const float* __restrict__ query,
                                 const float* __restrict__ wm,
                                 float* __restrict__ attn_out,
                                 __half* __restrict__ ctxf)
{
    __shared__ float cont[NSLOT][DSLOT];
    __shared__ float fresh[NSLOT];
    int tid = threadIdx.x;
    int tokenBase = blockIdx.x * 8;
    int b = tokenBase / SEQ;
    for (int i = tid; i < NSLOT * DSLOT; i += 256) {
        int k = i / DSLOT, d = i % DSLOT;
        cont[k][d] = wm[((size_t)b * NSLOT + k) * (DSLOT + 1) + d];
    }
    if (tid < NSLOT) fresh[tid] = wm[((size_t)b * NSLOT + tid) * (DSLOT + 1) + DSLOT];
    __syncthreads();
    int warp = tid >> 5, lane = tid & 31;
    int t = tokenBase + warp;
    const float* q = query + (size_t)t * 384;
    float ql[4];
    #pragma unroll
    for (int i = 0; i < 4; ++i) ql[i] = q[lane + 32 * i];
    float a[NSLOT];
    #pragma unroll
    for (int k = 0; k < NSLOT; ++k) {
        float s = 0.f;
        #pragma unroll
        for (int i = 0; i < 4; ++i) s = fmaf(ql[i], cont[k][lane + 32 * i], s);
        #pragma unroll
        for (int o = 16; o; o >>= 1) s += __shfl_xor_sync(0xffffffffu, s, o);
        s *= SCALE;
        if (fresh[k] < FRESH_THR) s = -1e9f;
        a[k] = s;
    }
    float mx = a[0];
    #pragma unroll
    for (int k = 1; k < NSLOT; ++k) mx = fmaxf(mx, a[k]);
    float sum = 0.f;
    #pragma unroll
    for (int k = 0; k < NSLOT; ++k) { a[k] = expf(a[k] - mx); sum += a[k]; }
    float inv = 1.f / sum;
    #pragma unroll
    for (int k = 0; k < NSLOT; ++k) a[k] *= inv;
    if (lane == 0) {
        #pragma unroll
        for (int k = 0; k < NSLOT; ++k) attn_out[(size_t)t * NSLOT + k] = a[k];
    }
    #pragma unroll
    for (int i = 0; i < 4; ++i) {
        int d = lane + 32 * i;
        float c = 0.f;
        #pragma unroll
        for (int k = 0; k < NSLOT; ++k) c = fmaf(a[k], cont[k][d], c);
        ctxf[(size_t)t * DSLOT + d] = __float2half(c);
    }
}

// ---------------- write attention (wq stride 384, ctx out fp16) ----------------
__global__ void write_attn_kernel(const float* __restrict__ wq,
                                  const float* __restrict__ wm,
                                  float* __restrict__ wsc_out,
                                  __half* __restrict__ wmf)
{
    __shared__ float cont[NSLOT][DSLOT];
    int tid = threadIdx.x;
    int tokenBase = blockIdx.x * 8;
    int b = tokenBase / SEQ;
    for (int i = tid; i < NSLOT * DSLOT; i += 256) {
        int k = i / DSLOT, d = i % DSLOT;
        cont[k][d] = wm[((size_t)b * NSLOT + k) * (DSLOT + 1) + d];
    }
    __syncthreads();
    int warp = tid >> 5, lane = tid & 31;
    int t = tokenBase + warp;
    const float* q = wq + (size_t)t * 384;
    float ql[4];
    #pragma unroll
    for (int i = 0; i < 4; ++i) ql[i] = q[lane + 32 * i];
    float a[NSLOT];
    #pragma unroll
    for (int k = 0; k < NSLOT; ++k) {
        float s = 0.f;
        #pragma unroll
        for (int i = 0; i < 4; ++i) s = fmaf(ql[i], cont[k][lane + 32 * i], s);
        #pragma unroll
        for (int o = 16; o; o >>= 1) s += __shfl_xor_sync(0xffffffffu, s, o);
        a[k] = s * SCALE;
    }
    if (lane == 0) {
        #pragma unroll
        for (int k = 0; k < NSLOT; ++k) wsc_out[(size_t)t * NSLOT + k] = a[k];
    }
    float mx = a[0];
    #pragma unroll
    for (int k = 1; k < NSLOT; ++k) mx = fmaxf(mx, a[k]);
    float sum = 0.f;
    #pragma unroll
    for (int k = 0; k < NSLOT; ++k) { a[k] = expf(a[k] - mx); sum += a[k]; }
    float inv = 1.f / sum;
    #pragma unroll
    for (int k = 0; k < NSLOT; ++k) a[k] *= inv;
    #pragma unroll
    for (int i = 0; i < 4; ++i) {
        int d = lane + 32 * i;
        float c = 0.f;
        #pragma unroll
        for (int k = 0; k < NSLOT; ++k) c = fmaf(a[k], cont[k][d], c);
        wmf[(size_t)t * DSLOT + d] = __float2half(c);
    }
}

// ---------------- small reductions ----------------
__global__ void pressure_kernel(const float* __restrict__ attn, float* __restrict__ rp)
{
    int b = blockIdx.x / NSLOT, k = blockIdx.x % NSLOT;
    __shared__ float sh[256];
    float s = 0.f;
    for (int si = threadIdx.x; si < SEQ; si += 256)
        s += attn[((size_t)b * SEQ + si) * NSLOT + k];
    sh[threadIdx.x] = s;
    __syncthreads();
    for (int o = 128; o; o >>= 1) {
        if (threadIdx.x < o) sh[threadIdx.x] += sh[threadIdx.x + o];
        __syncthreads();
    }
    if (threadIdx.x == 0) rp[blockIdx.x] = sh[0];
}

__global__ void freshness_kernel(const float* __restrict__ rp, const float* __restrict__ wm,
                                 float* __restrict__ nf)
{
    int t = threadIdx.x;
    int b = t / NSLOT;
    __shared__ float s[BATCH * NSLOT];
    s[t] = rp[t];
    __syncthreads();
    float mx = 1e-8f;
    #pragma unroll
    for (int k = 0; k < NSLOT; ++k) mx = fmaxf(mx, s[b * NSLOT + k]);
    float decay = 1.f - (s[t] / mx) * (1.f - READ_DECAY);
    nf[t] = wm[(size_t)t * (DSLOT + 1) + DSLOT] * decay;
}

__global__ void impsum_kernel(const float* __restrict__ logit, const float* __restrict__ wt,
                              float* __restrict__ outsum)
{
    int b = blockIdx.x;
    float temp = fmaxf(wt[0], 0.1f);
    __shared__ float sh[1024];
    float s = 0.f;
    for (int i = threadIdx.x; i < SEQ; i += 1024)
        s += expf(logit[(size_t)b * SEQ + i] / temp);
    sh[threadIdx.x] = s;
    __syncthreads();
    for (int o = 512; o; o >>= 1) {
        if (threadIdx.x < o) sh[threadIdx.x] += sh[threadIdx.x + o];
        __syncthreads();
    }
    if (threadIdx.x == 0) outsum[b] = sh[0];
}

__global__ void slotsel_kernel(const float* __restrict__ wsc, const float* __restrict__ nf,
                               const float* __restrict__ logit, const float* __restrict__ impsum,
                               const float* __restrict__ wg, const float* __restrict__ wt,
                               float* __restrict__ sel_onehot, int* __restrict__ sel_idx,
                               float* __restrict__ ww_out)
{
    int t = blockIdx.x * 256 + threadIdx.x;
    int b = t / SEQ;
    float temp = fmaxf(wt[0], 0.1f);
    float best = wsc[(size_t)t * NSLOT] - 2.f * nf[b * NSLOT];
    int bi = 0;
    #pragma unroll
    for (int k = 1; k < NSLOT; ++k) {
        float v = wsc[(size_t)t * NSLOT + k] - 2.f * nf[b * NSLOT + k];
        if (v > best) { best = v; bi = k; }
    }
    float imp = expf(logit[t] / temp) / (impsum[b] + 1e-8f) * (float)SEQ;
    sel_idx[t] = bi;
    ww_out[t] = wg[t] * imp;
    #pragma unroll
    for (int k = 0; k < NSLOT; ++k)
        sel_onehot[(size_t)t * NSLOT + k] = (k == bi) ? 1.f : 0.f;
}

// ---------------- slot aggregation: 2-phase ----------------
#define NSEG 8
#define SEGLEN (SEQ/NSEG)
__global__ void slotagg1_kernel(const int* __restrict__ sel, const float* __restrict__ ww,
                                const float* __restrict__ xslot,
                                float* __restrict__ pacc, float* __restrict__ pst)
{
    int blk = blockIdx.x;
    int bk = blk / NSEG, seg = blk % NSEG;
    int b = bk / NSLOT, k = bk % NSLOT;
    int d = threadIdx.x;
    float acc = 0.f, st = 0.f;
    const int s0 = b * SEQ + seg * SEGLEN;
    for (int si = 0; si < SEGLEN; ++si) {
        int tt = s0 + si;
        if (sel[tt] == k) {
            float w = ww[tt];
            st += w;
            acc = fmaf(w, xslot[(size_t)tt * 384 + d], acc);
        }
    }
    pacc[(size_t)blk * 128 + d] = acc;
    if (d == 0) pst[blk] = st;
}

__global__ void slotagg2_kernel(const float* __restrict__ pacc, const float* __restrict__ pst,
                                const float* __restrict__ wm, const float* __restrict__ nf,
                                float* __restrict__ wm_out)
{
    int bk = blockIdx.x;
    int d = threadIdx.x;
    float acc = 0.f, st = 0.f;
    #pragma unroll
    for (int s = 0; s < NSEG; ++s) {
        acc += pacc[(size_t)(bk * NSEG + s) * 128 + d];
        st  += pst[bk * NSEG + s];
    }
    float nc = acc / fmaxf(st, 1e-8f);
    float has = (st > 0.1f) ? 1.f : 0.f;
    float cont = wm[(size_t)bk * (DSLOT + 1) + d];
    wm_out[(size_t)bk * (DSLOT + 1) + d] = has * nc + (1.f - has) * cont;
    if (d == 0)
        wm_out[(size_t)bk * (DSLOT + 1) + DSLOT] = has * 1.f + (1.f - has) * nf[bk];
}

__global__ void enhance_kernel(const float* __restrict__ x, const float* __restrict__ fused,
                               const float* __restrict__ gate, float* __restrict__ out)
{
    size_t idx = (size_t)blockIdx.x * 256 + threadIdx.x;
    int t = (int)(idx >> 8);
    float g = gate[t];
    float4 xv = ((const float4*)x)[idx];
    float4 fv = ((const float4*)fused)[idx];
    float4 o;
    o.x = (1.f - g) * xv.x + g * fv.x;
    o.y = (1.f - g) * xv.y + g * fv.y;
    o.z = (1.f - g) * xv.z + g * fv.z;
    o.w = (1.f - g) * xv.w + g * fv.w;
    ((float4*)out)[idx] = o;
}

// ---------------- host ----------------
static void* symv(const void* s) { void* p = nullptr; cudaGetSymbolAddress(&p, s); return p; }

extern "C" void kernel_launch(void* const* d_in, const int* in_sizes, int n_in,
                              void* d_out, int out_size)
{
    const float* x      = (const float*)d_in[0];
    const float* wm     = (const float*)d_in[1];
    const float* rq_w   = (const float*)d_in[2];
    const float* rq_b   = (const float*)d_in[3];
    const float* fwm_w  = (const float*)d_in[4];
    const float* fwm_b  = (const float*)d_in[5];
    const float* rg1_w  = (const float*)d_in[6];
    const float* rg1_b  = (const float*)d_in[7];
    const float* rg2_w  = (const float*)d_in[8];
    const float* rg2_b  = (const float*)d_in[9];
    const float* fus_w  = (const float*)d_in[10];
    const float* fus_b  = (const float*)d_in[11];
    const float* twm_w  = (const float*)d_in[12];
    const float* twm_b  = (const float*)d_in[13];
    const float* wq_w   = (const float*)d_in[14];
    const float* wq_b   = (const float*)d_in[15];
    const float* imp1_w = (const float*)d_in[16];
    const float* imp1_b = (const float*)d_in[17];
    const float* imp2_w = (const float*)d_in[18];
    const float* imp2_b = (const float*)d_in[19];
    const float* wd1_w  = (const float*)d_in[20];
    const float* wd1_b  = (const float*)d_in[21];
    const float* wd2_w  = (const float*)d_in[22];
    const float* wd2_b  = (const float*)d_in[23];
    const float* wt     = (const float*)d_in[24];

    float* out = (float*)d_out;
    float* h1     = (float*)symv(g_h1);
    float* hg     = (float*)symv(g_hg);
    float* q3     = (float*)symv(g_q3);
    float* fused  = (float*)symv(g_fused);
    float* implog = (float*)symv(g_implogit);
    float* impsum = (float*)symv(g_impsum);
    float* wsc    = (float*)symv(g_wsc);
    float* nf     = (float*)symv(g_nf);
    float* rp     = (float*)symv(g_rp);
    int*   selidx = (int*)symv(g_sel);
    float* wwbuf  = (float*)symv(g_ww);
    float* bg     = (float*)symv(g_bg);
    float* b3     = (float*)symv(g_b3);
    float* pacc   = (float*)symv(g_pacc);
    float* pst    = (float*)symv(g_pst);
    __nv_bfloat16* xh  = (__nv_bfloat16*)symv(g_xh);
    __nv_bfloat16* xl  = (__nv_bfloat16*)symv(g_xl);
    __nv_bfloat16* wbh = (__nv_bfloat16*)symv(g_wbh);
    __nv_bfloat16* wbl = (__nv_bfloat16*)symv(g_wbl);
    __half* xf   = (__half*)symv(g_xf);
    __half* ctxf = (__half*)symv(g_ctxf);
    __half* conf = (__half*)symv(g_conf);
    __half* wmf  = (__half*)symv(g_wmf);
    __half* wfh  = (__half*)symv(g_wfh);
    __half* wfl  = (__half*)symv(g_wfl);

    cudaFuncSetAttribute(tc3_gemm,   cudaFuncAttributeMaxDynamicSharedMemorySize, SMEMB3);
    cudaFuncSetAttribute(tc2_gemm<0>, cudaFuncAttributeMaxDynamicSharedMemorySize, SMEMB2);
    cudaFuncSetAttribute(tc2_gemm<1>, cudaFuncAttributeMaxDynamicSharedMemorySize, SMEMB2);
    cudaFuncSetAttribute(tc2_gemm<2>, cudaFuncAttributeMaxDynamicSharedMemorySize, SMEMB2);

    dim3 tb8(32, 8);

    split_x_kernel<<<NT*DMODEL/4/256, 256>>>((const float4*)x, xh, xl, xf);
    // fp16 weights
    wsplit_hf<<<dim3(1024/32,  512/32), tb8>>>(rg1_w, 1024,  512, wfh+F_RG1, wfl+F_RG1);
    wsplit_hf<<<dim3(1024/32,  512/32), tb8>>>(imp1_w,1024,  512, wfh+F_IMP, wfl+F_IMP);
    wsplit_hf<<<dim3( 128/32, 1024/32), tb8>>>(fwm_w,  128, 1024, wfh+F_FWM, wfl+F_FWM);
    wsplit_hf<<<dim3(2048/32, 1024/32), tb8>>>(fus_w, 2048, 1024, wfh+F_FUS, wfl+F_FUS);
    wsplit_hf<<<dim3(1152/32,  512/32), tb8>>>(wd1_w, 1152,  512, wfh+F_WD1, wfl+F_WD1);
    // bf16 weights (q3)
    wsplit_bf<<<dim3(1024/32,  128/32), tb8>>>(rq_w,  1024,  128, wbh+B_RQ,  wbl+B_RQ);
    wsplit_bf<<<dim3(1024/32,  128/32), tb8>>>(twm_w, 1024,  128, wbh+B_TWM, wbl+B_TWM);
    wsplit_bf<<<dim3(1024/32,  128/32), tb8>>>(wq_w,  1024,  128, wbh+B_WQ,  wbl+B_WQ);
    biascat_kernel<<<6, 256>>>(rg1_b, imp1_b, rq_b, twm_b, wq_b, bg, b3);

    // merged gelu-hidden GEMM [rg1 | imp1]  (fp16 x2)
    tc2_gemm<1><<<dim3(8,128), 256, SMEMB2>>>(xf, 1024, nullptr,
        wfh+F_G, wfl+F_G, 1024, bg, hg, nullptr, 1024);
    rowdot_kernel<<<NT/8, 256>>>(hg,       1024, rg2_w,  rg2_b,  wt, 0, out + O_GATE);
    rowdot_kernel<<<NT/8, 256>>>(hg + 512, 1024, imp2_w, imp2_b, wt, 1, implog);
    impsum_kernel<<<BATCH, 1024>>>(implog, wt, impsum);

    // merged q3 GEMM [query | xslot | wq]  (bf16 x3 — argmax-critical)
    tc3_gemm<<<dim3(3,128), 256, SMEMB3>>>(xh, xl, wbh, wbl, 1024, b3, q3, 384);

    read_attn_kernel<<<NT/8, 256>>>(q3, wm, out + O_ATTN, ctxf);
    tc2_gemm<2><<<dim3(8,128), 256, SMEMB2>>>(ctxf, 128, nullptr,
        wfh+F_FWM, wfl+F_FWM, 128, fwm_b, nullptr, conf, 1024);
    tc2_gemm<0><<<dim3(8,128), 256, SMEMB2>>>(xf, 1024, conf,
        wfh+F_FUS, wfl+F_FUS, 2048, fus_b, fused, nullptr, 1024);
    enhance_kernel<<<(NT*DMODEL/4)/256, 256>>>(x, fused, out + O_GATE, out + O_XENH);

    pressure_kernel<<<BATCH*NSLOT, 256>>>(out + O_ATTN, rp);
    freshness_kernel<<<1, BATCH*NSLOT>>>(rp, wm, nf);

    write_attn_kernel<<<NT/8, 256>>>(q3 + 256, wm, wsc, wmf);
    tc2_gemm<1><<<dim3(4,128), 256, SMEMB2>>>(xf, 1024, wmf,
        wfh+F_WD1, wfl+F_WD1, 1152, wd1_b, h1, nullptr, 512);
    rowdot_kernel<<<NT/8, 256>>>(h1, 512, wd2_w, wd2_b, wt, 2, out + O_WG);

    slotsel_kernel<<<NT/256, 256>>>(wsc, nf, implog, impsum, out + O_WG, wt,
                                    out + O_SEL, selidx, wwbuf);
    slotagg1_kernel<<<BATCH*NSLOT*NSEG, 128>>>(selidx, wwbuf, q3 + 128, pacc, pst);
    slotagg2_kernel<<<BATCH*NSLOT, DSLOT>>>(pacc, pst, wm, nf, out + O_WM);
}

// round 13
// speedup vs baseline: 4.1477x; 1.0292x over previous
#include <cuda_runtime.h>
#include <cuda_bf16.h>
#include <cuda_fp16.h>
#include <math.h>
#include <stdint.h>

#define BATCH   4
#define SEQ     4096
#define NT      (BATCH*SEQ)
#define DMODEL  1024
#define DSLOT   128
#define NSLOT   8
#define HID     512
#define SCALE   (0.08838834764831845f)
#define FRESH_THR 0.1f
#define READ_DECAY 0.3f

#define O_XENH  ((size_t)0)
#define O_WM    ((size_t)16777216)
#define O_GATE  ((size_t)16781344)
#define O_WG    ((size_t)16797728)
#define O_ATTN  ((size_t)16814112)
#define O_SEL   ((size_t)16945184)

// ---------------- scratch ----------------
__device__ float g_h1[NT*HID];
__device__ float g_hg[NT*1024];
__device__ float g_q3[NT*384];
__device__ float g_implogit[NT];
__device__ float g_impsum[BATCH];
__device__ float g_wsc[NT*NSLOT];
__device__ float g_nf[BATCH*NSLOT];
__device__ float g_rp[BATCH*NSLOT];
__device__ int   g_sel[NT];
__device__ float g_ww[NT];
__device__ float g_bg[1024];
__device__ float g_b3[384];
__device__ float g_pacc[256*128];
__device__ float g_pst[256];

__device__ __nv_bfloat16 g_xh[NT*DMODEL], g_xl[NT*DMODEL];
__device__ __half g_xf[NT*DMODEL];
__device__ __half g_ctxf[NT*DSLOT];
__device__ __half g_conf[NT*DMODEL];
__device__ __half g_wmf[NT*DSLOT];

#define WB_TOTAL 393216
__device__ __nv_bfloat16 g_wbh[WB_TOTAL], g_wbl[WB_TOTAL];
#define B_RQ  0
#define B_TWM 131072
#define B_WQ  262144

#define WF_TOTAL 3866624
__device__ __half g_wfh[WF_TOTAL], g_wfl[WF_TOTAL];
#define F_G   0
#define F_RG1 (F_G)
#define F_IMP (F_G + 524288)
#define F_FWM 1048576
#define F_FUS 1179648
#define F_WD1 3276800

__device__ __forceinline__ float gelu_exact(float v) {
    return 0.5f * v * (1.0f + erff(v * 0.70710678118654752f));
}

// ---------------- asm helpers ----------------
__device__ __forceinline__ uint32_t smem_u32(const void* p) {
    uint32_t a;
    asm("{ .reg .u64 t; cvta.to.shared.u64 t, %1; cvt.u32.u64 %0, t; }" : "=r"(a) : "l"(p));
    return a;
}
__device__ __forceinline__ void cpa16(uint32_t s, const void* g) {
    asm volatile("cp.async.cg.shared.global [%0], [%1], 16;\n" :: "r"(s), "l"(g));
}
__device__ __forceinline__ void cp_commit() { asm volatile("cp.async.commit_group;\n" ::); }

__device__ __forceinline__ void mma_bf16(float* c, uint32_t a0, uint32_t a1, uint32_t a2,
                                         uint32_t a3, uint32_t b0, uint32_t b1) {
    asm volatile(
        "mma.sync.aligned.m16n8k16.row.col.f32.bf16.bf16.f32 "
        "{%0,%1,%2,%3},{%4,%5,%6,%7},{%8,%9},{%0,%1,%2,%3};"
        : "+f"(c[0]), "+f"(c[1]), "+f"(c[2]), "+f"(c[3])
        : "r"(a0), "r"(a1), "r"(a2), "r"(a3), "r"(b0), "r"(b1));
}
__device__ __forceinline__ void mma_f16(float* c, uint32_t a0, uint32_t a1, uint32_t a2,
                                        uint32_t a3, uint32_t b0, uint32_t b1) {
    asm volatile(
        "mma.sync.aligned.m16n8k16.row.col.f32.f16.f16.f32 "
        "{%0,%1,%2,%3},{%4,%5,%6,%7},{%8,%9},{%0,%1,%2,%3};"
        : "+f"(c[0]), "+f"(c[1]), "+f"(c[2]), "+f"(c[3])
        : "r"(a0), "r"(a1), "r"(a2), "r"(a3), "r"(b0), "r"(b1));
}
#define LDSM4(r, addr) \
    asm volatile("ldmatrix.sync.aligned.m8n8.x4.shared.b16 {%0,%1,%2,%3}, [%4];" \
        : "=r"((r)[0]), "=r"((r)[1]), "=r"((r)[2]), "=r"((r)[3]) : "r"(addr))

#define SROW   80
#define TILEB  10240

// ---------------- bf16x3 GEMM (q3 path): 2-stage, 2 CTA/SM ----------------
#define STAGEB3 40960
#define SMEMB3  81920

__global__ void __launch_bounds__(256, 2) tc3_gemm(
    const __nv_bfloat16* __restrict__ Ah, const __nv_bfloat16* __restrict__ Al,
    const __nv_bfloat16* __restrict__ Wh, const __nv_bfloat16* __restrict__ Wl, int Ktot,
    const float* __restrict__ bias, float* __restrict__ Cf, int N)
{
    extern __shared__ __align__(16) char smem[];
    const uint32_t sb = smem_u32(smem);
    const int tid = threadIdx.x, wid = tid >> 5, lane = tid & 31;
    const int g = lane >> 2, tg = lane & 3;
    const int m0 = blockIdx.y * 128, bn = blockIdx.x * 128;
    const int wm = (wid & 1) * 64, wn = (wid >> 1) * 32;

    float acc[4][4][4] = {};
    const int nchunk = Ktot / 32;

    auto load_chunk = [&](int ci, int buf) {
        int k0 = ci * 32;
        uint32_t base = sb + buf * STAGEB3;
        #pragma unroll
        for (int u = tid; u < 512; u += 256) {
            int r = u >> 2, c = (u & 3) * 8;
            uint32_t o = (uint32_t)(r * SROW + c * 2);
            size_t gi = (size_t)(m0 + r) * Ktot + k0 + c;
            cpa16(base + o, Ah + gi);
            cpa16(base + TILEB + o, Al + gi);
        }
        #pragma unroll
        for (int u = tid; u < 512; u += 256) {
            int r = u >> 2, c = (u & 3) * 8;
            uint32_t o = (uint32_t)(r * SROW + c * 2);
            size_t gi = (size_t)(bn + r) * Ktot + k0 + c;
            cpa16(base + 2 * TILEB + o, Wh + gi);
            cpa16(base + 3 * TILEB + o, Wl + gi);
        }
        cp_commit();
    };

    const uint32_t aoff = (uint32_t)(((lane & 7) + ((lane >> 3) & 1) * 8) * SROW
                                     + ((lane >> 4) & 1) * 16);
    const uint32_t boff = (uint32_t)(((lane & 7) + ((lane >> 4) & 1) * 8) * SROW
                                     + ((lane >> 3) & 1) * 16);

    load_chunk(0, 0);

    for (int ci = 0; ci < nchunk; ++ci) {
        if (ci + 1 < nchunk) {
            load_chunk(ci + 1, (ci + 1) & 1);
            asm volatile("cp.async.wait_group 1;" ::: "memory");
        } else {
            asm volatile("cp.async.wait_group 0;" ::: "memory");
        }
        __syncthreads();

        uint32_t st = sb + (ci & 1) * STAGEB3;
        uint32_t sAh = st, sAl = st + TILEB, sBh = st + 2 * TILEB, sBl = st + 3 * TILEB;

        #pragma unroll
        for (int ks = 0; ks < 2; ++ks) {
            uint32_t ka = (uint32_t)(ks * 32);
            uint32_t ah[4][4], bh[2][4], bl[2][4];
            uint32_t abase = (uint32_t)(wm * SROW) + aoff + ka;
            #pragma unroll
            for (int mi = 0; mi < 4; ++mi)
                LDSM4(ah[mi], sAh + abase + mi * 16 * SROW);
            uint32_t bbase = (uint32_t)(wn * SROW) + boff + ka;
            #pragma unroll
            for (int np = 0; np < 2; ++np) {
                LDSM4(bh[np], sBh + bbase + np * 16 * SROW);
                LDSM4(bl[np], sBl + bbase + np * 16 * SROW);
            }
            #pragma unroll
            for (int np = 0; np < 2; ++np)
                #pragma unroll
                for (int sub = 0; sub < 2; ++sub) {
                    int ni = np * 2 + sub;
                    uint32_t h0 = bh[np][sub * 2], h1 = bh[np][sub * 2 + 1];
                    uint32_t l0 = bl[np][sub * 2], l1 = bl[np][sub * 2 + 1];
                    #pragma unroll
                    for (int mi = 0; mi < 4; ++mi) {
                        mma_bf16(acc[mi][ni], ah[mi][0], ah[mi][1], ah[mi][2], ah[mi][3], h0, h1);
                        mma_bf16(acc[mi][ni], ah[mi][0], ah[mi][1], ah[mi][2], ah[mi][3], l0, l1);
                    }
                }
            #pragma unroll
            for (int mi = 0; mi < 4; ++mi)
                LDSM4(ah[mi], sAl + abase + mi * 16 * SROW);
            #pragma unroll
            for (int np = 0; np < 2; ++np)
                #pragma unroll
                for (int sub = 0; sub < 2; ++sub) {
                    int ni = np * 2 + sub;
                    uint32_t h0 = bh[np][sub * 2], h1 = bh[np][sub * 2 + 1];
                    #pragma unroll
                    for (int mi = 0; mi < 4; ++mi)
                        mma_bf16(acc[mi][ni], ah[mi][0], ah[mi][1], ah[mi][2], ah[mi][3], h0, h1);
                }
        }
        __syncthreads();
    }

    #pragma unroll
    for (int mi = 0; mi < 4; ++mi)
        #pragma unroll
        for (int ni = 0; ni < 4; ++ni) {
            int row = m0 + wm + mi * 16 + g;
            int col = bn + wn + ni * 8 + tg * 2;
            float b0 = bias[col], b1 = bias[col + 1];
            #pragma unroll
            for (int h = 0; h < 2; ++h) {
                int r = row + h * 8;
                float2 o;
                o.x = acc[mi][ni][h * 2]     + b0;
                o.y = acc[mi][ni][h * 2 + 1] + b1;
                *(float2*)&Cf[(size_t)r * N + col] = o;
            }
        }
}

// ---------------- fp16x2 GEMM: 3-stage, 2 CTA/SM ----------------
#define STAGEB2 30720
#define NST2    3
#define SMEMB2  (NST2*STAGEB2)

// MODE 0: f32 out, 1: f32 gelu, 2: f16 out, 3: enhance out=(1-g)x+g(acc+b)
template<int MODE>
__global__ void __launch_bounds__(256, 2) tc2_gemm(
    const __half* __restrict__ A1, int K1,
    const __half* __restrict__ A2,
    const __half* __restrict__ Wh, const __half* __restrict__ Wl, int Ktot,
    const float* __restrict__ bias,
    float* __restrict__ Cf, __half* __restrict__ Ch,
    const float* __restrict__ Xf, const float* __restrict__ gate,
    int N)
{
    extern __shared__ __align__(16) char smem[];
    const uint32_t sb = smem_u32(smem);
    const int tid = threadIdx.x, wid = tid >> 5, lane = tid & 31;
    const int g = lane >> 2, tg = lane & 3;
    const int m0 = blockIdx.y * 128, bn = blockIdx.x * 128;
    const int wm = (wid & 1) * 64, wn = (wid >> 1) * 32;

    float acc[4][4][4] = {};
    const int nchunk = Ktot / 32;

    auto load_chunk = [&](int ci, int buf) {
        int k0 = ci * 32;
        const __half* A; int sA, kA;
        if (k0 < K1) { A = A1; sA = K1; kA = k0; }
        else         { A = A2; sA = Ktot - K1; kA = k0 - K1; }
        uint32_t base = sb + buf * STAGEB2;
        #pragma unroll
        for (int u = tid; u < 512; u += 256) {
            int r = u >> 2, c = (u & 3) * 8;
            uint32_t o = (uint32_t)(r * SROW + c * 2);
            cpa16(base + o, A + (size_t)(m0 + r) * sA + kA + c);
        }
        #pragma unroll
        for (int u = tid; u < 512; u += 256) {
            int r = u >> 2, c = (u & 3) * 8;
            uint32_t o = (uint32_t)(r * SROW + c * 2);
            size_t gi = (size_t)(bn + r) * Ktot + k0 + c;
            cpa16(base + TILEB + o, Wh + gi);
            cpa16(base + 2 * TILEB + o, Wl + gi);
        }
        cp_commit();
    };

    const uint32_t aoff = (uint32_t)(((lane & 7) + ((lane >> 3) & 1) * 8) * SROW
                                     + ((lane >> 4) & 1) * 16);
    const uint32_t boff = (uint32_t)(((lane & 7) + ((lane >> 4) & 1) * 8) * SROW
                                     + ((lane >> 3) & 1) * 16);

    load_chunk(0, 0);
    if (nchunk > 1) load_chunk(1, 1);

    for (int ci = 0; ci < nchunk; ++ci) {
        if (ci + 2 < nchunk) {
            load_chunk(ci + 2, (ci + 2) % NST2);
            asm volatile("cp.async.wait_group 2;" ::: "memory");
        } else if (ci + 1 < nchunk) {
            asm volatile("cp.async.wait_group 1;" ::: "memory");
        } else {
            asm volatile("cp.async.wait_group 0;" ::: "memory");
        }
        __syncthreads();

        uint32_t st = sb + (ci % NST2) * STAGEB2;
        uint32_t sA = st, sBh = st + TILEB, sBl = st + 2 * TILEB;

        #pragma unroll
        for (int ks = 0; ks < 2; ++ks) {
            uint32_t ka = (uint32_t)(ks * 32);
            uint32_t ah[4][4], bh[2][4], bl[2][4];
            uint32_t abase = (uint32_t)(wm * SROW) + aoff + ka;
            #pragma unroll
            for (int mi = 0; mi < 4; ++mi)
                LDSM4(ah[mi], sA + abase + mi * 16 * SROW);
            uint32_t bbase = (uint32_t)(wn * SROW) + boff + ka;
            #pragma unroll
            for (int np = 0; np < 2; ++np) {
                LDSM4(bh[np], sBh + bbase + np * 16 * SROW);
                LDSM4(bl[np], sBl + bbase + np * 16 * SROW);
            }
            #pragma unroll
            for (int np = 0; np < 2; ++np)
                #pragma unroll
                for (int sub = 0; sub < 2; ++sub) {
                    int ni = np * 2 + sub;
                    uint32_t h0 = bh[np][sub * 2], h1 = bh[np][sub * 2 + 1];
                    uint32_t l0 = bl[np][sub * 2], l1 = bl[np][sub * 2 + 1];
                    #pragma unroll
                    for (int mi = 0; mi < 4; ++mi) {
                        mma_f16(acc[mi][ni], ah[mi][0], ah[mi][1], ah[mi][2], ah[mi][3], h0, h1);
                        mma_f16(acc[mi][ni], ah[mi][0], ah[mi][1], ah[mi][2], ah[mi][3], l0, l1);
                    }
                }
        }
        __syncthreads();
    }

    #pragma unroll
    for (int mi = 0; mi < 4; ++mi)
        #pragma unroll
        for (int ni = 0; ni < 4; ++ni) {
            int row = m0 + wm + mi * 16 + g;
            int col = bn + wn + ni * 8 + tg * 2;
            float b0 = bias[col], b1 = bias[col + 1];
            #pragma unroll
            for (int h = 0; h < 2; ++h) {
                int r = row + h * 8;
                float v0 = acc[mi][ni][h * 2]     + b0;
                float v1 = acc[mi][ni][h * 2 + 1] + b1;
                if (MODE == 1) { v0 = gelu_exact(v0); v1 = gelu_exact(v1); }
                if (MODE == 2) {
                    __half2 hp; hp.x = __float2half(v0); hp.y = __float2half(v1);
                    *(__half2*)&Ch[(size_t)r * N + col] = hp;
                } else if (MODE == 3) {
                    float gv = gate[r];
                    float2 xv = *(const float2*)&Xf[(size_t)r * N + col];
                    float2 o;
                    o.x = (1.f - gv) * xv.x + gv * v0;
                    o.y = (1.f - gv) * xv.y + gv * v1;
                    *(float2*)&Cf[(size_t)r * N + col] = o;
                } else {
                    float2 o; o.x = v0; o.y = v1;
                    *(float2*)&Cf[(size_t)r * N + col] = o;
                }
            }
        }
}

// ---------------- split x -> bf16 hi/lo + fp16 ----------------
__global__ void split_x_kernel(const float4* __restrict__ x,
                               __nv_bfloat16* __restrict__ h, __nv_bfloat16* __restrict__ l,
                               __half* __restrict__ f)
{
    size_t i = (size_t)blockIdx.x * 256 + threadIdx.x;
    float4 v = x[i];
    float a[4] = {v.x, v.y, v.z, v.w};
    __nv_bfloat16 hh[4];
    #pragma unroll
    for (int c = 0; c < 4; ++c) hh[c] = __float2bfloat16(a[c]);
    __nv_bfloat162 hp0, hp1, lp0, lp1;
    hp0.x = hh[0]; hp0.y = hh[1]; hp1.x = hh[2]; hp1.y = hh[3];
    lp0.x = __float2bfloat16(a[0] - __bfloat162float(hh[0]));
    lp0.y = __float2bfloat16(a[1] - __bfloat162float(hh[1]));
    lp1.x = __float2bfloat16(a[2] - __bfloat162float(hh[2]));
    lp1.y = __float2bfloat16(a[3] - __bfloat162float(hh[3]));
    *(__nv_bfloat162*)&h[i * 4]     = hp0;
    *(__nv_bfloat162*)&h[i * 4 + 2] = hp1;
    *(__nv_bfloat162*)&l[i * 4]     = lp0;
    *(__nv_bfloat162*)&l[i * 4 + 2] = lp1;
    __half2 f0, f1;
    f0.x = __float2half(a[0]); f0.y = __float2half(a[1]);
    f1.x = __float2half(a[2]); f1.y = __float2half(a[3]);
    *(__half2*)&f[i * 4]     = f0;
    *(__half2*)&f[i * 4 + 2] = f1;
}

// ---------------- weight transpose + split (bf16 / fp16) ----------------
__global__ void wsplit_bf(const float* __restrict__ W, int K, int N,
                          __nv_bfloat16* __restrict__ Th, __nv_bfloat16* __restrict__ Tl)
{
    __shared__ float tile[32][33];
    int kb = blockIdx.x * 32, nb = blockIdx.y * 32;
    int tx = threadIdx.x, ty = threadIdx.y;
    #pragma unroll
    for (int i = 0; i < 4; ++i)
        tile[ty + i * 8][tx] = W[(size_t)(kb + ty + i * 8) * N + nb + tx];
    __syncthreads();
    #pragma unroll
    for (int i = 0; i < 4; ++i) {
        int n = nb + ty + i * 8, k = kb + tx;
        float v = tile[tx][ty + i * 8];
        size_t o = (size_t)n * K + k;
        __nv_bfloat16 h = __float2bfloat16(v);
        Th[o] = h;
        Tl[o] = __float2bfloat16(v - __bfloat162float(h));
    }
}

__global__ void wsplit_hf(const float* __restrict__ W, int K, int N,
                          __half* __restrict__ Th, __half* __restrict__ Tl)
{
    __shared__ float tile[32][33];
    int kb = blockIdx.x * 32, nb = blockIdx.y * 32;
    int tx = threadIdx.x, ty = threadIdx.y;
    #pragma unroll
    for (int i = 0; i < 4; ++i)
        tile[ty + i * 8][tx] = W[(size_t)(kb + ty + i * 8) * N + nb + tx];
    __syncthreads();
    #pragma unroll
    for (int i = 0; i < 4; ++i) {
        int n = nb + ty + i * 8, k = kb + tx;
        float v = tile[tx][ty + i * 8];
        size_t o = (size_t)n * K + k;
        __half h = __float2half(v);
        Th[o] = h;
        Tl[o] = __float2half(v - __half2float(h));
    }
}

// ---------------- bias concat ----------------
__global__ void biascat_kernel(const float* rg1_b, const float* imp1_b,
                               const float* rq_b, const float* twm_b, const float* wq_b,
                               float* bg, float* b3)
{
    int i = blockIdx.x * 256 + threadIdx.x;
    if (i < 512) bg[i] = rg1_b[i];
    else if (i < 1024) bg[i] = imp1_b[i - 512];
    else if (i < 1152) b3[i - 1024] = rq_b[i - 1024];
    else if (i < 1280) b3[i - 1024] = twm_b[i - 1152];
    else if (i < 1408) b3[i - 1024] = wq_b[i - 1280];
}

// ---------------- row-dot ----------------
__global__ void rowdot_kernel(const float* __restrict__ Hm, int stride,
                              const float* __restrict__ w, const float* __restrict__ bias,
                              const float* __restrict__ wt, int mode,
                              float* __restrict__ out)
{
    __shared__ float ws[HID];
    for (int i = threadIdx.x; i < HID; i += blockDim.x) ws[i] = w[i];
    __syncthreads();
    int warp = threadIdx.x >> 5, lane = threadIdx.x & 31;
    int row = blockIdx.x * 8 + warp;
    const float* h = Hm + (size_t)row * stride;
    float s = 0.f;
    for (int i = lane; i < HID; i += 32) s = fmaf(h[i], ws[i], s);
    #pragma unroll
    for (int o = 16; o; o >>= 1) s += __shfl_xor_sync(0xffffffffu, s, o);
    if (lane == 0) {
        float z = s + bias[0];
        if (mode == 1) out[row] = z;
        else {
            if (mode == 2) z /= fmaxf(wt[0], 0.1f);
            out[row] = 1.f / (1.f + expf(-z));
        }
    }
}

// ---------------- combined read+write attention ----------------
__global__ void attn_kernel(const float* __restrict__ q3,
                            const float* __restrict__ wm,
                            float* __restrict__ attn_out,
                            __half* __restrict__ ctxf,
                            float* __restrict__ wsc_out,
                            __half* __restrict__ wmf)
{
    __shared__ float cont[NSLOT][DSLOT];
    __shared__ float fresh[NSLOT];
    int tid = threadIdx.x;
    int tokenBase = blockIdx.x * 8;
    int b = tokenBase / SEQ;
    for (int i = tid; i < NSLOT * DSLOT; i += 256) {
        int k = i / DSLOT, d = i % DSLOT;
        cont[k][d] = wm[((size_t)b * NSLOT + k) * (DSLOT + 1) + d];
    }
    if (tid < NSLOT) fresh[tid] = wm[((size_t)b * NSLOT + tid) * (DSLOT + 1) + DSLOT];
    __syncthreads();
    int warp = tid >> 5, lane = tid & 31;
    int t = tokenBase + warp;

    // ---- read attention (query at offset 0) ----
    {
        const float* q = q3 + (size_t)t * 384;
        float ql[4];
        #pragma unroll
        for (int i = 0; i < 4; ++i) ql[i] = q[lane + 32 * i];
        float a[NSLOT];
        #pragma unroll
        for (int k = 0; k < NSLOT; ++k) {
            float s = 0.f;
            #pragma unroll
            for (int i = 0; i < 4; ++i) s = fmaf(ql[i], cont[k][lane + 32 * i], s);
            #pragma unroll
            for (int o = 16; o; o >>= 1) s += __shfl_xor_sync(0xffffffffu, s, o);
            s *= SCALE;
            if (fresh[k] < FRESH_THR) s = -1e9f;
            a[k] = s;
        }
        float mx = a[0];
        #pragma unroll
        for (int k = 1; k < NSLOT; ++k) mx = fmaxf(mx, a[k]);
        float sum = 0.f;
        #pragma unroll
        for (int k = 0; k < NSLOT; ++k) { a[k] = expf(a[k] - mx); sum += a[k]; }
        float inv = 1.f / sum;
        #pragma unroll
        for (int k = 0; k < NSLOT; ++k) a[k] *= inv;
        if (lane == 0) {
            #pragma unroll
            for (int k = 0; k < NSLOT; ++k) attn_out[(size_t)t * NSLOT + k] = a[k];
        }
        #pragma unroll
        for (int i = 0; i < 4; ++i) {
            int d = lane + 32 * i;
            float c = 0.f;
            #pragma unroll
            for (int k = 0; k < NSLOT; ++k) c = fmaf(a[k], cont[k][d], c);
            ctxf[(size_t)t * DSLOT + d] = __float2half(c);
        }
    }
    // ---- write attention (wq at offset 256) ----
    {
        const float* q = q3 + (size_t)t * 384 + 256;
        float ql[4];
        #pragma unroll
        for (int i = 0; i < 4; ++i) ql[i] = q[lane + 32 * i];
        float a[NSLOT];
        #pragma unroll
        for (int k = 0; k < NSLOT; ++k) {
            float s = 0.f;
            #pragma unroll
            for (int i = 0; i < 4; ++i) s = fmaf(ql[i], cont[k][lane + 32 * i], s);
            #pragma unroll
            for (int o = 16; o; o >>= 1) s += __shfl_xor_sync(0xffffffffu, s, o);
            a[k] = s * SCALE;
        }
        if (lane == 0) {
            #pragma unroll
            for (int k = 0; k < NSLOT; ++k) wsc_out[(size_t)t * NSLOT + k] = a[k];
        }
        float mx = a[0];
        #pragma unroll
        for (int k = 1; k < NSLOT; ++k) mx = fmaxf(mx, a[k]);
        float sum = 0.f;
        #pragma unroll
        for (int k = 0; k < NSLOT; ++k) { a[k] = expf(a[k] - mx); sum += a[k]; }
        float inv = 1.f / sum;
        #pragma unroll
        for (int k = 0; k < NSLOT; ++k) a[k] *= inv;
        #pragma unroll
        for (int i = 0; i < 4; ++i) {
            int d = lane + 32 * i;
            float c = 0.f;
            #pragma unroll
            for (int k = 0; k < NSLOT; ++k) c = fmaf(a[k], cont[k][d], c);
            wmf[(size_t)t * DSLOT + d] = __float2half(c);
        }
    }
}

// ---------------- small reductions ----------------
__global__ void pressure_kernel(const float* __restrict__ attn, float* __restrict__ rp)
{
    int b = blockIdx.x / NSLOT, k = blockIdx.x % NSLOT;
    __shared__ float sh[256];
    float s = 0.f;
    for (int si = threadIdx.x; si < SEQ; si += 256)
        s += attn[((size_t)b * SEQ + si) * NSLOT + k];
    sh[threadIdx.x] = s;
    __syncthreads();
    for (int o = 128; o; o >>= 1) {
        if (threadIdx.x < o) sh[threadIdx.x] += sh[threadIdx.x + o];
        __syncthreads();
    }
    if (threadIdx.x == 0) rp[blockIdx.x] = sh[0];
}

__global__ void freshness_kernel(const float* __restrict__ rp, const float* __restrict__ wm,
                                 float* __restrict__ nf)
{
    int t = threadIdx.x;
    int b = t / NSLOT;
    __shared__ float s[BATCH * NSLOT];
    s[t] = rp[t];
    __syncthreads();
    float mx = 1e-8f;
    #pragma unroll
    for (int k = 0; k < NSLOT; ++k) mx = fmaxf(mx, s[b * NSLOT + k]);
    float decay = 1.f - (s[t] / mx) * (1.f - READ_DECAY);
    nf[t] = wm[(size_t)t * (DSLOT + 1) + DSLOT] * decay;
}

__global__ void impsum_kernel(const float* __restrict__ logit, const float* __restrict__ wt,
                              float* __restrict__ outsum)
{
    int b = blockIdx.x;
    float temp = fmaxf(wt[0], 0.1f);
    __shared__ float sh[1024];
    float s = 0.f;
    for (int i = threadIdx.x; i < SEQ; i += 1024)
        s += expf(logit[(size_t)b * SEQ + i] / temp);
    sh[threadIdx.x] = s;
    __syncthreads();
    for (int o = 512; o; o >>= 1) {
        if (threadIdx.x < o) sh[threadIdx.x] += sh[threadIdx.x + o];
        __syncthreads();
    }
    if (threadIdx.x == 0) outsum[b] = sh[0];
}

__global__ void slotsel_kernel(const float* __restrict__ wsc, const float* __restrict__ nf,
                               const float* __restrict__ logit, const float* __restrict__ impsum,
                               const float* __restrict__ wg, const float* __restrict__ wt,
                               float* __restrict__ sel_onehot, int* __restrict__ sel_idx,
                               float* __restrict__ ww_out)
{
    int t = blockIdx.x * 256 + threadIdx.x;
    int b = t / SEQ;
    float temp = fmaxf(wt[0], 0.1f);
    float best = wsc[(size_t)t * NSLOT] - 2.f * nf[b * NSLOT];
    int bi = 0;
    #pragma unroll
    for (int k = 1; k < NSLOT; ++k) {
        float v = wsc[(size_t)t * NSLOT + k] - 2.f * nf[b * NSLOT + k];
        if (v > best) { best = v; bi = k; }
    }
    float imp = expf(logit[t] / temp) / (impsum[b] + 1e-8f) * (float)SEQ;
    sel_idx[t] = bi;
    ww_out[t] = wg[t] * imp;
    #pragma unroll
    for (int k = 0; k < NSLOT; ++k)
        sel_onehot[(size_t)t * NSLOT + k] = (k == bi) ? 1.f : 0.f;
}

// ---------------- slot aggregation: 2-phase ----------------
#define NSEG 8
#define SEGLEN (SEQ/NSEG)
__global__ void slotagg1_kernel(const int* __restrict__ sel, const float* __restrict__ ww,
                                const float* __restrict__ xslot,
                                float* __restrict__ pacc, float* __restrict__ pst)
{
    int blk = blockIdx.x;
    int bk = blk / NSEG, seg = blk % NSEG;
    int b = bk / NSLOT, k = bk % NSLOT;
    int d = threadIdx.x;
    float acc = 0.f, st = 0.f;
    const int s0 = b * SEQ + seg * SEGLEN;
    for (int si = 0; si < SEGLEN; ++si) {
        int tt = s0 + si;
        if (sel[tt] == k) {
            float w = ww[tt];
            st += w;
            acc = fmaf(w, xslot[(size_t)tt * 384 + d], acc);
        }
    }
    pacc[(size_t)blk * 128 + d] = acc;
    if (d == 0) pst[blk] = st;
}

__global__ void slotagg2_kernel(const float* __restrict__ pacc, const float* __restrict__ pst,
                                const float* __restrict__ wm, const float* __restrict__ nf,
                                float* __restrict__ wm_out)
{
    int bk = blockIdx.x;
    int d = threadIdx.x;
    float acc = 0.f, st = 0.f;
    #pragma unroll
    for (int s = 0; s < NSEG; ++s) {
        acc += pacc[(size_t)(bk * NSEG + s) * 128 + d];
        st  += pst[bk * NSEG + s];
    }
    float nc = acc / fmaxf(st, 1e-8f);
    float has = (st > 0.1f) ? 1.f : 0.f;
    float cont = wm[(size_t)bk * (DSLOT + 1) + d];
    wm_out[(size_t)bk * (DSLOT + 1) + d] = has * nc + (1.f - has) * cont;
    if (d == 0)
        wm_out[(size_t)bk * (DSLOT + 1) + DSLOT] = has * 1.f + (1.f - has) * nf[bk];
}

// ---------------- host ----------------
static void* symv(const void* s) { void* p = nullptr; cudaGetSymbolAddress(&p, s); return p; }

extern "C" void kernel_launch(void* const* d_in, const int* in_sizes, int n_in,
                              void* d_out, int out_size)
{
    const float* x      = (const float*)d_in[0];
    const float* wm     = (const float*)d_in[1];
    const float* rq_w   = (const float*)d_in[2];
    const float* rq_b   = (const float*)d_in[3];
    const float* fwm_w  = (const float*)d_in[4];
    const float* fwm_b  = (const float*)d_in[5];
    const float* rg1_w  = (const float*)d_in[6];
    const float* rg1_b  = (const float*)d_in[7];
    const float* rg2_w  = (const float*)d_in[8];
    const float* rg2_b  = (const float*)d_in[9];
    const float* fus_w  = (const float*)d_in[10];
    const float* fus_b  = (const float*)d_in[11];
    const float* twm_w  = (const float*)d_in[12];
    const float* twm_b  = (const float*)d_in[13];
    const float* wq_w   = (const float*)d_in[14];
    const float* wq_b   = (const float*)d_in[15];
    const float* imp1_w = (const float*)d_in[16];
    const float* imp1_b = (const float*)d_in[17];
    const float* imp2_w = (const float*)d_in[18];
    const float* imp2_b = (const float*)d_in[19];
    const float* wd1_w  = (const float*)d_in[20];
    const float* wd1_b  = (const float*)d_in[21];
    const float* wd2_w  = (const float*)d_in[22];
    const float* wd2_b  = (const float*)d_in[23];
    const float* wt     = (const float*)d_in[24];

    float* out = (float*)d_out;
    float* h1     = (float*)symv(g_h1);
    float* hg     = (float*)symv(g_hg);
    float* q3     = (float*)symv(g_q3);
    float* implog = (float*)symv(g_implogit);
    float* impsum = (float*)symv(g_impsum);
    float* wsc    = (float*)symv(g_wsc);
    float* nf     = (float*)symv(g_nf);
    float* rp     = (float*)symv(g_rp);
    int*   selidx = (int*)symv(g_sel);
    float* wwbuf  = (float*)symv(g_ww);
    float* bg     = (float*)symv(g_bg);
    float* b3     = (float*)symv(g_b3);
    float* pacc   = (float*)symv(g_pacc);
    float* pst    = (float*)symv(g_pst);
    __nv_bfloat16* xh  = (__nv_bfloat16*)symv(g_xh);
    __nv_bfloat16* xl  = (__nv_bfloat16*)symv(g_xl);
    __nv_bfloat16* wbh = (__nv_bfloat16*)symv(g_wbh);
    __nv_bfloat16* wbl = (__nv_bfloat16*)symv(g_wbl);
    __half* xf   = (__half*)symv(g_xf);
    __half* ctxf = (__half*)symv(g_ctxf);
    __half* conf = (__half*)symv(g_conf);
    __half* wmf  = (__half*)symv(g_wmf);
    __half* wfh  = (__half*)symv(g_wfh);
    __half* wfl  = (__half*)symv(g_wfl);

    cudaFuncSetAttribute(tc3_gemm,    cudaFuncAttributeMaxDynamicSharedMemorySize, SMEMB3);
    cudaFuncSetAttribute(tc2_gemm<0>, cudaFuncAttributeMaxDynamicSharedMemorySize, SMEMB2);
    cudaFuncSetAttribute(tc2_gemm<1>, cudaFuncAttributeMaxDynamicSharedMemorySize, SMEMB2);
    cudaFuncSetAttribute(tc2_gemm<2>, cudaFuncAttributeMaxDynamicSharedMemorySize, SMEMB2);
    cudaFuncSetAttribute(tc2_gemm<3>, cudaFuncAttributeMaxDynamicSharedMemorySize, SMEMB2);

    dim3 tb8(32, 8);

    split_x_kernel<<<NT*DMODEL/4/256, 256>>>((const float4*)x, xh, xl, xf);
    wsplit_hf<<<dim3(1024/32,  512/32), tb8>>>(rg1_w, 1024,  512, wfh+F_RG1, wfl+F_RG1);
    wsplit_hf<<<dim3(1024/32,  512/32), tb8>>>(imp1_w,1024,  512, wfh+F_IMP, wfl+F_IMP);
    wsplit_hf<<<dim3( 128/32, 1024/32), tb8>>>(fwm_w,  128, 1024, wfh+F_FWM, wfl+F_FWM);
    wsplit_hf<<<dim3(2048/32, 1024/32), tb8>>>(fus_w, 2048, 1024, wfh+F_FUS, wfl+F_FUS);
    wsplit_hf<<<dim3(1152/32,  512/32), tb8>>>(wd1_w, 1152,  512, wfh+F_WD1, wfl+F_WD1);
    wsplit_bf<<<dim3(1024/32,  128/32), tb8>>>(rq_w,  1024,  128, wbh+B_RQ,  wbl+B_RQ);
    wsplit_bf<<<dim3(1024/32,  128/32), tb8>>>(twm_w, 1024,  128, wbh+B_TWM, wbl+B_TWM);
    wsplit_bf<<<dim3(1024/32,  128/32), tb8>>>(wq_w,  1024,  128, wbh+B_WQ,  wbl+B_WQ);
    biascat_kernel<<<6, 256>>>(rg1_b, imp1_b, rq_b, twm_b, wq_b, bg, b3);

    // merged gelu-hidden GEMM [rg1 | imp1]  (fp16 x2)
    tc2_gemm<1><<<dim3(8,128), 256, SMEMB2>>>(xf, 1024, nullptr,
        wfh+F_G, wfl+F_G, 1024, bg, hg, nullptr, nullptr, nullptr, 1024);
    rowdot_kernel<<<NT/8, 256>>>(hg,       1024, rg2_w,  rg2_b,  wt, 0, out + O_GATE);
    rowdot_kernel<<<NT/8, 256>>>(hg + 512, 1024, imp2_w, imp2_b, wt, 1, implog);
    impsum_kernel<<<BATCH, 1024>>>(implog, wt, impsum);

    // merged q3 GEMM [query | xslot | wq]  (bf16 x3 — argmax-critical)
    tc3_gemm<<<dim3(3,128), 256, SMEMB3>>>(xh, xl, wbh, wbl, 1024, b3, q3, 384);

    attn_kernel<<<NT/8, 256>>>(q3, wm, out + O_ATTN, ctxf, wsc, wmf);
    tc2_gemm<2><<<dim3(8,128), 256, SMEMB2>>>(ctxf, 128, nullptr,
        wfh+F_FWM, wfl+F_FWM, 128, fwm_b, nullptr, conf, nullptr, nullptr, 1024);
    // fusion GEMM with fused enhance epilogue -> x_enhanced directly
    tc2_gemm<3><<<dim3(8,128), 256, SMEMB2>>>(xf, 1024, conf,
        wfh+F_FUS, wfl+F_FUS, 2048, fus_b, out + O_XENH, nullptr, x, out + O_GATE, 1024);

    pressure_kernel<<<BATCH*NSLOT, 256>>>(out + O_ATTN, rp);
    freshness_kernel<<<1, BATCH*NSLOT>>>(rp, wm, nf);

    tc2_gemm<1><<<dim3(4,128), 256, SMEMB2>>>(xf, 1024, wmf,
        wfh+F_WD1, wfl+F_WD1, 1152, wd1_b, h1, nullptr, nullptr, nullptr, 512);
    rowdot_kernel<<<NT/8, 256>>>(h1, 512, wd2_w, wd2_b, wt, 2, out + O_WG);

    slotsel_kernel<<<NT/256, 256>>>(wsc, nf, implog, impsum, out + O_WG, wt,
                                    out + O_SEL, selidx, wwbuf);
    slotagg1_kernel<<<BATCH*NSLOT*NSEG, 128>>>(selidx, wwbuf, q3 + 128, pacc, pst);
    slotagg2_kernel<<<BATCH*NSLOT, DSLOT>>>(pacc, pst, wm, nf, out + O_WM);
}

// round 16
// speedup vs baseline: 5.4772x; 1.3205x over previous
#include <cuda_runtime.h>
#include <cuda_bf16.h>
#include <cuda_fp16.h>
#include <math.h>
#include <stdint.h>

#define BATCH   4
#define SEQ     4096
#define NT      (BATCH*SEQ)
#define DMODEL  1024
#define DSLOT   128
#define NSLOT   8
#define HID     512
#define SCALE   (0.08838834764831845f)
#define FRESH_THR 0.1f
#define READ_DECAY 0.3f

#define O_XENH  ((size_t)0)
#define O_WM    ((size_t)16777216)
#define O_GATE  ((size_t)16781344)
#define O_WG    ((size_t)16797728)
#define O_ATTN  ((size_t)16814112)
#define O_SEL   ((size_t)16945184)

// ---------------- scratch ----------------
__device__ float g_h1[NT*HID];
__device__ float g_hg[NT*1024];
__device__ float g_q3[NT*384];
__device__ float g_implogit[NT];
__device__ float g_impsum[BATCH];
__device__ float g_wsc[NT*NSLOT];
__device__ float g_nf[BATCH*NSLOT];
__device__ float g_rp[BATCH*NSLOT];
__device__ int   g_sel[NT];
__device__ float g_ww[NT];
__device__ float g_bg[1024];
__device__ float g_b3[384];
__device__ float g_pacc[256*128];
__device__ float g_pst[256];

__device__ __nv_bfloat16 g_xh[NT*DMODEL], g_xl[NT*DMODEL];
__device__ __half g_xf[NT*DMODEL];
__device__ __half g_ctxf[NT*DSLOT];
__device__ __half g_conf[NT*DMODEL];
__device__ __half g_wmf[NT*DSLOT];

#define WB_TOTAL 393216
__device__ __nv_bfloat16 g_wbh[WB_TOTAL], g_wbl[WB_TOTAL];
#define B_RQ  0
#define B_TWM 131072
#define B_WQ  262144

#define WF_TOTAL 3866624
__device__ __half g_wfh[WF_TOTAL];
#define F_G   0
#define F_RG1 (F_G)
#define F_IMP (F_G + 524288)
#define F_FWM 1048576
#define F_FUS 1179648
#define F_WD1 3276800

__device__ __forceinline__ float gelu_exact(float v) {
    return 0.5f * v * (1.0f + erff(v * 0.70710678118654752f));
}

// ---------------- asm helpers ----------------
__device__ __forceinline__ uint32_t smem_u32(const void* p) {
    uint32_t a;
    asm("{ .reg .u64 t; cvta.to.shared.u64 t, %1; cvt.u32.u64 %0, t; }" : "=r"(a) : "l"(p));
    return a;
}
__device__ __forceinline__ void cpa16(uint32_t s, const void* g) {
    asm volatile("cp.async.cg.shared.global [%0], [%1], 16;\n" :: "r"(s), "l"(g));
}
__device__ __forceinline__ void cp_commit() { asm volatile("cp.async.commit_group;\n" ::); }

__device__ __forceinline__ void mma_bf16(float* c, uint32_t a0, uint32_t a1, uint32_t a2,
                                         uint32_t a3, uint32_t b0, uint32_t b1) {
    asm volatile(
        "mma.sync.aligned.m16n8k16.row.col.f32.bf16.bf16.f32 "
        "{%0,%1,%2,%3},{%4,%5,%6,%7},{%8,%9},{%0,%1,%2,%3};"
        : "+f"(c[0]), "+f"(c[1]), "+f"(c[2]), "+f"(c[3])
        : "r"(a0), "r"(a1), "r"(a2), "r"(a3), "r"(b0), "r"(b1));
}
__device__ __forceinline__ void mma_f16(float* c, uint32_t a0, uint32_t a1, uint32_t a2,
                                        uint32_t a3, uint32_t b0, uint32_t b1) {
    asm volatile(
        "mma.sync.aligned.m16n8k16.row.col.f32.f16.f16.f32 "
        "{%0,%1,%2,%3},{%4,%5,%6,%7},{%8,%9},{%0,%1,%2,%3};"
        : "+f"(c[0]), "+f"(c[1]), "+f"(c[2]), "+f"(c[3])
        : "r"(a0), "r"(a1), "r"(a2), "r"(a3), "r"(b0), "r"(b1));
}
#define LDSM4(r, addr) \
    asm volatile("ldmatrix.sync.aligned.m8n8.x4.shared.b16 {%0,%1,%2,%3}, [%4];" \
        : "=r"((r)[0]), "=r"((r)[1]), "=r"((r)[2]), "=r"((r)[3]) : "r"(addr))

#define SROW   80
#define TILEB  10240

// ---------------- bf16x3 GEMM (q3 path): 2-stage, 2 CTA/SM ----------------
#define STAGEB3 40960
#define SMEMB3  81920

__global__ void __launch_bounds__(256, 2) tc3_gemm(
    const __nv_bfloat16* __restrict__ Ah, const __nv_bfloat16* __restrict__ Al,
    const __nv_bfloat16* __restrict__ Wh, const __nv_bfloat16* __restrict__ Wl, int Ktot,
    const float* __restrict__ bias, float* __restrict__ Cf, int N)
{
    extern __shared__ __align__(16) char smem[];
    const uint32_t sb = smem_u32(smem);
    const int tid = threadIdx.x, wid = tid >> 5, lane = tid & 31;
    const int g = lane >> 2, tg = lane & 3;
    const int m0 = blockIdx.y * 128, bn = blockIdx.x * 128;
    const int wm = (wid & 1) * 64, wn = (wid >> 1) * 32;

    float acc[4][4][4] = {};
    const int nchunk = Ktot / 32;

    auto load_chunk = [&](int ci, int buf) {
        int k0 = ci * 32;
        uint32_t base = sb + buf * STAGEB3;
        #pragma unroll
        for (int u = tid; u < 512; u += 256) {
            int r = u >> 2, c = (u & 3) * 8;
            uint32_t o = (uint32_t)(r * SROW + c * 2);
            size_t gi = (size_t)(m0 + r) * Ktot + k0 + c;
            cpa16(base + o, Ah + gi);
            cpa16(base + TILEB + o, Al + gi);
        }
        #pragma unroll
        for (int u = tid; u < 512; u += 256) {
            int r = u >> 2, c = (u & 3) * 8;
            uint32_t o = (uint32_t)(r * SROW + c * 2);
            size_t gi = (size_t)(bn + r) * Ktot + k0 + c;
            cpa16(base + 2 * TILEB + o, Wh + gi);
            cpa16(base + 3 * TILEB + o, Wl + gi);
        }
        cp_commit();
    };

    const uint32_t aoff = (uint32_t)(((lane & 7) + ((lane >> 3) & 1) * 8) * SROW
                                     + ((lane >> 4) & 1) * 16);
    const uint32_t boff = (uint32_t)(((lane & 7) + ((lane >> 4) & 1) * 8) * SROW
                                     + ((lane >> 3) & 1) * 16);

    load_chunk(0, 0);

    for (int ci = 0; ci < nchunk; ++ci) {
        if (ci + 1 < nchunk) {
            load_chunk(ci + 1, (ci + 1) & 1);
            asm volatile("cp.async.wait_group 1;" ::: "memory");
        } else {
            asm volatile("cp.async.wait_group 0;" ::: "memory");
        }
        __syncthreads();

        uint32_t st = sb + (ci & 1) * STAGEB3;
        uint32_t sAh = st, sAl = st + TILEB, sBh = st + 2 * TILEB, sBl = st + 3 * TILEB;

        #pragma unroll
        for (int ks = 0; ks < 2; ++ks) {
            uint32_t ka = (uint32_t)(ks * 32);
            uint32_t ah[4][4], bh[2][4], bl[2][4];
            uint32_t abase = (uint32_t)(wm * SROW) + aoff + ka;
            #pragma unroll
            for (int mi = 0; mi < 4; ++mi)
                LDSM4(ah[mi], sAh + abase + mi * 16 * SROW);
            uint32_t bbase = (uint32_t)(wn * SROW) + boff + ka;
            #pragma unroll
            for (int np = 0; np < 2; ++np) {
                LDSM4(bh[np], sBh + bbase + np * 16 * SROW);
                LDSM4(bl[np], sBl + bbase + np * 16 * SROW);
            }
            #pragma unroll
            for (int np = 0; np < 2; ++np)
                #pragma unroll
                for (int sub = 0; sub < 2; ++sub) {
                    int ni = np * 2 + sub;
                    uint32_t h0 = bh[np][sub * 2], h1 = bh[np][sub * 2 + 1];
                    uint32_t l0 = bl[np][sub * 2], l1 = bl[np][sub * 2 + 1];
                    #pragma unroll
                    for (int mi = 0; mi < 4; ++mi) {
                        mma_bf16(acc[mi][ni], ah[mi][0], ah[mi][1], ah[mi][2], ah[mi][3], h0, h1);
                        mma_bf16(acc[mi][ni], ah[mi][0], ah[mi][1], ah[mi][2], ah[mi][3], l0, l1);
                    }
                }
            #pragma unroll
            for (int mi = 0; mi < 4; ++mi)
                LDSM4(ah[mi], sAl + abase + mi * 16 * SROW);
            #pragma unroll
            for (int np = 0; np < 2; ++np)
                #pragma unroll
                for (int sub = 0; sub < 2; ++sub) {
                    int ni = np * 2 + sub;
                    uint32_t h0 = bh[np][sub * 2], h1 = bh[np][sub * 2 + 1];
                    #pragma unroll
                    for (int mi = 0; mi < 4; ++mi)
                        mma_bf16(acc[mi][ni], ah[mi][0], ah[mi][1], ah[mi][2], ah[mi][3], h0, h1);
                }
        }
        __syncthreads();
    }

    #pragma unroll
    for (int mi = 0; mi < 4; ++mi)
        #pragma unroll
        for (int ni = 0; ni < 4; ++ni) {
            int row = m0 + wm + mi * 16 + g;
            int col = bn + wn + ni * 8 + tg * 2;
            float b0 = bias[col], b1 = bias[col + 1];
            #pragma unroll
            for (int h = 0; h < 2; ++h) {
                int r = row + h * 8;
                float2 o;
                o.x = acc[mi][ni][h * 2]     + b0;
                o.y = acc[mi][ni][h * 2 + 1] + b1;
                *(float2*)&Cf[(size_t)r * N + col] = o;
            }
        }
}

// ---------------- fp16 single-product GEMM: 3-stage, 2 CTA/SM ----------------
#define STAGEB1 20480
#define NST1    3
#define SMEMB1  (NST1*STAGEB1)

// MODE 0: f32 out, 1: f32 gelu, 2: f16 out, 3: enhance out=(1-g)x+g(acc+b)
template<int MODE>
__global__ void __launch_bounds__(256, 2) tc1_gemm(
    const __half* __restrict__ A1, int K1,
    const __half* __restrict__ A2,
    const __half* __restrict__ W, int Ktot,
    const float* __restrict__ bias,
    float* __restrict__ Cf, __half* __restrict__ Ch,
    const float* __restrict__ Xf, const float* __restrict__ gate,
    int N)
{
    extern __shared__ __align__(16) char smem[];
    const uint32_t sb = smem_u32(smem);
    const int tid = threadIdx.x, wid = tid >> 5, lane = tid & 31;
    const int g = lane >> 2, tg = lane & 3;
    const int m0 = blockIdx.y * 128, bn = blockIdx.x * 128;
    const int wm = (wid & 1) * 64, wn = (wid >> 1) * 32;

    float acc[4][4][4] = {};
    const int nchunk = Ktot / 32;

    auto load_chunk = [&](int ci, int buf) {
        int k0 = ci * 32;
        const __half* A; int sA, kA;
        if (k0 < K1) { A = A1; sA = K1; kA = k0; }
        else         { A = A2; sA = Ktot - K1; kA = k0 - K1; }
        uint32_t base = sb + buf * STAGEB1;
        #pragma unroll
        for (int u = tid; u < 512; u += 256) {
            int r = u >> 2, c = (u & 3) * 8;
            uint32_t o = (uint32_t)(r * SROW + c * 2);
            cpa16(base + o, A + (size_t)(m0 + r) * sA + kA + c);
        }
        #pragma unroll
        for (int u = tid; u < 512; u += 256) {
            int r = u >> 2, c = (u & 3) * 8;
            uint32_t o = (uint32_t)(r * SROW + c * 2);
            cpa16(base + TILEB + o, W + (size_t)(bn + r) * Ktot + k0 + c);
        }
        cp_commit();
    };

    const uint32_t aoff = (uint32_t)(((lane & 7) + ((lane >> 3) & 1) * 8) * SROW
                                     + ((lane >> 4) & 1) * 16);
    const uint32_t boff = (uint32_t)(((lane & 7) + ((lane >> 4) & 1) * 8) * SROW
                                     + ((lane >> 3) & 1) * 16);

    load_chunk(0, 0);
    if (nchunk > 1) load_chunk(1, 1);

    for (int ci = 0; ci < nchunk; ++ci) {
        if (ci + 2 < nchunk) {
            load_chunk(ci + 2, (ci + 2) % NST1);
            asm volatile("cp.async.wait_group 2;" ::: "memory");
        } else if (ci + 1 < nchunk) {
            asm volatile("cp.async.wait_group 1;" ::: "memory");
        } else {
            asm volatile("cp.async.wait_group 0;" ::: "memory");
        }
        __syncthreads();

        uint32_t st = sb + (ci % NST1) * STAGEB1;
        uint32_t sA = st, sB = st + TILEB;

        #pragma unroll
        for (int ks = 0; ks < 2; ++ks) {
            uint32_t ka = (uint32_t)(ks * 32);
            uint32_t ah[4][4], bh[2][4];
            uint32_t abase = (uint32_t)(wm * SROW) + aoff + ka;
            #pragma unroll
            for (int mi = 0; mi < 4; ++mi)
                LDSM4(ah[mi], sA + abase + mi * 16 * SROW);
            uint32_t bbase = (uint32_t)(wn * SROW) + boff + ka;
            #pragma unroll
            for (int np = 0; np < 2; ++np)
                LDSM4(bh[np], sB + bbase + np * 16 * SROW);
            #pragma unroll
            for (int np = 0; np < 2; ++np)
                #pragma unroll
                for (int sub = 0; sub < 2; ++sub) {
                    int ni = np * 2 + sub;
                    uint32_t h0 = bh[np][sub * 2], h1 = bh[np][sub * 2 + 1];
                    #pragma unroll
                    for (int mi = 0; mi < 4; ++mi)
                        mma_f16(acc[mi][ni], ah[mi][0], ah[mi][1], ah[mi][2], ah[mi][3], h0, h1);
                }
        }
        __syncthreads();
    }

    #pragma unroll
    for (int mi = 0; mi < 4; ++mi)
        #pragma unroll
        for (int ni = 0; ni < 4; ++ni) {
            int row = m0 + wm + mi * 16 + g;
            int col = bn + wn + ni * 8 + tg * 2;
            float b0 = bias[col], b1 = bias[col + 1];
            #pragma unroll
            for (int h = 0; h < 2; ++h) {
                int r = row + h * 8;
                float v0 = acc[mi][ni][h * 2]     + b0;
                float v1 = acc[mi][ni][h * 2 + 1] + b1;
                if (MODE == 1) { v0 = gelu_exact(v0); v1 = gelu_exact(v1); }
                if (MODE == 2) {
                    __half2 hp; hp.x = __float2half(v0); hp.y = __float2half(v1);
                    *(__half2*)&Ch[(size_t)r * N + col] = hp;
                } else if (MODE == 3) {
                    float gv = gate[r];
                    float2 xv = *(const float2*)&Xf[(size_t)r * N + col];
                    float2 o;
                    o.x = (1.f - gv) * xv.x + gv * v0;
                    o.y = (1.f - gv) * xv.y + gv * v1;
                    *(float2*)&Cf[(size_t)r * N + col] = o;
                } else {
                    float2 o; o.x = v0; o.y = v1;
                    *(float2*)&Cf[(size_t)r * N + col] = o;
                }
            }
        }
}

// ---------------- split x -> bf16 hi/lo + fp16 ----------------
__global__ void split_x_kernel(const float4* __restrict__ x,
                               __nv_bfloat16* __restrict__ h, __nv_bfloat16* __restrict__ l,
                               __half* __restrict__ f)
{
    size_t i = (size_t)blockIdx.x * 256 + threadIdx.x;
    float4 v = x[i];
    float a[4] = {v.x, v.y, v.z, v.w};
    __nv_bfloat16 hh[4];
    #pragma unroll
    for (int c = 0; c < 4; ++c) hh[c] = __float2bfloat16(a[c]);
    __nv_bfloat162 hp0, hp1, lp0, lp1;
    hp0.x = hh[0]; hp0.y = hh[1]; hp1.x = hh[2]; hp1.y = hh[3];
    lp0.x = __float2bfloat16(a[0] - __bfloat162float(hh[0]));
    lp0.y = __float2bfloat16(a[1] - __bfloat162float(hh[1]));
    lp1.x = __float2bfloat16(a[2] - __bfloat162float(hh[2]));
    lp1.y = __float2bfloat16(a[3] - __bfloat162float(hh[3]));
    *(__nv_bfloat162*)&h[i * 4]     = hp0;
    *(__nv_bfloat162*)&h[i * 4 + 2] = hp1;
    *(__nv_bfloat162*)&l[i * 4]     = lp0;
    *(__nv_bfloat162*)&l[i * 4 + 2] = lp1;
    __half2 f0, f1;
    f0.x = __float2half(a[0]); f0.y = __float2half(a[1]);
    f1.x = __float2half(a[2]); f1.y = __float2half(a[3]);
    *(__half2*)&f[i * 4]     = f0;
    *(__half2*)&f[i * 4 + 2] = f1;
}

// ---------------- weight transpose: bf16 hi/lo split  /  fp16 convert ----------------
__global__ void wsplit_bf(const float* __restrict__ W, int K, int N,
                          __nv_bfloat16* __restrict__ Th, __nv_bfloat16* __restrict__ Tl)
{
    __shared__ float tile[32][33];
    int kb = blockIdx.x * 32, nb = blockIdx.y * 32;
    int tx = threadIdx.x, ty = threadIdx.y;
    #pragma unroll
    for (int i = 0; i < 4; ++i)
        tile[ty + i * 8][tx] = W[(size_t)(kb + ty + i * 8) * N + nb + tx];
    __syncthreads();
    #pragma unroll
    for (int i = 0; i < 4; ++i) {
        int n = nb + ty + i * 8, k = kb + tx;
        float v = tile[tx][ty + i * 8];
        size_t o = (size_t)n * K + k;
        __nv_bfloat16 h = __float2bfloat16(v);
        Th[o] = h;
        Tl[o] = __float2bfloat16(v - __bfloat162float(h));
    }
}

__global__ void wconv_hf(const float* __restrict__ W, int K, int N,
                         __half* __restrict__ Th)
{
    __shared__ float tile[32][33];
    int kb = blockIdx.x * 32, nb = blockIdx.y * 32;
    int tx = threadIdx.x, ty = threadIdx.y;
    #pragma unroll
    for (int i = 0; i < 4; ++i)
        tile[ty + i * 8][tx] = W[(size_t)(kb + ty + i * 8) * N + nb + tx];
    __syncthreads();
    #pragma unroll
    for (int i = 0; i < 4; ++i) {
        int n = nb + ty + i * 8, k = kb + tx;
        Th[(size_t)n * K + k] = __float2half(tile[tx][ty + i * 8]);
    }
}

// ---------------- bias concat ----------------
__global__ void biascat_kernel(const float* rg1_b, const float* imp1_b,
                               const float* rq_b, const float* twm_b, const float* wq_b,
                               float* bg, float* b3)
{
    int i = blockIdx.x * 256 + threadIdx.x;
    if (i < 512) bg[i] = rg1_b[i];
    else if (i < 1024) bg[i] = imp1_b[i - 512];
    else if (i < 1152) b3[i - 1024] = rq_b[i - 1024];
    else if (i < 1280) b3[i - 1024] = twm_b[i - 1152];
    else if (i < 1408) b3[i - 1024] = wq_b[i - 1280];
}

// ---------------- row-dot ----------------
__global__ void rowdot_kernel(const float* __restrict__ Hm, int stride,
                              const float* __restrict__ w, const float* __restrict__ bias,
                              const float* __restrict__ wt, int mode,
                              float* __restrict__ out)
{
    __shared__ float ws[HID];
    for (int i = threadIdx.x; i < HID; i += blockDim.x) ws[i] = w[i];
    __syncthreads();
    int warp = threadIdx.x >> 5, lane = threadIdx.x & 31;
    int row = blockIdx.x * 8 + warp;
    const float* h = Hm + (size_t)row * stride;
    float s = 0.f;
    for (int i = lane; i < HID; i += 32) s = fmaf(h[i], ws[i], s);
    #pragma unroll
    for (int o = 16; o; o >>= 1) s += __shfl_xor_sync(0xffffffffu, s, o);
    if (lane == 0) {
        float z = s + bias[0];
        if (mode == 1) out[row] = z;
        else {
            if (mode == 2) z /= fmaxf(wt[0], 0.1f);
            out[row] = 1.f / (1.f + expf(-z));
        }
    }
}

// ---------------- combined read+write attention ----------------
__global__ void attn_kernel(const float* __restrict__ q3,
                            const float* __restrict__ wm,
                            float* __restrict__ attn_out,
                            __half* __restrict__ ctxf,
                            float* __restrict__ wsc_out,
                            __half* __restrict__ wmf)
{
    __shared__ float cont[NSLOT][DSLOT];
    __shared__ float fresh[NSLOT];
    int tid = threadIdx.x;
    int tokenBase = blockIdx.x * 8;
    int b = tokenBase / SEQ;
    for (int i = tid; i < NSLOT * DSLOT; i += 256) {
        int k = i / DSLOT, d = i % DSLOT;
        cont[k][d] = wm[((size_t)b * NSLOT + k) * (DSLOT + 1) + d];
    }
    if (tid < NSLOT) fresh[tid] = wm[((size_t)b * NSLOT + tid) * (DSLOT + 1) + DSLOT];
    __syncthreads();
    int warp = tid >> 5, lane = tid & 31;
    int t = tokenBase + warp;

    {
        const float* q = q3 + (size_t)t * 384;
        float ql[4];
        #pragma unroll
        for (int i = 0; i < 4; ++i) ql[i] = q[lane + 32 * i];
        float a[NSLOT];
        #pragma unroll
        for (int k = 0; k < NSLOT; ++k) {
            float s = 0.f;
            #pragma unroll
            for (int i = 0; i < 4; ++i) s = fmaf(ql[i], cont[k][lane + 32 * i], s);
            #pragma unroll
            for (int o = 16; o; o >>= 1) s += __shfl_xor_sync(0xffffffffu, s, o);
            s *= SCALE;
            if (fresh[k] < FRESH_THR) s = -1e9f;
            a[k] = s;
        }
        float mx = a[0];
        #pragma unroll
        for (int k = 1; k < NSLOT; ++k) mx = fmaxf(mx, a[k]);
        float sum = 0.f;
        #pragma unroll
        for (int k = 0; k < NSLOT; ++k) { a[k] = expf(a[k] - mx); sum += a[k]; }
        float inv = 1.f / sum;
        #pragma unroll
        for (int k = 0; k < NSLOT; ++k) a[k] *= inv;
        if (lane == 0) {
            #pragma unroll
            for (int k = 0; k < NSLOT; ++k) attn_out[(size_t)t * NSLOT + k] = a[k];
        }
        #pragma unroll
        for (int i = 0; i < 4; ++i) {
            int d = lane + 32 * i;
            float c = 0.f;
            #pragma unroll
            for (int k = 0; k < NSLOT; ++k) c = fmaf(a[k], cont[k][d], c);
            ctxf[(size_t)t * DSLOT + d] = __float2half(c);
        }
    }
    {
        const float* q = q3 + (size_t)t * 384 + 256;
        float ql[4];
        #pragma unroll
        for (int i = 0; i < 4; ++i) ql[i] = q[lane + 32 * i];
        float a[NSLOT];
        #pragma unroll
        for (int k = 0; k < NSLOT; ++k) {
            float s = 0.f;
            #pragma unroll
            for (int i = 0; i < 4; ++i) s = fmaf(ql[i], cont[k][lane + 32 * i], s);
            #pragma unroll
            for (int o = 16; o; o >>= 1) s += __shfl_xor_sync(0xffffffffu, s, o);
            a[k] = s * SCALE;
        }
        if (lane == 0) {
            #pragma unroll
            for (int k = 0; k < NSLOT; ++k) wsc_out[(size_t)t * NSLOT + k] = a[k];
        }
        float mx = a[0];
        #pragma unroll
        for (int k = 1; k < NSLOT; ++k) mx = fmaxf(mx, a[k]);
        float sum = 0.f;
        #pragma unroll
        for (int k = 0; k < NSLOT; ++k) { a[k] = expf(a[k] - mx); sum += a[k]; }
        float inv = 1.f / sum;
        #pragma unroll
        for (int k = 0; k < NSLOT; ++k) a[k] *= inv;
        #pragma unroll
        for (int i = 0; i < 4; ++i) {
            int d = lane + 32 * i;
            float c = 0.f;
            #pragma unroll
            for (int k = 0; k < NSLOT; ++k) c = fmaf(a[k], cont[k][d], c);
            wmf[(size_t)t * DSLOT + d] = __float2half(c);
        }
    }
}

// ---------------- small reductions ----------------
__global__ void pressure_kernel(const float* __restrict__ attn, float* __restrict__ rp)
{
    int b = blockIdx.x / NSLOT, k = blockIdx.x % NSLOT;
    __shared__ float sh[256];
    float s = 0.f;
    for (int si = threadIdx.x; si < SEQ; si += 256)
        s += attn[((size_t)b * SEQ + si) * NSLOT + k];
    sh[threadIdx.x] = s;
    __syncthreads();
    for (int o = 128; o; o >>= 1) {
        if (threadIdx.x < o) sh[threadIdx.x] += sh[threadIdx.x + o];
        __syncthreads();
    }
    if (threadIdx.x == 0) rp[blockIdx.x] = sh[0];
}

__global__ void freshness_kernel(const float* __restrict__ rp, const float* __restrict__ wm,
                                 float* __restrict__ nf)
{
    int t = threadIdx.x;
    int b = t / NSLOT;
    __shared__ float s[BATCH * NSLOT];
    s[t] = rp[t];
    __syncthreads();
    float mx = 1e-8f;
    #pragma unroll
    for (int k = 0; k < NSLOT; ++k) mx = fmaxf(mx, s[b * NSLOT + k]);
    float decay = 1.f - (s[t] / mx) * (1.f - READ_DECAY);
    nf[t] = wm[(size_t)t * (DSLOT + 1) + DSLOT] * decay;
}

__global__ void impsum_kernel(const float* __restrict__ logit, const float* __restrict__ wt,
                              float* __restrict__ outsum)
{
    int b = blockIdx.x;
    float temp = fmaxf(wt[0], 0.1f);
    __shared__ float sh[1024];
    float s = 0.f;
    for (int i = threadIdx.x; i < SEQ; i += 1024)
        s += expf(logit[(size_t)b * SEQ + i] / temp);
    sh[threadIdx.x] = s;
    __syncthreads();
    for (int o = 512; o; o >>= 1) {
        if (threadIdx.x < o) sh[threadIdx.x] += sh[threadIdx.x + o];
        __syncthreads();
    }
    if (threadIdx.x == 0) outsum[b] = sh[0];
}

__global__ void slotsel_kernel(const float* __restrict__ wsc, const float* __restrict__ nf,
                               const float* __restrict__ logit, const float* __restrict__ impsum,
                               const float* __restrict__ wg, const float* __restrict__ wt,
                               float* __restrict__ sel_onehot, int* __restrict__ sel_idx,
                               float* __restrict__ ww_out)
{
    int t = blockIdx.x * 256 + threadIdx.x;
    int b = t / SEQ;
    float temp = fmaxf(wt[0], 0.1f);
    float best = wsc[(size_t)t * NSLOT] - 2.f * nf[b * NSLOT];
    int bi = 0;
    #pragma unroll
    for (int k = 1; k < NSLOT; ++k) {
        float v = wsc[(size_t)t * NSLOT + k] - 2.f * nf[b * NSLOT + k];
        if (v > best) { best = v; bi = k; }
    }
    float imp = expf(logit[t] / temp) / (impsum[b] + 1e-8f) * (float)SEQ;
    sel_idx[t] = bi;
    ww_out[t] = wg[t] * imp;
    #pragma unroll
    for (int k = 0; k < NSLOT; ++k)
        sel_onehot[(size_t)t * NSLOT + k] = (k == bi) ? 1.f : 0.f;
}

// ---------------- slot aggregation: 2-phase ----------------
#define NSEG 8
#define SEGLEN (SEQ/NSEG)
__global__ void slotagg1_kernel(const int* __restrict__ sel, const float* __restrict__ ww,
                                const float* __restrict__ xslot,
                                float* __restrict__ pacc, float* __restrict__ pst)
{
    int blk = blockIdx.x;
    int bk = blk / NSEG, seg = blk % NSEG;
    int b = bk / NSLOT, k = bk % NSLOT;
    int d = threadIdx.x;
    float acc = 0.f, st = 0.f;
    const int s0 = b * SEQ + seg * SEGLEN;
    for (int si = 0; si < SEGLEN; ++si) {
        int tt = s0 + si;
        if (sel[tt] == k) {
            float w = ww[tt];
            st += w;
            acc = fmaf(w, xslot[(size_t)tt * 384 + d], acc);
        }
    }
    pacc[(size_t)blk * 128 + d] = acc;
    if (d == 0) pst[blk] = st;
}

__global__ void slotagg2_kernel(const float* __restrict__ pacc, const float* __restrict__ pst,
                                const float* __restrict__ wm, const float* __restrict__ nf,
                                float* __restrict__ wm_out)
{
    int bk = blockIdx.x;
    int d = threadIdx.x;
    float acc = 0.f, st = 0.f;
    #pragma unroll
    for (int s = 0; s < NSEG; ++s) {
        acc += pacc[(size_t)(bk * NSEG + s) * 128 + d];
        st  += pst[bk * NSEG + s];
    }
    float nc = acc / fmaxf(st, 1e-8f);
    float has = (st > 0.1f) ? 1.f : 0.f;
    float cont = wm[(size_t)bk * (DSLOT + 1) + d];
    wm_out[(size_t)bk * (DSLOT + 1) + d] = has * nc + (1.f - has) * cont;
    if (d == 0)
        wm_out[(size_t)bk * (DSLOT + 1) + DSLOT] = has * 1.f + (1.f - has) * nf[bk];
}

// ---------------- host ----------------
static void* symv(const void* s) { void* p = nullptr; cudaGetSymbolAddress(&p, s); return p; }

extern "C" void kernel_launch(void* const* d_in, const int* in_sizes, int n_in,
                              void* d_out, int out_size)
{
    const float* x      = (const float*)d_in[0];
    const float* wm     = (const float*)d_in[1];
    const float* rq_w   = (const float*)d_in[2];
    const float* rq_b   = (const float*)d_in[3];
    const float* fwm_w  = (const float*)d_in[4];
    const float* fwm_b  = (const float*)d_in[5];
    const float* rg1_w  = (const float*)d_in[6];
    const float* rg1_b  = (const float*)d_in[7];
    const float* rg2_w  = (const float*)d_in[8];
    const float* rg2_b  = (const float*)d_in[9];
    const float* fus_w  = (const float*)d_in[10];
    const float* fus_b  = (const float*)d_in[11];
    const float* twm_w  = (const float*)d_in[12];
    const float* twm_b  = (const float*)d_in[13];
    const float* wq_w   = (const float*)d_in[14];
    const float* wq_b   = (const float*)d_in[15];
    const float* imp1_w = (const float*)d_in[16];
    const float* imp1_b = (const float*)d_in[17];
    const float* imp2_w = (const float*)d_in[18];
    const float* imp2_b = (const float*)d_in[19];
    const float* wd1_w  = (const float*)d_in[20];
    const float* wd1_b  = (const float*)d_in[21];
    const float* wd2_w  = (const float*)d_in[22];
    const float* wd2_b  = (const float*)d_in[23];
    const float* wt     = (const float*)d_in[24];

    float* out = (float*)d_out;
    float* h1     = (float*)symv(g_h1);
    float* hg     = (float*)symv(g_hg);
    float* q3     = (float*)symv(g_q3);
    float* implog = (float*)symv(g_implogit);
    float* impsum = (float*)symv(g_impsum);
    float* wsc    = (float*)symv(g_wsc);
    float* nf     = (float*)symv(g_nf);
    float* rp     = (float*)symv(g_rp);
    int*   selidx = (int*)symv(g_sel);
    float* wwbuf  = (float*)symv(g_ww);
    float* bg     = (float*)symv(g_bg);
    float* b3     = (float*)symv(g_b3);
    float* pacc   = (float*)symv(g_pacc);
    float* pst    = (float*)symv(g_pst);
    __nv_bfloat16* xh  = (__nv_bfloat16*)symv(g_xh);
    __nv_bfloat16* xl  = (__nv_bfloat16*)symv(g_xl);
    __nv_bfloat16* wbh = (__nv_bfloat16*)symv(g_wbh);
    __nv_bfloat16* wbl = (__nv_bfloat16*)symv(g_wbl);
    __half* xf   = (__half*)symv(g_xf);
    __half* ctxf = (__half*)symv(g_ctxf);
    __half* conf = (__half*)symv(g_conf);
    __half* wmf  = (__half*)symv(g_wmf);
    __half* wfh  = (__half*)symv(g_wfh);

    cudaFuncSetAttribute(tc3_gemm,    cudaFuncAttributeMaxDynamicSharedMemorySize, SMEMB3);
    cudaFuncSetAttribute(tc1_gemm<0>, cudaFuncAttributeMaxDynamicSharedMemorySize, SMEMB1);
    cudaFuncSetAttribute(tc1_gemm<1>, cudaFuncAttributeMaxDynamicSharedMemorySize, SMEMB1);
    cudaFuncSetAttribute(tc1_gemm<2>, cudaFuncAttributeMaxDynamicSharedMemorySize, SMEMB1);
    cudaFuncSetAttribute(tc1_gemm<3>, cudaFuncAttributeMaxDynamicSharedMemorySize, SMEMB1);

    dim3 tb8(32, 8);

    split_x_kernel<<<NT*DMODEL/4/256, 256>>>((const float4*)x, xh, xl, xf);
    wconv_hf<<<dim3(1024/32,  512/32), tb8>>>(rg1_w, 1024,  512, wfh+F_RG1);
    wconv_hf<<<dim3(1024/32,  512/32), tb8>>>(imp1_w,1024,  512, wfh+F_IMP);
    wconv_hf<<<dim3( 128/32, 1024/32), tb8>>>(fwm_w,  128, 1024, wfh+F_FWM);
    wconv_hf<<<dim3(2048/32, 1024/32), tb8>>>(fus_w, 2048, 1024, wfh+F_FUS);
    wconv_hf<<<dim3(1152/32,  512/32), tb8>>>(wd1_w, 1152,  512, wfh+F_WD1);
    wsplit_bf<<<dim3(1024/32,  128/32), tb8>>>(rq_w,  1024,  128, wbh+B_RQ,  wbl+B_RQ);
    wsplit_bf<<<dim3(1024/32,  128/32), tb8>>>(twm_w, 1024,  128, wbh+B_TWM, wbl+B_TWM);
    wsplit_bf<<<dim3(1024/32,  128/32), tb8>>>(wq_w,  1024,  128, wbh+B_WQ,  wbl+B_WQ);
    biascat_kernel<<<6, 256>>>(rg1_b, imp1_b, rq_b, twm_b, wq_b, bg, b3);

    // merged gelu-hidden GEMM [rg1 | imp1]  (fp16 single-product)
    tc1_gemm<1><<<dim3(8,128), 256, SMEMB1>>>(xf, 1024, nullptr,
        wfh+F_G, 1024, bg, hg, nullptr, nullptr, nullptr, 1024);
    rowdot_kernel<<<NT/8, 256>>>(hg,       1024, rg2_w,  rg2_b,  wt, 0, out + O_GATE);
    rowdot_kernel<<<NT/8, 256>>>(hg + 512, 1024, imp2_w, imp2_b, wt, 1, implog);
    impsum_kernel<<<BATCH, 1024>>>(implog, wt, impsum);

    // merged q3 GEMM [query | xslot | wq]  (bf16 x3 — argmax-critical)
    tc3_gemm<<<dim3(3,128), 256, SMEMB3>>>(xh, xl, wbh, wbl, 1024, b3, q3, 384);

    attn_kernel<<<NT/8, 256>>>(q3, wm, out + O_ATTN, ctxf, wsc, wmf);
    tc1_gemm<2><<<dim3(8,128), 256, SMEMB1>>>(ctxf, 128, nullptr,
        wfh+F_FWM, 128, fwm_b, nullptr, conf, nullptr, nullptr, 1024);
    // fusion GEMM with fused enhance epilogue -> x_enhanced directly
    tc1_gemm<3><<<dim3(8,128), 256, SMEMB1>>>(xf, 1024, conf,
        wfh+F_FUS, 2048, fus_b, out + O_XENH, nullptr, x, out + O_GATE, 1024);

    pressure_kernel<<<BATCH*NSLOT, 256>>>(out + O_ATTN, rp);
    freshness_kernel<<<1, BATCH*NSLOT>>>(rp, wm, nf);

    tc1_gemm<1><<<dim3(4,128), 256, SMEMB1>>>(xf, 1024, wmf,
        wfh+F_WD1, 1152, wd1_b, h1, nullptr, nullptr, nullptr, 512);
    rowdot_kernel<<<NT/8, 256>>>(h1, 512, wd2_w, wd2_b, wt, 2, out + O_WG);

    slotsel_kernel<<<NT/256, 256>>>(wsc, nf, implog, impsum, out + O_WG, wt,
                                    out + O_SEL, selidx, wwbuf);
    slotagg1_kernel<<<BATCH*NSLOT*NSEG, 128>>>(selidx, wwbuf, q3 + 128, pacc, pst);
    slotagg2_kernel<<<BATCH*NSLOT, DSLOT>>>(pacc, pst, wm, nf, out + O_WM);
}

// round 17
// speedup vs baseline: 5.8130x; 1.0613x over previous
#include <cuda_runtime.h>
#include <cuda_bf16.h>
#include <cuda_fp16.h>
#include <math.h>
#include <stdint.h>

#define BATCH   4
#define SEQ     4096
#define NT      (BATCH*SEQ)
#define DMODEL  1024
#define DSLOT   128
#define NSLOT   8
#define HID     512
#define SCALE   (0.08838834764831845f)
#define FRESH_THR 0.1f
#define READ_DECAY 0.3f

#define O_XENH  ((size_t)0)
#define O_WM    ((size_t)16777216)
#define O_GATE  ((size_t)16781344)
#define O_WG    ((size_t)16797728)
#define O_ATTN  ((size_t)16814112)
#define O_SEL   ((size_t)16945184)

// ---------------- scratch ----------------
__device__ __half g_h1h[NT*HID];
__device__ __half g_hgh[NT*1024];
__device__ float g_q3[NT*384];
__device__ float g_implogit[NT];
__device__ float g_impsum[BATCH];
__device__ float g_wsc[NT*NSLOT];
__device__ float g_nf[BATCH*NSLOT];
__device__ float g_rp[BATCH*NSLOT];
__device__ int   g_sel[NT];
__device__ float g_ww[NT];
__device__ float g_bg[1024];
__device__ float g_b3[384];
__device__ float g_pacc[256*128];
__device__ float g_pst[256];

__device__ __nv_bfloat16 g_xh[NT*DMODEL], g_xl[NT*DMODEL];
__device__ __half g_xf[NT*DMODEL];
__device__ __half g_ctxf[NT*DSLOT];
__device__ __half g_conf[NT*DMODEL];
__device__ __half g_wmf[NT*DSLOT];

#define WB_TOTAL 393216
__device__ __nv_bfloat16 g_wbh[WB_TOTAL], g_wbl[WB_TOTAL];

#define WF_TOTAL 3866624
__device__ __half g_wfh[WF_TOTAL];
#define F_G   0
#define F_FWM 1048576
#define F_FUS 1179648
#define F_WD1 3276800

__device__ __forceinline__ float gelu_exact(float v) {
    return 0.5f * v * (1.0f + erff(v * 0.70710678118654752f));
}

// ---------------- asm helpers ----------------
__device__ __forceinline__ uint32_t smem_u32(const void* p) {
    uint32_t a;
    asm("{ .reg .u64 t; cvta.to.shared.u64 t, %1; cvt.u32.u64 %0, t; }" : "=r"(a) : "l"(p));
    return a;
}
__device__ __forceinline__ void cpa16(uint32_t s, const void* g) {
    asm volatile("cp.async.cg.shared.global [%0], [%1], 16;\n" :: "r"(s), "l"(g));
}
__device__ __forceinline__ void cp_commit() { asm volatile("cp.async.commit_group;\n" ::); }

__device__ __forceinline__ void mma_bf16(float* c, uint32_t a0, uint32_t a1, uint32_t a2,
                                         uint32_t a3, uint32_t b0, uint32_t b1) {
    asm volatile(
        "mma.sync.aligned.m16n8k16.row.col.f32.bf16.bf16.f32 "
        "{%0,%1,%2,%3},{%4,%5,%6,%7},{%8,%9},{%0,%1,%2,%3};"
        : "+f"(c[0]), "+f"(c[1]), "+f"(c[2]), "+f"(c[3])
        : "r"(a0), "r"(a1), "r"(a2), "r"(a3), "r"(b0), "r"(b1));
}
__device__ __forceinline__ void mma_f16(float* c, uint32_t a0, uint32_t a1, uint32_t a2,
                                        uint32_t a3, uint32_t b0, uint32_t b1) {
    asm volatile(
        "mma.sync.aligned.m16n8k16.row.col.f32.f16.f16.f32 "
        "{%0,%1,%2,%3},{%4,%5,%6,%7},{%8,%9},{%0,%1,%2,%3};"
        : "+f"(c[0]), "+f"(c[1]), "+f"(c[2]), "+f"(c[3])
        : "r"(a0), "r"(a1), "r"(a2), "r"(a3), "r"(b0), "r"(b1));
}
#define LDSM4(r, addr) \
    asm volatile("ldmatrix.sync.aligned.m8n8.x4.shared.b16 {%0,%1,%2,%3}, [%4];" \
        : "=r"((r)[0]), "=r"((r)[1]), "=r"((r)[2]), "=r"((r)[3]) : "r"(addr))

#define SROW   80
#define TILEB  10240

// ---------------- bf16x3 GEMM (q3 path): 2-stage, 2 CTA/SM, 1 sync/iter ----------------
#define STAGEB3 40960
#define SMEMB3  81920

__global__ void __launch_bounds__(256, 2) tc3_gemm(
    const __nv_bfloat16* __restrict__ Ah, const __nv_bfloat16* __restrict__ Al,
    const __nv_bfloat16* __restrict__ Wh, const __nv_bfloat16* __restrict__ Wl, int Ktot,
    const float* __restrict__ bias, float* __restrict__ Cf, int N)
{
    extern __shared__ __align__(16) char smem[];
    const uint32_t sb = smem_u32(smem);
    const int tid = threadIdx.x, wid = tid >> 5, lane = tid & 31;
    const int g = lane >> 2, tg = lane & 3;
    const int m0 = blockIdx.y * 128, bn = blockIdx.x * 128;
    const int wm = (wid & 1) * 64, wn = (wid >> 1) * 32;

    float acc[4][4][4] = {};
    const int nchunk = Ktot / 32;

    auto load_chunk = [&](int ci, int buf) {
        int k0 = ci * 32;
        uint32_t base = sb + buf * STAGEB3;
        #pragma unroll
        for (int u = tid; u < 512; u += 256) {
            int r = u >> 2, c = (u & 3) * 8;
            uint32_t o = (uint32_t)(r * SROW + c * 2);
            size_t gi = (size_t)(m0 + r) * Ktot + k0 + c;
            cpa16(base + o, Ah + gi);
            cpa16(base + TILEB + o, Al + gi);
        }
        #pragma unroll
        for (int u = tid; u < 512; u += 256) {
            int r = u >> 2, c = (u & 3) * 8;
            uint32_t o = (uint32_t)(r * SROW + c * 2);
            size_t gi = (size_t)(bn + r) * Ktot + k0 + c;
            cpa16(base + 2 * TILEB + o, Wh + gi);
            cpa16(base + 3 * TILEB + o, Wl + gi);
        }
        cp_commit();
    };

    const uint32_t aoff = (uint32_t)(((lane & 7) + ((lane >> 3) & 1) * 8) * SROW
                                     + ((lane >> 4) & 1) * 16);
    const uint32_t boff = (uint32_t)(((lane & 7) + ((lane >> 4) & 1) * 8) * SROW
                                     + ((lane >> 3) & 1) * 16);

    load_chunk(0, 0);

    for (int ci = 0; ci < nchunk; ++ci) {
        asm volatile("cp.async.wait_group 0;" ::: "memory");
        __syncthreads();
        if (ci + 1 < nchunk) load_chunk(ci + 1, (ci + 1) & 1);

        uint32_t st = sb + (ci & 1) * STAGEB3;
        uint32_t sAh = st, sAl = st + TILEB, sBh = st + 2 * TILEB, sBl = st + 3 * TILEB;

        #pragma unroll
        for (int ks = 0; ks < 2; ++ks) {
            uint32_t ka = (uint32_t)(ks * 32);
            uint32_t ah[4][4], bh[2][4], bl[2][4];
            uint32_t abase = (uint32_t)(wm * SROW) + aoff + ka;
            #pragma unroll
            for (int mi = 0; mi < 4; ++mi)
                LDSM4(ah[mi], sAh + abase + mi * 16 * SROW);
            uint32_t bbase = (uint32_t)(wn * SROW) + boff + ka;
            #pragma unroll
            for (int np = 0; np < 2; ++np) {
                LDSM4(bh[np], sBh + bbase + np * 16 * SROW);
                LDSM4(bl[np], sBl + bbase + np * 16 * SROW);
            }
            #pragma unroll
            for (int np = 0; np < 2; ++np)
                #pragma unroll
                for (int sub = 0; sub < 2; ++sub) {
                    int ni = np * 2 + sub;
                    uint32_t h0 = bh[np][sub * 2], h1 = bh[np][sub * 2 + 1];
                    uint32_t l0 = bl[np][sub * 2], l1 = bl[np][sub * 2 + 1];
                    #pragma unroll
                    for (int mi = 0; mi < 4; ++mi) {
                        mma_bf16(acc[mi][ni], ah[mi][0], ah[mi][1], ah[mi][2], ah[mi][3], h0, h1);
                        mma_bf16(acc[mi][ni], ah[mi][0], ah[mi][1], ah[mi][2], ah[mi][3], l0, l1);
                    }
                }
            #pragma unroll
            for (int mi = 0; mi < 4; ++mi)
                LDSM4(ah[mi], sAl + abase + mi * 16 * SROW);
            #pragma unroll
            for (int np = 0; np < 2; ++np)
                #pragma unroll
                for (int sub = 0; sub < 2; ++sub) {
                    int ni = np * 2 + sub;
                    uint32_t h0 = bh[np][sub * 2], h1 = bh[np][sub * 2 + 1];
                    #pragma unroll
                    for (int mi = 0; mi < 4; ++mi)
                        mma_bf16(acc[mi][ni], ah[mi][0], ah[mi][1], ah[mi][2], ah[mi][3], h0, h1);
                }
        }
    }

    #pragma unroll
    for (int mi = 0; mi < 4; ++mi)
        #pragma unroll
        for (int ni = 0; ni < 4; ++ni) {
            int row = m0 + wm + mi * 16 + g;
            int col = bn + wn + ni * 8 + tg * 2;
            float b0 = bias[col], b1 = bias[col + 1];
            #pragma unroll
            for (int h = 0; h < 2; ++h) {
                int r = row + h * 8;
                float2 o;
                o.x = acc[mi][ni][h * 2]     + b0;
                o.y = acc[mi][ni][h * 2 + 1] + b1;
                *(float2*)&Cf[(size_t)r * N + col] = o;
            }
        }
}

// ---------------- fp16 single-product GEMM: 3-stage, 2 CTA/SM, 1 sync/iter ----------------
#define STAGEB1 20480
#define NST1    3
#define SMEMB1  (NST1*STAGEB1)

// MODE 0: f32, 1: f32 gelu, 2: f16, 3: enhance, 4: f16 gelu
template<int MODE>
__global__ void __launch_bounds__(256, 2) tc1_gemm(
    const __half* __restrict__ A1, int K1,
    const __half* __restrict__ A2,
    const __half* __restrict__ W, int Ktot,
    const float* __restrict__ bias,
    float* __restrict__ Cf, __half* __restrict__ Ch,
    const float* __restrict__ Xf, const float* __restrict__ gate,
    int N)
{
    extern __shared__ __align__(16) char smem[];
    const uint32_t sb = smem_u32(smem);
    const int tid = threadIdx.x, wid = tid >> 5, lane = tid & 31;
    const int g = lane >> 2, tg = lane & 3;
    const int m0 = blockIdx.y * 128, bn = blockIdx.x * 128;
    const int wm = (wid & 1) * 64, wn = (wid >> 1) * 32;

    float acc[4][4][4] = {};
    const int nchunk = Ktot / 32;

    auto load_chunk = [&](int ci, int buf) {
        int k0 = ci * 32;
        const __half* A; int sA, kA;
        if (k0 < K1) { A = A1; sA = K1; kA = k0; }
        else         { A = A2; sA = Ktot - K1; kA = k0 - K1; }
        uint32_t base = sb + buf * STAGEB1;
        #pragma unroll
        for (int u = tid; u < 512; u += 256) {
            int r = u >> 2, c = (u & 3) * 8;
            uint32_t o = (uint32_t)(r * SROW + c * 2);
            cpa16(base + o, A + (size_t)(m0 + r) * sA + kA + c);
        }
        #pragma unroll
        for (int u = tid; u < 512; u += 256) {
            int r = u >> 2, c = (u & 3) * 8;
            uint32_t o = (uint32_t)(r * SROW + c * 2);
            cpa16(base + TILEB + o, W + (size_t)(bn + r) * Ktot + k0 + c);
        }
        cp_commit();
    };

    const uint32_t aoff = (uint32_t)(((lane & 7) + ((lane >> 3) & 1) * 8) * SROW
                                     + ((lane >> 4) & 1) * 16);
    const uint32_t boff = (uint32_t)(((lane & 7) + ((lane >> 4) & 1) * 8) * SROW
                                     + ((lane >> 3) & 1) * 16);

    load_chunk(0, 0);
    if (nchunk > 1) load_chunk(1, 1);

    for (int ci = 0; ci < nchunk; ++ci) {
        if (ci + 1 < nchunk) {
            asm volatile("cp.async.wait_group 1;" ::: "memory");
        } else {
            asm volatile("cp.async.wait_group 0;" ::: "memory");
        }
        __syncthreads();
        if (ci + 2 < nchunk) load_chunk(ci + 2, (ci + 2) % NST1);

        uint32_t st = sb + (ci % NST1) * STAGEB1;
        uint32_t sA = st, sB = st + TILEB;

        #pragma unroll
        for (int ks = 0; ks < 2; ++ks) {
            uint32_t ka = (uint32_t)(ks * 32);
            uint32_t ah[4][4], bh[2][4];
            uint32_t abase = (uint32_t)(wm * SROW) + aoff + ka;
            #pragma unroll
            for (int mi = 0; mi < 4; ++mi)
                LDSM4(ah[mi], sA + abase + mi * 16 * SROW);
            uint32_t bbase = (uint32_t)(wn * SROW) + boff + ka;
            #pragma unroll
            for (int np = 0; np < 2; ++np)
                LDSM4(bh[np], sB + bbase + np * 16 * SROW);
            #pragma unroll
            for (int np = 0; np < 2; ++np)
                #pragma unroll
                for (int sub = 0; sub < 2; ++sub) {
                    int ni = np * 2 + sub;
                    uint32_t h0 = bh[np][sub * 2], h1 = bh[np][sub * 2 + 1];
                    #pragma unroll
                    for (int mi = 0; mi < 4; ++mi)
                        mma_f16(acc[mi][ni], ah[mi][0], ah[mi][1], ah[mi][2], ah[mi][3], h0, h1);
                }
        }
    }

    #pragma unroll
    for (int mi = 0; mi < 4; ++mi)
        #pragma unroll
        for (int ni = 0; ni < 4; ++ni) {
            int row = m0 + wm + mi * 16 + g;
            int col = bn + wn + ni * 8 + tg * 2;
            float b0 = bias[col], b1 = bias[col + 1];
            #pragma unroll
            for (int h = 0; h < 2; ++h) {
                int r = row + h * 8;
                float v0 = acc[mi][ni][h * 2]     + b0;
                float v1 = acc[mi][ni][h * 2 + 1] + b1;
                if (MODE == 1 || MODE == 4) { v0 = gelu_exact(v0); v1 = gelu_exact(v1); }
                if (MODE == 2 || MODE == 4) {
                    __half2 hp; hp.x = __float2half(v0); hp.y = __float2half(v1);
                    *(__half2*)&Ch[(size_t)r * N + col] = hp;
                } else if (MODE == 3) {
                    float gv = gate[r];
                    float2 xv = *(const float2*)&Xf[(size_t)r * N + col];
                    float2 o;
                    o.x = (1.f - gv) * xv.x + gv * v0;
                    o.y = (1.f - gv) * xv.y + gv * v1;
                    *(float2*)&Cf[(size_t)r * N + col] = o;
                } else if (MODE == 0 || MODE == 1) {
                    float2 o; o.x = v0; o.y = v1;
                    *(float2*)&Cf[(size_t)r * N + col] = o;
                }
            }
        }
}

// ---------------- split x -> bf16 hi/lo + fp16 ----------------
__global__ void split_x_kernel(const float4* __restrict__ x,
                               __nv_bfloat16* __restrict__ h, __nv_bfloat16* __restrict__ l,
                               __half* __restrict__ f)
{
    size_t i = (size_t)blockIdx.x * 256 + threadIdx.x;
    float4 v = x[i];
    float a[4] = {v.x, v.y, v.z, v.w};
    __nv_bfloat16 hh[4];
    #pragma unroll
    for (int c = 0; c < 4; ++c) hh[c] = __float2bfloat16(a[c]);
    __nv_bfloat162 hp0, hp1, lp0, lp1;
    hp0.x = hh[0]; hp0.y = hh[1]; hp1.x = hh[2]; hp1.y = hh[3];
    lp0.x = __float2bfloat16(a[0] - __bfloat162float(hh[0]));
    lp0.y = __float2bfloat16(a[1] - __bfloat162float(hh[1]));
    lp1.x = __float2bfloat16(a[2] - __bfloat162float(hh[2]));
    lp1.y = __float2bfloat16(a[3] - __bfloat162float(hh[3]));
    *(__nv_bfloat162*)&h[i * 4]     = hp0;
    *(__nv_bfloat162*)&h[i * 4 + 2] = hp1;
    *(__nv_bfloat162*)&l[i * 4]     = lp0;
    *(__nv_bfloat162*)&l[i * 4 + 2] = lp1;
    __half2 f0, f1;
    f0.x = __float2half(a[0]); f0.y = __float2half(a[1]);
    f1.x = __float2half(a[2]); f1.y = __float2half(a[3]);
    *(__half2*)&f[i * 4]     = f0;
    *(__half2*)&f[i * 4 + 2] = f1;
}

// ---------------- weight prep ----------------
// merged bf16 split for the three [1024,128] q3 weights (z selects source)
__global__ void wsplit_bf3(const float* __restrict__ W0, const float* __restrict__ W1,
                           const float* __restrict__ W2,
                           __nv_bfloat16* __restrict__ Th, __nv_bfloat16* __restrict__ Tl)
{
    __shared__ float tile[32][33];
    const float* W = (blockIdx.z == 0) ? W0 : (blockIdx.z == 1 ? W1 : W2);
    size_t doff = (size_t)blockIdx.z * 131072;
    const int K = 1024, N = 128;
    int kb = blockIdx.x * 32, nb = blockIdx.y * 32;
    int tx = threadIdx.x, ty = threadIdx.y;
    #pragma unroll
    for (int i = 0; i < 4; ++i)
        tile[ty + i * 8][tx] = W[(size_t)(kb + ty + i * 8) * N + nb + tx];
    __syncthreads();
    #pragma unroll
    for (int i = 0; i < 4; ++i) {
        int n = nb + ty + i * 8, k = kb + tx;
        float v = tile[tx][ty + i * 8];
        size_t o = doff + (size_t)n * K + k;
        __nv_bfloat16 h = __float2bfloat16(v);
        Th[o] = h;
        Tl[o] = __float2bfloat16(v - __bfloat162float(h));
    }
}

// merged fp16 conv for rg1|imp1 (each [1024,512], z selects source; dst contiguous)
__global__ void wconv_hf2(const float* __restrict__ W0, const float* __restrict__ W1,
                          __half* __restrict__ Th)
{
    __shared__ float tile[32][33];
    const float* W = blockIdx.z ? W1 : W0;
    size_t doff = (size_t)blockIdx.z * 524288;
    const int K = 1024, N = 512;
    int kb = blockIdx.x * 32, nb = blockIdx.y * 32;
    int tx = threadIdx.x, ty = threadIdx.y;
    #pragma unroll
    for (int i = 0; i < 4; ++i)
        tile[ty + i * 8][tx] = W[(size_t)(kb + ty + i * 8) * N + nb + tx];
    __syncthreads();
    #pragma unroll
    for (int i = 0; i < 4; ++i) {
        int n = nb + ty + i * 8, k = kb + tx;
        Th[doff + (size_t)n * K + k] = __float2half(tile[tx][ty + i * 8]);
    }
}

__global__ void wconv_hf(const float* __restrict__ W, int K, int N,
                         __half* __restrict__ Th)
{
    __shared__ float tile[32][33];
    int kb = blockIdx.x * 32, nb = blockIdx.y * 32;
    int tx = threadIdx.x, ty = threadIdx.y;
    #pragma unroll
    for (int i = 0; i < 4; ++i)
        tile[ty + i * 8][tx] = W[(size_t)(kb + ty + i * 8) * N + nb + tx];
    __syncthreads();
    #pragma unroll
    for (int i = 0; i < 4; ++i) {
        int n = nb + ty + i * 8, k = kb + tx;
        Th[(size_t)n * K + k] = __float2half(tile[tx][ty + i * 8]);
    }
}

// ---------------- bias concat ----------------
__global__ void biascat_kernel(const float* rg1_b, const float* imp1_b,
                               const float* rq_b, const float* twm_b, const float* wq_b,
                               float* bg, float* b3)
{
    int i = blockIdx.x * 256 + threadIdx.x;
    if (i < 512) bg[i] = rg1_b[i];
    else if (i < 1024) bg[i] = imp1_b[i - 512];
    else if (i < 1152) b3[i - 1024] = rq_b[i - 1024];
    else if (i < 1280) b3[i - 1024] = twm_b[i - 1152];
    else if (i < 1408) b3[i - 1024] = wq_b[i - 1280];
}

// ---------------- row-dot over fp16 hidden ----------------
__global__ void rowdot_h(const __half* __restrict__ Hm, int stride,
                         const float* __restrict__ w, const float* __restrict__ bias,
                         const float* __restrict__ wt, int mode,
                         float* __restrict__ out)
{
    __shared__ float ws[HID];
    for (int i = threadIdx.x; i < HID; i += blockDim.x) ws[i] = w[i];
    __syncthreads();
    int warp = threadIdx.x >> 5, lane = threadIdx.x & 31;
    int row = blockIdx.x * 8 + warp;
    const __half* h = Hm + (size_t)row * stride;
    float s = 0.f;
    for (int i = lane; i < HID; i += 32) s = fmaf(__half2float(h[i]), ws[i], s);
    #pragma unroll
    for (int o = 16; o; o >>= 1) s += __shfl_xor_sync(0xffffffffu, s, o);
    if (lane == 0) {
        float z = s + bias[0];
        if (mode == 1) out[row] = z;
        else {
            if (mode == 2) z /= fmaxf(wt[0], 0.1f);
            out[row] = 1.f / (1.f + expf(-z));
        }
    }
}

// ---------------- combined read+write attention ----------------
__global__ void attn_kernel(const float* __restrict__ q3,
                            const float* __restrict__ wm,
                            float* __restrict__ attn_out,
                            __half* __restrict__ ctxf,
                            float* __restrict__ wsc_out,
                            __half* __restrict__ wmf)
{
    __shared__ float cont[NSLOT][DSLOT];
    __shared__ float fresh[NSLOT];
    int tid = threadIdx.x;
    int tokenBase = blockIdx.x * 8;
    int b = tokenBase / SEQ;
    for (int i = tid; i < NSLOT * DSLOT; i += 256) {
        int k = i / DSLOT, d = i % DSLOT;
        cont[k][d] = wm[((size_t)b * NSLOT + k) * (DSLOT + 1) + d];
    }
    if (tid < NSLOT) fresh[tid] = wm[((size_t)b * NSLOT + tid) * (DSLOT + 1) + DSLOT];
    __syncthreads();
    int warp = tid >> 5, lane = tid & 31;
    int t = tokenBase + warp;

    {
        const float* q = q3 + (size_t)t * 384;
        float ql[4];
        #pragma unroll
        for (int i = 0; i < 4; ++i) ql[i] = q[lane + 32 * i];
        float a[NSLOT];
        #pragma unroll
        for (int k = 0; k < NSLOT; ++k) {
            float s = 0.f;
            #pragma unroll
            for (int i = 0; i < 4; ++i) s = fmaf(ql[i], cont[k][lane + 32 * i], s);
            #pragma unroll
            for (int o = 16; o; o >>= 1) s += __shfl_xor_sync(0xffffffffu, s, o);
            s *= SCALE;
            if (fresh[k] < FRESH_THR) s = -1e9f;
            a[k] = s;
        }
        float mx = a[0];
        #pragma unroll
        for (int k = 1; k < NSLOT; ++k) mx = fmaxf(mx, a[k]);
        float sum = 0.f;
        #pragma unroll
        for (int k = 0; k < NSLOT; ++k) { a[k] = expf(a[k] - mx); sum += a[k]; }
        float inv = 1.f / sum;
        #pragma unroll
        for (int k = 0; k < NSLOT; ++k) a[k] *= inv;
        if (lane == 0) {
            #pragma unroll
            for (int k = 0; k < NSLOT; ++k) attn_out[(size_t)t * NSLOT + k] = a[k];
        }
        #pragma unroll
        for (int i = 0; i < 4; ++i) {
            int d = lane + 32 * i;
            float c = 0.f;
            #pragma unroll
            for (int k = 0; k < NSLOT; ++k) c = fmaf(a[k], cont[k][d], c);
            ctxf[(size_t)t * DSLOT + d] = __float2half(c);
        }
    }
    {
        const float* q = q3 + (size_t)t * 384 + 256;
        float ql[4];
        #pragma unroll
        for (int i = 0; i < 4; ++i) ql[i] = q[lane + 32 * i];
        float a[NSLOT];
        #pragma unroll
        for (int k = 0; k < NSLOT; ++k) {
            float s = 0.f;
            #pragma unroll
            for (int i = 0; i < 4; ++i) s = fmaf(ql[i], cont[k][lane + 32 * i], s);
            #pragma unroll
            for (int o = 16; o; o >>= 1) s += __shfl_xor_sync(0xffffffffu, s, o);
            a[k] = s * SCALE;
        }
        if (lane == 0) {
            #pragma unroll
            for (int k = 0; k < NSLOT; ++k) wsc_out[(size_t)t * NSLOT + k] = a[k];
        }
        float mx = a[0];
        #pragma unroll
        for (int k = 1; k < NSLOT; ++k) mx = fmaxf(mx, a[k]);
        float sum = 0.f;
        #pragma unroll
        for (int k = 0; k < NSLOT; ++k) { a[k] = expf(a[k] - mx); sum += a[k]; }
        float inv = 1.f / sum;
        #pragma unroll
        for (int k = 0; k < NSLOT; ++k) a[k] *= inv;
        #pragma unroll
        for (int i = 0; i < 4; ++i) {
            int d = lane + 32 * i;
            float c = 0.f;
            #pragma unroll
            for (int k = 0; k < NSLOT; ++k) c = fmaf(a[k], cont[k][d], c);
            wmf[(size_t)t * DSLOT + d] = __float2half(c);
        }
    }
}

// ---------------- small reductions ----------------
__global__ void pressure_kernel(const float* __restrict__ attn, float* __restrict__ rp)
{
    int b = blockIdx.x / NSLOT, k = blockIdx.x % NSLOT;
    __shared__ float sh[256];
    float s = 0.f;
    for (int si = threadIdx.x; si < SEQ; si += 256)
        s += attn[((size_t)b * SEQ + si) * NSLOT + k];
    sh[threadIdx.x] = s;
    __syncthreads();
    for (int o = 128; o; o >>= 1) {
        if (threadIdx.x < o) sh[threadIdx.x] += sh[threadIdx.x + o];
        __syncthreads();
    }
    if (threadIdx.x == 0) rp[blockIdx.x] = sh[0];
}

__global__ void freshness_kernel(const float* __restrict__ rp, const float* __restrict__ wm,
                                 float* __restrict__ nf)
{
    int t = threadIdx.x;
    int b = t / NSLOT;
    __shared__ float s[BATCH * NSLOT];
    s[t] = rp[t];
    __syncthreads();
    float mx = 1e-8f;
    #pragma unroll
    for (int k = 0; k < NSLOT; ++k) mx = fmaxf(mx, s[b * NSLOT + k]);
    float decay = 1.f - (s[t] / mx) * (1.f - READ_DECAY);
    nf[t] = wm[(size_t)t * (DSLOT + 1) + DSLOT] * decay;
}

__global__ void impsum_kernel(const float* __restrict__ logit, const float* __restrict__ wt,
                              float* __restrict__ outsum)
{
    int b = blockIdx.x;
    float temp = fmaxf(wt[0], 0.1f);
    __shared__ float sh[1024];
    float s = 0.f;
    for (int i = threadIdx.x; i < SEQ; i += 1024)
        s += expf(logit[(size_t)b * SEQ + i] / temp);
    sh[threadIdx.x] = s;
    __syncthreads();
    for (int o = 512; o; o >>= 1) {
        if (threadIdx.x < o) sh[threadIdx.x] += sh[threadIdx.x + o];
        __syncthreads();
    }
    if (threadIdx.x == 0) outsum[b] = sh[0];
}

__global__ void slotsel_kernel(const float* __restrict__ wsc, const float* __restrict__ nf,
                               const float* __restrict__ logit, const float* __restrict__ impsum,
                               const float* __restrict__ wg, const float* __restrict__ wt,
                               float* __restrict__ sel_onehot, int* __restrict__ sel_idx,
                               float* __restrict__ ww_out)
{
    int t = blockIdx.x * 256 + threadIdx.x;
    int b = t / SEQ;
    float temp = fmaxf(wt[0], 0.1f);
    float best = wsc[(size_t)t * NSLOT] - 2.f * nf[b * NSLOT];
    int bi = 0;
    #pragma unroll
    for (int k = 1; k < NSLOT; ++k) {
        float v = wsc[(size_t)t * NSLOT + k] - 2.f * nf[b * NSLOT + k];
        if (v > best) { best = v; bi = k; }
    }
    float imp = expf(logit[t] / temp) / (impsum[b] + 1e-8f) * (float)SEQ;
    sel_idx[t] = bi;
    ww_out[t] = wg[t] * imp;
    #pragma unroll
    for (int k = 0; k < NSLOT; ++k)
        sel_onehot[(size_t)t * NSLOT + k] = (k == bi) ? 1.f : 0.f;
}

// ---------------- slot aggregation: 2-phase ----------------
#define NSEG 8
#define SEGLEN (SEQ/NSEG)
__global__ void slotagg1_kernel(const int* __restrict__ sel, const float* __restrict__ ww,
                                const float* __restrict__ xslot,
                                float* __restrict__ pacc, float* __restrict__ pst)
{
    int blk = blockIdx.x;
    int bk = blk / NSEG, seg = blk % NSEG;
    int b = bk / NSLOT, k = bk % NSLOT;
    int d = threadIdx.x;
    float acc = 0.f, st = 0.f;
    const int s0 = b * SEQ + seg * SEGLEN;
    for (int si = 0; si < SEGLEN; ++si) {
        int tt = s0 + si;
        if (sel[tt] == k) {
            float w = ww[tt];
            st += w;
            acc = fmaf(w, xslot[(size_t)tt * 384 + d], acc);
        }
    }
    pacc[(size_t)blk * 128 + d] = acc;
    if (d == 0) pst[blk] = st;
}

__global__ void slotagg2_kernel(const float* __restrict__ pacc, const float* __restrict__ pst,
                                const float* __restrict__ wm, const float* __restrict__ nf,
                                float* __restrict__ wm_out)
{
    int bk = blockIdx.x;
    int d = threadIdx.x;
    float acc = 0.f, st = 0.f;
    #pragma unroll
    for (int s = 0; s < NSEG; ++s) {
        acc += pacc[(size_t)(bk * NSEG + s) * 128 + d];
        st  += pst[bk * NSEG + s];
    }
    float nc = acc / fmaxf(st, 1e-8f);
    float has = (st > 0.1f) ? 1.f : 0.f;
    float cont = wm[(size_t)bk * (DSLOT + 1) + d];
    wm_out[(size_t)bk * (DSLOT + 1) + d] = has * nc + (1.f - has) * cont;
    if (d == 0)
        wm_out[(size_t)bk * (DSLOT + 1) + DSLOT] = has * 1.f + (1.f - has) * nf[bk];
}

// ---------------- host ----------------
static void* symv(const void* s) { void* p = nullptr; cudaGetSymbolAddress(&p, s); return p; }

extern "C" void kernel_launch(void* const* d_in, const int* in_sizes, int n_in,
                              void* d_out, int out_size)
{
    const float* x      = (const float*)d_in[0];
    const float* wm     = (const float*)d_in[1];
    const float* rq_w   = (const float*)d_in[2];
    const float* rq_b   = (const float*)d_in[3];
    const float* fwm_w  = (const float*)d_in[4];
    const float* fwm_b  = (const float*)d_in[5];
    const float* rg1_w  = (const float*)d_in[6];
    const float* rg1_b  = (const float*)d_in[7];
    const float* rg2_w  = (const float*)d_in[8];
    const float* rg2_b  = (const float*)d_in[9];
    const float* fus_w  = (const float*)d_in[10];
    const float* fus_b  = (const float*)d_in[11];
    const float* twm_w  = (const float*)d_in[12];
    const float* twm_b  = (const float*)d_in[13];
    const float* wq_w   = (const float*)d_in[14];
    const float* wq_b   = (const float*)d_in[15];
    const float* imp1_w = (const float*)d_in[16];
    const float* imp1_b = (const float*)d_in[17];
    const float* imp2_w = (const float*)d_in[18];
    const float* imp2_b = (const float*)d_in[19];
    const float* wd1_w  = (const float*)d_in[20];
    const float* wd1_b  = (const float*)d_in[21];
    const float* wd2_w  = (const float*)d_in[22];
    const float* wd2_b  = (const float*)d_in[23];
    const float* wt     = (const float*)d_in[24];

    float* out = (float*)d_out;
    __half* h1h   = (__half*)symv(g_h1h);
    __half* hgh   = (__half*)symv(g_hgh);
    float* q3     = (float*)symv(g_q3);
    float* implog = (float*)symv(g_implogit);
    float* impsum = (float*)symv(g_impsum);
    float* wsc    = (float*)symv(g_wsc);
    float* nf     = (float*)symv(g_nf);
    float* rp     = (float*)symv(g_rp);
    int*   selidx = (int*)symv(g_sel);
    float* wwbuf  = (float*)symv(g_ww);
    float* bg     = (float*)symv(g_bg);
    float* b3     = (float*)symv(g_b3);
    float* pacc   = (float*)symv(g_pacc);
    float* pst    = (float*)symv(g_pst);
    __nv_bfloat16* xh  = (__nv_bfloat16*)symv(g_xh);
    __nv_bfloat16* xl  = (__nv_bfloat16*)symv(g_xl);
    __nv_bfloat16* wbh = (__nv_bfloat16*)symv(g_wbh);
    __nv_bfloat16* wbl = (__nv_bfloat16*)symv(g_wbl);
    __half* xf   = (__half*)symv(g_xf);
    __half* ctxf = (__half*)symv(g_ctxf);
    __half* conf = (__half*)symv(g_conf);
    __half* wmf  = (__half*)symv(g_wmf);
    __half* wfh  = (__half*)symv(g_wfh);

    cudaFuncSetAttribute(tc3_gemm,    cudaFuncAttributeMaxDynamicSharedMemorySize, SMEMB3);
    cudaFuncSetAttribute(tc1_gemm<0>, cudaFuncAttributeMaxDynamicSharedMemorySize, SMEMB1);
    cudaFuncSetAttribute(tc1_gemm<2>, cudaFuncAttributeMaxDynamicSharedMemorySize, SMEMB1);
    cudaFuncSetAttribute(tc1_gemm<3>, cudaFuncAttributeMaxDynamicSharedMemorySize, SMEMB1);
    cudaFuncSetAttribute(tc1_gemm<4>, cudaFuncAttributeMaxDynamicSharedMemorySize, SMEMB1);

    dim3 tb8(32, 8);

    split_x_kernel<<<NT*DMODEL/4/256, 256>>>((const float4*)x, xh, xl, xf);
    wconv_hf2<<<dim3(1024/32, 512/32, 2), tb8>>>(rg1_w, imp1_w, wfh+F_G);
    wconv_hf<<<dim3( 128/32, 1024/32), tb8>>>(fwm_w,  128, 1024, wfh+F_FWM);
    wconv_hf<<<dim3(2048/32, 1024/32), tb8>>>(fus_w, 2048, 1024, wfh+F_FUS);
    wconv_hf<<<dim3(1152/32,  512/32), tb8>>>(wd1_w, 1152,  512, wfh+F_WD1);
    wsplit_bf3<<<dim3(1024/32, 128/32, 3), tb8>>>(rq_w, twm_w, wq_w, wbh, wbl);
    biascat_kernel<<<6, 256>>>(rg1_b, imp1_b, rq_b, twm_b, wq_b, bg, b3);

    // merged gelu-hidden GEMM [rg1 | imp1]  (fp16, f16 out)
    tc1_gemm<4><<<dim3(8,128), 256, SMEMB1>>>(xf, 1024, nullptr,
        wfh+F_G, 1024, bg, nullptr, hgh, nullptr, nullptr, 1024);
    rowdot_h<<<NT/8, 256>>>(hgh,       1024, rg2_w,  rg2_b,  wt, 0, out + O_GATE);
    rowdot_h<<<NT/8, 256>>>(hgh + 512, 1024, imp2_w, imp2_b, wt, 1, implog);
    impsum_kernel<<<BATCH, 1024>>>(implog, wt, impsum);

    // merged q3 GEMM [query | xslot | wq]  (bf16 x3 — argmax-critical)
    tc3_gemm<<<dim3(3,128), 256, SMEMB3>>>(xh, xl, wbh, wbl, 1024, b3, q3, 384);

    attn_kernel<<<NT/8, 256>>>(q3, wm, out + O_ATTN, ctxf, wsc, wmf);
    tc1_gemm<2><<<dim3(8,128), 256, SMEMB1>>>(ctxf, 128, nullptr,
        wfh+F_FWM, 128, fwm_b, nullptr, conf, nullptr, nullptr, 1024);
    // fusion GEMM with fused enhance epilogue -> x_enhanced directly
    tc1_gemm<3><<<dim3(8,128), 256, SMEMB1>>>(xf, 1024, conf,
        wfh+F_FUS, 2048, fus_b, out + O_XENH, nullptr, x, out + O_GATE, 1024);

    pressure_kernel<<<BATCH*NSLOT, 256>>>(out + O_ATTN, rp);
    freshness_kernel<<<1, BATCH*NSLOT>>>(rp, wm, nf);

    tc1_gemm<4><<<dim3(4,128), 256, SMEMB1>>>(xf, 1024, wmf,
        wfh+F_WD1, 1152, wd1_b, nullptr, h1h, nullptr, nullptr, 512);
    rowdot_h<<<NT/8, 256>>>(h1h, 512, wd2_w, wd2_b, wt, 2, out + O_WG);

    slotsel_kernel<<<NT/256, 256>>>(wsc, nf, implog, impsum, out + O_WG, wt,
                                    out + O_SEL, selidx, wwbuf);
    slotagg1_kernel<<<BATCH*NSLOT*NSEG, 128>>>(selidx, wwbuf, q3 + 128, pacc, pst);
    slotagg2_kernel<<<BATCH*NSLOT, DSLOT>>>(pacc, pst, wm, nf, out + O_WM);
}